// round 1
// baseline (speedup 1.0000x reference)
#include <cuda_runtime.h>
#include <math.h>

#define Bdim 4
#define Sdim 2048
#define Edim 1024
#define Hdim 16
#define Ddim 64
#define Mrows (Bdim * Sdim)          // 8192
#define HD (Hdim * Ddim)             // 1024

// ---------------- scratch (static device globals; no allocs) ----------------
__device__ float g_xn[Mrows * Edim];
__device__ float g_q [Mrows * HD];
__device__ float g_k [Mrows * HD];
__device__ float g_v [Mrows * HD];
__device__ float g_ao[Mrows * HD];

// ---------------- LayerNorm: one block per row, 256 threads x 4 elems -------
__global__ void __launch_bounds__(256) ln_kernel(const float* __restrict__ x,
                                                 const float* __restrict__ gamma,
                                                 const float* __restrict__ beta,
                                                 float* __restrict__ y) {
    const int row = blockIdx.x;
    const int tid = threadIdx.x;
    const float4 xv = reinterpret_cast<const float4*>(x + (size_t)row * Edim)[tid];
    float s  = xv.x + xv.y + xv.z + xv.w;
    float ss = xv.x * xv.x + xv.y * xv.y + xv.z * xv.z + xv.w * xv.w;
    #pragma unroll
    for (int m = 16; m; m >>= 1) {
        s  += __shfl_xor_sync(0xffffffffu, s,  m);
        ss += __shfl_xor_sync(0xffffffffu, ss, m);
    }
    __shared__ float sh_s[8], sh_ss[8];
    __shared__ float s_mu, s_rstd;
    const int w = tid >> 5, l = tid & 31;
    if (l == 0) { sh_s[w] = s; sh_ss[w] = ss; }
    __syncthreads();
    if (w == 0) {
        float a = (l < 8) ? sh_s[l]  : 0.f;
        float c = (l < 8) ? sh_ss[l] : 0.f;
        #pragma unroll
        for (int m = 4; m; m >>= 1) {
            a += __shfl_xor_sync(0xffffffffu, a, m);
            c += __shfl_xor_sync(0xffffffffu, c, m);
        }
        if (l == 0) {
            float mu  = a * (1.0f / Edim);
            float var = c * (1.0f / Edim) - mu * mu;
            s_mu = mu;
            s_rstd = rsqrtf(var + 1e-5f);
        }
    }
    __syncthreads();
    const float mu = s_mu, rstd = s_rstd;
    const float4 gv = reinterpret_cast<const float4*>(gamma)[tid];
    const float4 bv = reinterpret_cast<const float4*>(beta)[tid];
    float4 yv;
    yv.x = (xv.x - mu) * rstd * gv.x + bv.x;
    yv.y = (xv.y - mu) * rstd * gv.y + bv.y;
    yv.z = (xv.z - mu) * rstd * gv.z + bv.z;
    yv.w = (xv.w - mu) * rstd * gv.w + bv.w;
    reinterpret_cast<float4*>(y + (size_t)row * Edim)[tid] = yv;
}

// ---------------- SGEMM: C = A(MxK) * W(KxN) + bias (+ residual) -----------
// 128x128 block tile, BK=8, 256 threads, 8x8 per thread.
__global__ void __launch_bounds__(256) gemm_kernel(const float* __restrict__ A,
                                                   const float* __restrict__ W,
                                                   const float* __restrict__ bias,
                                                   const float* __restrict__ res,
                                                   float* __restrict__ C,
                                                   int M, int N, int K) {
    __shared__ float As[8][128];
    __shared__ float Ws[8][128];
    const int tid = threadIdx.x;
    const int tx = tid & 15, ty = tid >> 4;
    const int row0 = blockIdx.y * 128, col0 = blockIdx.x * 128;
    const int arow = tid >> 1, acol = (tid & 1) << 2;
    const int wrow = tid >> 5, wcol = (tid & 31) << 2;

    float acc[8][8] = {};
    const float* Ap = A + (size_t)(row0 + arow) * K + acol;
    const float* Wp = W + (size_t)wrow * N + col0 + wcol;

    for (int k0 = 0; k0 < K; k0 += 8) {
        float4 av = *reinterpret_cast<const float4*>(Ap + k0);
        float4 wv = *reinterpret_cast<const float4*>(Wp + (size_t)k0 * N);
        As[acol + 0][arow] = av.x;
        As[acol + 1][arow] = av.y;
        As[acol + 2][arow] = av.z;
        As[acol + 3][arow] = av.w;
        *reinterpret_cast<float4*>(&Ws[wrow][wcol]) = wv;
        __syncthreads();
        #pragma unroll
        for (int k = 0; k < 8; k++) {
            float a[8], b[8];
            #pragma unroll
            for (int i = 0; i < 8; i++) a[i] = As[k][ty * 8 + i];
            #pragma unroll
            for (int j = 0; j < 8; j++) b[j] = Ws[k][tx * 8 + j];
            #pragma unroll
            for (int i = 0; i < 8; i++)
                #pragma unroll
                for (int j = 0; j < 8; j++)
                    acc[i][j] = fmaf(a[i], b[j], acc[i][j]);
        }
        __syncthreads();
    }

    #pragma unroll
    for (int i = 0; i < 8; i++) {
        const int r = row0 + ty * 8 + i;
        #pragma unroll
        for (int j = 0; j < 8; j++) {
            const int c = col0 + tx * 8 + j;
            float v = acc[i][j] + bias[c];
            if (res) v += res[(size_t)r * N + c];
            C[(size_t)r * N + c] = v;
        }
    }
}

// ---------------- Flash attention (causal), fp32 ---------------------------
// grid: (S/64, H, B). block: 256 threads (16x16 -> 4x4 microtile).
// smem tiles 64 x (stride 65): Q, K, V, P  + m/l/scale arrays.
#define TSTR 65
#define SM_Q 0
#define SM_K (64 * TSTR)
#define SM_V (2 * 64 * TSTR)
#define SM_P (3 * 64 * TSTR)
#define SM_M (4 * 64 * TSTR)
#define ATTN_SMEM_FLOATS (4 * 64 * TSTR + 3 * 64)

__global__ void __launch_bounds__(256) attn_kernel(const float* __restrict__ Q,
                                                   const float* __restrict__ K,
                                                   const float* __restrict__ V,
                                                   float* __restrict__ O) {
    extern __shared__ float sm[];
    float* Qs = sm + SM_Q;
    float* Ks = sm + SM_K;
    float* Vs = sm + SM_V;
    float* Ps = sm + SM_P;
    float* m_sh  = sm + SM_M;
    float* l_sh  = m_sh + 64;
    float* sc_sh = l_sh + 64;

    const int tid = threadIdx.x;
    const int tx = tid & 15, ty = tid >> 4;
    const int q0 = blockIdx.x * 64;
    const int h = blockIdx.y, b = blockIdx.z;
    const size_t base = (size_t)b * Sdim * HD + (size_t)h * Ddim;

    // load Q tile (64 x 64)
    #pragma unroll
    for (int it = 0; it < 4; it++) {
        int lin = tid + it * 256;
        int r = lin >> 4, c4 = (lin & 15) << 2;
        float4 qv = *reinterpret_cast<const float4*>(Q + base + (size_t)(q0 + r) * HD + c4);
        Qs[r * TSTR + c4 + 0] = qv.x;
        Qs[r * TSTR + c4 + 1] = qv.y;
        Qs[r * TSTR + c4 + 2] = qv.z;
        Qs[r * TSTR + c4 + 3] = qv.w;
    }
    if (tid < 64) { m_sh[tid] = -1e30f; l_sh[tid] = 0.f; }

    float o[4][4] = {};
    const int ntiles = (q0 >> 6) + 1;

    for (int jt = 0; jt < ntiles; jt++) {
        const int j0 = jt * 64;
        __syncthreads();   // previous PV done before overwriting K/V
        #pragma unroll
        for (int it = 0; it < 4; it++) {
            int lin = tid + it * 256;
            int r = lin >> 4, c4 = (lin & 15) << 2;
            float4 kv = *reinterpret_cast<const float4*>(K + base + (size_t)(j0 + r) * HD + c4);
            Ks[r * TSTR + c4 + 0] = kv.x;
            Ks[r * TSTR + c4 + 1] = kv.y;
            Ks[r * TSTR + c4 + 2] = kv.z;
            Ks[r * TSTR + c4 + 3] = kv.w;
            float4 vv = *reinterpret_cast<const float4*>(V + base + (size_t)(j0 + r) * HD + c4);
            Vs[r * TSTR + c4 + 0] = vv.x;
            Vs[r * TSTR + c4 + 1] = vv.y;
            Vs[r * TSTR + c4 + 2] = vv.z;
            Vs[r * TSTR + c4 + 3] = vv.w;
        }
        __syncthreads();

        // S = Q K^T
        float s[4][4] = {};
        #pragma unroll 4
        for (int kk = 0; kk < 64; kk++) {
            float qr[4], kr[4];
            #pragma unroll
            for (int i = 0; i < 4; i++) qr[i] = Qs[(ty * 4 + i) * TSTR + kk];
            #pragma unroll
            for (int j = 0; j < 4; j++) kr[j] = Ks[(tx * 4 + j) * TSTR + kk];
            #pragma unroll
            for (int i = 0; i < 4; i++)
                #pragma unroll
                for (int j = 0; j < 4; j++)
                    s[i][j] = fmaf(qr[i], kr[j], s[i][j]);
        }

        const bool diag = (jt == ntiles - 1);
        float mnew[4], mold[4], rsum[4], p[4][4];
        #pragma unroll
        for (int i = 0; i < 4; i++) {
            const int row = ty * 4 + i;
            float rm = -1e30f;
            #pragma unroll
            for (int j = 0; j < 4; j++) {
                s[i][j] *= 0.125f;                               // 1/sqrt(64)
                if (diag && (tx * 4 + j) > row) s[i][j] = -1e30f; // causal mask
                rm = fmaxf(rm, s[i][j]);
            }
            #pragma unroll
            for (int msk = 8; msk; msk >>= 1)
                rm = fmaxf(rm, __shfl_xor_sync(0xffffffffu, rm, msk));
            mold[i] = m_sh[row];
            mnew[i] = fmaxf(mold[i], rm);
            float rs = 0.f;
            #pragma unroll
            for (int j = 0; j < 4; j++) {
                p[i][j] = __expf(s[i][j] - mnew[i]);
                rs += p[i][j];
            }
            #pragma unroll
            for (int msk = 8; msk; msk >>= 1)
                rs += __shfl_xor_sync(0xffffffffu, rs, msk);
            rsum[i] = rs;
        }
        __syncwarp();
        if (tx == 0) {
            #pragma unroll
            for (int i = 0; i < 4; i++) {
                const int row = ty * 4 + i;
                float scl = __expf(mold[i] - mnew[i]);
                sc_sh[row] = scl;
                m_sh[row] = mnew[i];
                l_sh[row] = l_sh[row] * scl + rsum[i];
            }
        }
        #pragma unroll
        for (int i = 0; i < 4; i++)
            #pragma unroll
            for (int j = 0; j < 4; j++)
                Ps[(ty * 4 + i) * TSTR + tx * 4 + j] = p[i][j];
        __syncthreads();

        // rescale accumulator, then O += P V
        #pragma unroll
        for (int i = 0; i < 4; i++) {
            const float scl = sc_sh[ty * 4 + i];
            #pragma unroll
            for (int j = 0; j < 4; j++) o[i][j] *= scl;
        }
        #pragma unroll 4
        for (int kk = 0; kk < 64; kk++) {
            float pr[4], vr[4];
            #pragma unroll
            for (int i = 0; i < 4; i++) pr[i] = Ps[(ty * 4 + i) * TSTR + kk];
            #pragma unroll
            for (int j = 0; j < 4; j++) vr[j] = Vs[kk * TSTR + tx * 4 + j];
            #pragma unroll
            for (int i = 0; i < 4; i++)
                #pragma unroll
                for (int j = 0; j < 4; j++)
                    o[i][j] = fmaf(pr[i], vr[j], o[i][j]);
        }
    }

    #pragma unroll
    for (int i = 0; i < 4; i++) {
        const float inv = 1.0f / l_sh[ty * 4 + i];
        #pragma unroll
        for (int j = 0; j < 4; j++)
            O[base + (size_t)(q0 + ty * 4 + i) * HD + tx * 4 + j] = o[i][j] * inv;
    }
}

// ---------------- launch ----------------------------------------------------
extern "C" void kernel_launch(void* const* d_in, const int* in_sizes, int n_in,
                              void* d_out, int out_size) {
    const float* x     = (const float*)d_in[0];
    const float* gamma = (const float*)d_in[1];
    const float* beta  = (const float*)d_in[2];
    const float* Wq    = (const float*)d_in[3];
    const float* bq    = (const float*)d_in[4];
    const float* Wk    = (const float*)d_in[5];
    const float* bk    = (const float*)d_in[6];
    const float* Wv    = (const float*)d_in[7];
    const float* bv    = (const float*)d_in[8];
    const float* Wo    = (const float*)d_in[9];
    const float* bo    = (const float*)d_in[10];
    float* out = (float*)d_out;

    float *xn, *qp, *kp, *vp, *ao;
    cudaGetSymbolAddress((void**)&xn, g_xn);
    cudaGetSymbolAddress((void**)&qp, g_q);
    cudaGetSymbolAddress((void**)&kp, g_k);
    cudaGetSymbolAddress((void**)&vp, g_v);
    cudaGetSymbolAddress((void**)&ao, g_ao);

    ln_kernel<<<Mrows, 256>>>(x, gamma, beta, xn);

    dim3 gg(HD / 128, Mrows / 128);   // (8, 64)
    gemm_kernel<<<gg, 256>>>(xn, Wq, bq, nullptr, qp, Mrows, HD, Edim);
    gemm_kernel<<<gg, 256>>>(xn, Wk, bk, nullptr, kp, Mrows, HD, Edim);
    gemm_kernel<<<gg, 256>>>(xn, Wv, bv, nullptr, vp, Mrows, HD, Edim);

    const int attn_smem = ATTN_SMEM_FLOATS * (int)sizeof(float);  // ~67 KB
    cudaFuncSetAttribute(attn_kernel, cudaFuncAttributeMaxDynamicSharedMemorySize, attn_smem);
    attn_kernel<<<dim3(Sdim / 64, Hdim, Bdim), 256, attn_smem>>>(qp, kp, vp, ao);

    gemm_kernel<<<dim3(Edim / 128, Mrows / 128), 256>>>(ao, Wo, bo, x, out, Mrows, Edim, HD);
}

// round 2
// speedup vs baseline: 3.0636x; 3.0636x over previous
#include <cuda_runtime.h>
#include <math.h>
#include <stdint.h>

#define Bdim 4
#define Sdim 2048
#define Edim 1024
#define Hdim 16
#define Ddim 64
#define Mrows (Bdim * Sdim)          // 8192
#define HD (Hdim * Ddim)             // 1024

// ---------------- scratch (static device globals; no allocs) ----------------
__device__ float g_xn[Mrows * Edim];
__device__ float g_q [Mrows * HD];
__device__ float g_k [Mrows * HD];
__device__ float g_v [Mrows * HD];
__device__ float g_ao[Mrows * HD];

// ---------------- helpers ----------------------------------------------------
__device__ __forceinline__ float f2tf(float x) {
    uint32_t u;
    asm("cvt.rna.tf32.f32 %0, %1;" : "=r"(u) : "f"(x));
    return __uint_as_float(u);
}
__device__ __forceinline__ uint32_t fu(float x) { return __float_as_uint(x); }

// D(16x8) += A(16x8,row) * B(8x8,col)  tf32
__device__ __forceinline__ void mma_tf32(float c[4],
                                         uint32_t a0, uint32_t a1, uint32_t a2, uint32_t a3,
                                         uint32_t b0, uint32_t b1) {
    asm volatile(
        "mma.sync.aligned.m16n8k8.row.col.f32.tf32.tf32.f32 "
        "{%0,%1,%2,%3}, {%4,%5,%6,%7}, {%8,%9}, {%0,%1,%2,%3};\n"
        : "+f"(c[0]), "+f"(c[1]), "+f"(c[2]), "+f"(c[3])
        : "r"(a0), "r"(a1), "r"(a2), "r"(a3), "r"(b0), "r"(b1));
}

// ---------------- LayerNorm --------------------------------------------------
__global__ void __launch_bounds__(256) ln_kernel(const float* __restrict__ x,
                                                 const float* __restrict__ gamma,
                                                 const float* __restrict__ beta,
                                                 float* __restrict__ y) {
    const int row = blockIdx.x;
    const int tid = threadIdx.x;
    const float4 xv = reinterpret_cast<const float4*>(x + (size_t)row * Edim)[tid];
    float s  = xv.x + xv.y + xv.z + xv.w;
    float ss = xv.x * xv.x + xv.y * xv.y + xv.z * xv.z + xv.w * xv.w;
    #pragma unroll
    for (int m = 16; m; m >>= 1) {
        s  += __shfl_xor_sync(0xffffffffu, s,  m);
        ss += __shfl_xor_sync(0xffffffffu, ss, m);
    }
    __shared__ float sh_s[8], sh_ss[8];
    __shared__ float s_mu, s_rstd;
    const int w = tid >> 5, l = tid & 31;
    if (l == 0) { sh_s[w] = s; sh_ss[w] = ss; }
    __syncthreads();
    if (w == 0) {
        float a = (l < 8) ? sh_s[l]  : 0.f;
        float c = (l < 8) ? sh_ss[l] : 0.f;
        #pragma unroll
        for (int m = 4; m; m >>= 1) {
            a += __shfl_xor_sync(0xffffffffu, a, m);
            c += __shfl_xor_sync(0xffffffffu, c, m);
        }
        if (l == 0) {
            float mu  = a * (1.0f / Edim);
            float var = c * (1.0f / Edim) - mu * mu;
            s_mu = mu;
            s_rstd = rsqrtf(var + 1e-5f);
        }
    }
    __syncthreads();
    const float mu = s_mu, rstd = s_rstd;
    const float4 gv = reinterpret_cast<const float4*>(gamma)[tid];
    const float4 bv = reinterpret_cast<const float4*>(beta)[tid];
    float4 yv;
    yv.x = (xv.x - mu) * rstd * gv.x + bv.x;
    yv.y = (xv.y - mu) * rstd * gv.y + bv.y;
    yv.z = (xv.z - mu) * rstd * gv.z + bv.z;
    yv.w = (xv.w - mu) * rstd * gv.w + bv.w;
    reinterpret_cast<float4*>(y + (size_t)row * Edim)[tid] = yv;
}

// ---------------- TF32 tensor-core GEMM -------------------------------------
// C = A(MxK) * W(KxN) + bias (+ residual). 128x128 block, BK=16, 256 threads.
// Warp grid 2(m) x 4(n) -> warp tile 64x32 (4 m16 x 4 n8 mma tiles).
#define BM 128
#define BN 128
#define BK 16
#define ASTR 20
#define BSTR 136

__global__ void __launch_bounds__(256) gemm_tf32_kernel(const float* __restrict__ A,
                                                        const float* __restrict__ W,
                                                        const float* __restrict__ bias,
                                                        const float* __restrict__ res,
                                                        float* __restrict__ C,
                                                        int M, int N, int K) {
    __shared__ float As[2][BM * ASTR];
    __shared__ float Bs[2][BK * BSTR];

    const int tid  = threadIdx.x;
    const int lane = tid & 31;
    const int wid  = tid >> 5;
    const int g  = lane >> 2;   // 0..7
    const int tg = lane & 3;    // 0..3
    const int wm = wid >> 2;    // 0..1
    const int wn = wid & 3;     // 0..3
    const int row0 = blockIdx.y * BM;
    const int col0 = blockIdx.x * BN;

    // global-load mapping
    const int ar = tid >> 2;            // 0..63 (+64)
    const int ac = (tid & 3) << 2;      // 0,4,8,12
    const int br = tid >> 5;            // 0..7 (+8)
    const int bc = (tid & 31) << 2;     // 0..124

    const float* Ap = A + (size_t)(row0 + ar) * K + ac;
    const float* Bp = W + (size_t)br * N + col0 + bc;

    float4 a0v = *reinterpret_cast<const float4*>(Ap);
    float4 a1v = *reinterpret_cast<const float4*>(Ap + (size_t)64 * K);
    float4 b0v = *reinterpret_cast<const float4*>(Bp);
    float4 b1v = *reinterpret_cast<const float4*>(Bp + (size_t)8 * N);

    {
        float* a_dst0 = &As[0][ar * ASTR + ac];
        float* a_dst1 = &As[0][(ar + 64) * ASTR + ac];
        a_dst0[0] = f2tf(a0v.x); a_dst0[1] = f2tf(a0v.y); a_dst0[2] = f2tf(a0v.z); a_dst0[3] = f2tf(a0v.w);
        a_dst1[0] = f2tf(a1v.x); a_dst1[1] = f2tf(a1v.y); a_dst1[2] = f2tf(a1v.z); a_dst1[3] = f2tf(a1v.w);
        float* b_dst0 = &Bs[0][br * BSTR + bc];
        float* b_dst1 = &Bs[0][(br + 8) * BSTR + bc];
        b_dst0[0] = f2tf(b0v.x); b_dst0[1] = f2tf(b0v.y); b_dst0[2] = f2tf(b0v.z); b_dst0[3] = f2tf(b0v.w);
        b_dst1[0] = f2tf(b1v.x); b_dst1[1] = f2tf(b1v.y); b_dst1[2] = f2tf(b1v.z); b_dst1[3] = f2tf(b1v.w);
    }
    __syncthreads();

    float acc[4][4][4] = {};
    const int NIT = K / BK;

    for (int it = 0; it < NIT; it++) {
        const int cur = it & 1;
        if (it + 1 < NIT) {
            const float* Ap2 = Ap + (it + 1) * BK;
            const float* Bp2 = Bp + (size_t)(it + 1) * BK * N;
            a0v = *reinterpret_cast<const float4*>(Ap2);
            a1v = *reinterpret_cast<const float4*>(Ap2 + (size_t)64 * K);
            b0v = *reinterpret_cast<const float4*>(Bp2);
            b1v = *reinterpret_cast<const float4*>(Bp2 + (size_t)8 * N);
        }

        const float* Asc = As[cur];
        const float* Bsc = Bs[cur];
        #pragma unroll
        for (int kb = 0; kb < 2; kb++) {
            const int k0 = kb * 8;
            uint32_t af[4][4];
            #pragma unroll
            for (int mi = 0; mi < 4; mi++) {
                const int rb = wm * 64 + mi * 16;
                af[mi][0] = fu(Asc[(rb + g)     * ASTR + k0 + tg]);
                af[mi][1] = fu(Asc[(rb + g + 8) * ASTR + k0 + tg]);
                af[mi][2] = fu(Asc[(rb + g)     * ASTR + k0 + tg + 4]);
                af[mi][3] = fu(Asc[(rb + g + 8) * ASTR + k0 + tg + 4]);
            }
            uint32_t bf[4][2];
            #pragma unroll
            for (int ni = 0; ni < 4; ni++) {
                const int cb = wn * 32 + ni * 8 + g;
                bf[ni][0] = fu(Bsc[(k0 + tg)     * BSTR + cb]);
                bf[ni][1] = fu(Bsc[(k0 + tg + 4) * BSTR + cb]);
            }
            #pragma unroll
            for (int mi = 0; mi < 4; mi++)
                #pragma unroll
                for (int ni = 0; ni < 4; ni++)
                    mma_tf32(acc[mi][ni], af[mi][0], af[mi][1], af[mi][2], af[mi][3],
                             bf[ni][0], bf[ni][1]);
        }

        if (it + 1 < NIT) {
            const int nxt = cur ^ 1;
            float* a_dst0 = &As[nxt][ar * ASTR + ac];
            float* a_dst1 = &As[nxt][(ar + 64) * ASTR + ac];
            a_dst0[0] = f2tf(a0v.x); a_dst0[1] = f2tf(a0v.y); a_dst0[2] = f2tf(a0v.z); a_dst0[3] = f2tf(a0v.w);
            a_dst1[0] = f2tf(a1v.x); a_dst1[1] = f2tf(a1v.y); a_dst1[2] = f2tf(a1v.z); a_dst1[3] = f2tf(a1v.w);
            float* b_dst0 = &Bs[nxt][br * BSTR + bc];
            float* b_dst1 = &Bs[nxt][(br + 8) * BSTR + bc];
            b_dst0[0] = f2tf(b0v.x); b_dst0[1] = f2tf(b0v.y); b_dst0[2] = f2tf(b0v.z); b_dst0[3] = f2tf(b0v.w);
            b_dst1[0] = f2tf(b1v.x); b_dst1[1] = f2tf(b1v.y); b_dst1[2] = f2tf(b1v.z); b_dst1[3] = f2tf(b1v.w);
        }
        __syncthreads();
    }

    // epilogue: bias (+ residual), float2 stores (c0,c1 / c2,c3 are adjacent cols)
    #pragma unroll
    for (int mi = 0; mi < 4; mi++) {
        const int r1 = row0 + wm * 64 + mi * 16 + g;
        const int r2 = r1 + 8;
        #pragma unroll
        for (int ni = 0; ni < 4; ni++) {
            const int cb = col0 + wn * 32 + ni * 8 + 2 * tg;
            float2 v1, v2;
            v1.x = acc[mi][ni][0] + bias[cb];
            v1.y = acc[mi][ni][1] + bias[cb + 1];
            v2.x = acc[mi][ni][2] + bias[cb];
            v2.y = acc[mi][ni][3] + bias[cb + 1];
            if (res) {
                const float2 r1v = *reinterpret_cast<const float2*>(res + (size_t)r1 * N + cb);
                const float2 r2v = *reinterpret_cast<const float2*>(res + (size_t)r2 * N + cb);
                v1.x += r1v.x; v1.y += r1v.y;
                v2.x += r2v.x; v2.y += r2v.y;
            }
            *reinterpret_cast<float2*>(C + (size_t)r1 * N + cb) = v1;
            *reinterpret_cast<float2*>(C + (size_t)r2 * N + cb) = v2;
        }
    }
}

// ---------------- Flash attention (causal) with tf32 mma --------------------
// grid (S/64, H, B), 128 threads (4 warps). Warp w owns query rows [16w,16w+16).
// smem: Q,K,V,P tiles 64 x stride 72 (conflict-free for all frag patterns).
#define QSTR 72
#define ATTN_SMEM_BYTES (4 * 64 * QSTR * 4)

__global__ void __launch_bounds__(128) attn_tf32_kernel(const float* __restrict__ Q,
                                                        const float* __restrict__ K,
                                                        const float* __restrict__ V,
                                                        float* __restrict__ O) {
    extern __shared__ float sm[];
    float* Qs = sm;
    float* Ks = Qs + 64 * QSTR;
    float* Vs = Ks + 64 * QSTR;
    float* Ps = Vs + 64 * QSTR;

    const int tid  = threadIdx.x;
    const int lane = tid & 31;
    const int wid  = tid >> 5;      // 0..3
    const int g  = lane >> 2;
    const int tg = lane & 3;
    const int rbase = wid * 16;
    const int q0 = blockIdx.x * 64;
    const int h = blockIdx.y, b = blockIdx.z;
    const size_t base = (size_t)b * Sdim * HD + (size_t)h * Ddim;

    // load Q tile (64x64), tf32-rounded
    #pragma unroll
    for (int it = 0; it < 8; it++) {
        const int f4i = tid + it * 128;
        const int r = f4i >> 4, c4 = (f4i & 15) << 2;
        float4 qv = *reinterpret_cast<const float4*>(Q + base + (size_t)(q0 + r) * HD + c4);
        float* d = &Qs[r * QSTR + c4];
        d[0] = f2tf(qv.x); d[1] = f2tf(qv.y); d[2] = f2tf(qv.z); d[3] = f2tf(qv.w);
    }

    float m1 = -1e30f, m2 = -1e30f, l1 = 0.f, l2 = 0.f;
    float o[8][4] = {};
    const int row1 = rbase + g, row2 = row1 + 8;   // block-local query rows
    const int ntiles = (q0 >> 6) + 1;

    for (int jt = 0; jt < ntiles; jt++) {
        const int j0 = jt * 64;
        __syncthreads();   // prev iter done with Ks/Vs; also covers initial Q visibility
        #pragma unroll
        for (int it = 0; it < 8; it++) {
            const int f4i = tid + it * 128;
            const int r = f4i >> 4, c4 = (f4i & 15) << 2;
            float4 kv = *reinterpret_cast<const float4*>(K + base + (size_t)(j0 + r) * HD + c4);
            float* dk = &Ks[r * QSTR + c4];
            dk[0] = f2tf(kv.x); dk[1] = f2tf(kv.y); dk[2] = f2tf(kv.z); dk[3] = f2tf(kv.w);
            float4 vv = *reinterpret_cast<const float4*>(V + base + (size_t)(j0 + r) * HD + c4);
            float* dv = &Vs[r * QSTR + c4];
            dv[0] = f2tf(vv.x); dv[1] = f2tf(vv.y); dv[2] = f2tf(vv.z); dv[3] = f2tf(vv.w);
        }
        __syncthreads();

        // S = Q K^T  (warp: 16 rows x 64 cols)
        float s[8][4] = {};
        #pragma unroll
        for (int kb = 0; kb < 8; kb++) {
            const int k0 = kb * 8;
            const uint32_t a0 = fu(Qs[(row1)     * QSTR + k0 + tg]);
            const uint32_t a1 = fu(Qs[(row2)     * QSTR + k0 + tg]);
            const uint32_t a2 = fu(Qs[(row1)     * QSTR + k0 + tg + 4]);
            const uint32_t a3 = fu(Qs[(row2)     * QSTR + k0 + tg + 4]);
            #pragma unroll
            for (int nt = 0; nt < 8; nt++) {
                const uint32_t b0 = fu(Ks[(nt * 8 + g) * QSTR + k0 + tg]);
                const uint32_t b1 = fu(Ks[(nt * 8 + g) * QSTR + k0 + tg + 4]);
                mma_tf32(s[nt], a0, a1, a2, a3, b0, b1);
            }
        }

        // online softmax
        const bool diag = (jt == ntiles - 1);
        float rm1 = -1e30f, rm2 = -1e30f;
        #pragma unroll
        for (int nt = 0; nt < 8; nt++) {
            s[nt][0] *= 0.125f; s[nt][1] *= 0.125f; s[nt][2] *= 0.125f; s[nt][3] *= 0.125f;
            if (diag) {
                const int c0 = nt * 8 + 2 * tg;
                if (c0     > row1) s[nt][0] = -1e30f;
                if (c0 + 1 > row1) s[nt][1] = -1e30f;
                if (c0     > row2) s[nt][2] = -1e30f;
                if (c0 + 1 > row2) s[nt][3] = -1e30f;
            }
            rm1 = fmaxf(rm1, fmaxf(s[nt][0], s[nt][1]));
            rm2 = fmaxf(rm2, fmaxf(s[nt][2], s[nt][3]));
        }
        rm1 = fmaxf(rm1, __shfl_xor_sync(0xffffffffu, rm1, 1));
        rm1 = fmaxf(rm1, __shfl_xor_sync(0xffffffffu, rm1, 2));
        rm2 = fmaxf(rm2, __shfl_xor_sync(0xffffffffu, rm2, 1));
        rm2 = fmaxf(rm2, __shfl_xor_sync(0xffffffffu, rm2, 2));

        const float mn1 = fmaxf(m1, rm1), mn2 = fmaxf(m2, rm2);
        const float sc1 = __expf(m1 - mn1), sc2 = __expf(m2 - mn2);
        m1 = mn1; m2 = mn2;

        float sum1 = 0.f, sum2 = 0.f;
        #pragma unroll
        for (int nt = 0; nt < 8; nt++) {
            const float p0 = __expf(s[nt][0] - mn1);
            const float p1 = __expf(s[nt][1] - mn1);
            const float p2 = __expf(s[nt][2] - mn2);
            const float p3 = __expf(s[nt][3] - mn2);
            sum1 += p0 + p1;
            sum2 += p2 + p3;
            const int cb = nt * 8 + 2 * tg;
            float2 w1; w1.x = f2tf(p0); w1.y = f2tf(p1);
            float2 w2; w2.x = f2tf(p2); w2.y = f2tf(p3);
            *reinterpret_cast<float2*>(&Ps[row1 * QSTR + cb]) = w1;
            *reinterpret_cast<float2*>(&Ps[row2 * QSTR + cb]) = w2;
        }
        sum1 += __shfl_xor_sync(0xffffffffu, sum1, 1);
        sum1 += __shfl_xor_sync(0xffffffffu, sum1, 2);
        sum2 += __shfl_xor_sync(0xffffffffu, sum2, 1);
        sum2 += __shfl_xor_sync(0xffffffffu, sum2, 2);
        l1 = l1 * sc1 + sum1;
        l2 = l2 * sc2 + sum2;

        #pragma unroll
        for (int nt = 0; nt < 8; nt++) {
            o[nt][0] *= sc1; o[nt][1] *= sc1;
            o[nt][2] *= sc2; o[nt][3] *= sc2;
        }
        __syncwarp();

        // O += P V   (A=P 16x64, B=V 64x64)
        #pragma unroll
        for (int kb = 0; kb < 8; kb++) {
            const int k0 = kb * 8;
            const uint32_t a0 = fu(Ps[row1 * QSTR + k0 + tg]);
            const uint32_t a1 = fu(Ps[row2 * QSTR + k0 + tg]);
            const uint32_t a2 = fu(Ps[row1 * QSTR + k0 + tg + 4]);
            const uint32_t a3 = fu(Ps[row2 * QSTR + k0 + tg + 4]);
            #pragma unroll
            for (int nt = 0; nt < 8; nt++) {
                const uint32_t b0 = fu(Vs[(k0 + tg)     * QSTR + nt * 8 + g]);
                const uint32_t b1 = fu(Vs[(k0 + tg + 4) * QSTR + nt * 8 + g]);
                mma_tf32(o[nt], a0, a1, a2, a3, b0, b1);
            }
        }
    }

    const float inv1 = 1.0f / l1;
    const float inv2 = 1.0f / l2;
    #pragma unroll
    for (int nt = 0; nt < 8; nt++) {
        const int cb = nt * 8 + 2 * tg;
        float2 v1; v1.x = o[nt][0] * inv1; v1.y = o[nt][1] * inv1;
        float2 v2; v2.x = o[nt][2] * inv2; v2.y = o[nt][3] * inv2;
        *reinterpret_cast<float2*>(O + base + (size_t)(q0 + row1) * HD + cb) = v1;
        *reinterpret_cast<float2*>(O + base + (size_t)(q0 + row2) * HD + cb) = v2;
    }
}

// ---------------- launch ----------------------------------------------------
extern "C" void kernel_launch(void* const* d_in, const int* in_sizes, int n_in,
                              void* d_out, int out_size) {
    const float* x     = (const float*)d_in[0];
    const float* gamma = (const float*)d_in[1];
    const float* beta  = (const float*)d_in[2];
    const float* Wq    = (const float*)d_in[3];
    const float* bq    = (const float*)d_in[4];
    const float* Wk    = (const float*)d_in[5];
    const float* bk    = (const float*)d_in[6];
    const float* Wv    = (const float*)d_in[7];
    const float* bv    = (const float*)d_in[8];
    const float* Wo    = (const float*)d_in[9];
    const float* bo    = (const float*)d_in[10];
    float* out = (float*)d_out;

    float *xn, *qp, *kp, *vp, *ao;
    cudaGetSymbolAddress((void**)&xn, g_xn);
    cudaGetSymbolAddress((void**)&qp, g_q);
    cudaGetSymbolAddress((void**)&kp, g_k);
    cudaGetSymbolAddress((void**)&vp, g_v);
    cudaGetSymbolAddress((void**)&ao, g_ao);

    ln_kernel<<<Mrows, 256>>>(x, gamma, beta, xn);

    dim3 gg(HD / BN, Mrows / BM);   // (8, 64)
    gemm_tf32_kernel<<<gg, 256>>>(xn, Wq, bq, nullptr, qp, Mrows, HD, Edim);
    gemm_tf32_kernel<<<gg, 256>>>(xn, Wk, bk, nullptr, kp, Mrows, HD, Edim);
    gemm_tf32_kernel<<<gg, 256>>>(xn, Wv, bv, nullptr, vp, Mrows, HD, Edim);

    cudaFuncSetAttribute(attn_tf32_kernel, cudaFuncAttributeMaxDynamicSharedMemorySize,
                         ATTN_SMEM_BYTES);
    attn_tf32_kernel<<<dim3(Sdim / 64, Hdim, Bdim), 128, ATTN_SMEM_BYTES>>>(qp, kp, vp, ao);

    gemm_tf32_kernel<<<dim3(Edim / BN, Mrows / BM), 256>>>(ao, Wo, bo, x, out, Mrows, Edim, HD);
}

// round 3
// speedup vs baseline: 3.3762x; 1.1020x over previous
#include <cuda_runtime.h>
#include <math.h>
#include <stdint.h>

#define Bdim 4
#define Sdim 2048
#define Edim 1024
#define Hdim 16
#define Ddim 64
#define Mrows (Bdim * Sdim)          // 8192
#define HD (Hdim * Ddim)             // 1024

// ---------------- scratch (static device globals; no allocs) ----------------
__device__ float g_xn[Mrows * Edim];
__device__ float g_q [Mrows * HD];
__device__ float g_k [Mrows * HD];
__device__ float g_v [Mrows * HD];
__device__ float g_ao[Mrows * HD];

// ---------------- helpers ----------------------------------------------------
__device__ __forceinline__ float f2tf(float x) {
    uint32_t u;
    asm("cvt.rna.tf32.f32 %0, %1;" : "=r"(u) : "f"(x));
    return __uint_as_float(u);
}
__device__ __forceinline__ uint32_t fu(float x) { return __float_as_uint(x); }

// D(16x8) += A(16x8,row) * B(8x8,col)  tf32
__device__ __forceinline__ void mma_tf32(float c[4],
                                         uint32_t a0, uint32_t a1, uint32_t a2, uint32_t a3,
                                         uint32_t b0, uint32_t b1) {
    asm volatile(
        "mma.sync.aligned.m16n8k8.row.col.f32.tf32.tf32.f32 "
        "{%0,%1,%2,%3}, {%4,%5,%6,%7}, {%8,%9}, {%0,%1,%2,%3};\n"
        : "+f"(c[0]), "+f"(c[1]), "+f"(c[2]), "+f"(c[3])
        : "r"(a0), "r"(a1), "r"(a2), "r"(a3), "r"(b0), "r"(b1));
}

// ldmatrix x4 (b16): on tf32 data this yields exactly the tf32 mma A-fragment.
__device__ __forceinline__ void ldsm4(uint32_t r[4], uint32_t addr) {
    asm volatile("ldmatrix.sync.aligned.m8n8.x4.shared.b16 {%0,%1,%2,%3}, [%4];"
                 : "=r"(r[0]), "=r"(r[1]), "=r"(r[2]), "=r"(r[3])
                 : "r"(addr));
}

// ---------------- LayerNorm --------------------------------------------------
__global__ void __launch_bounds__(256) ln_kernel(const float* __restrict__ x,
                                                 const float* __restrict__ gamma,
                                                 const float* __restrict__ beta,
                                                 float* __restrict__ y) {
    const int row = blockIdx.x;
    const int tid = threadIdx.x;
    const float4 xv = reinterpret_cast<const float4*>(x + (size_t)row * Edim)[tid];
    float s  = xv.x + xv.y + xv.z + xv.w;
    float ss = xv.x * xv.x + xv.y * xv.y + xv.z * xv.z + xv.w * xv.w;
    #pragma unroll
    for (int m = 16; m; m >>= 1) {
        s  += __shfl_xor_sync(0xffffffffu, s,  m);
        ss += __shfl_xor_sync(0xffffffffu, ss, m);
    }
    __shared__ float sh_s[8], sh_ss[8];
    __shared__ float s_mu, s_rstd;
    const int w = tid >> 5, l = tid & 31;
    if (l == 0) { sh_s[w] = s; sh_ss[w] = ss; }
    __syncthreads();
    if (w == 0) {
        float a = (l < 8) ? sh_s[l]  : 0.f;
        float c = (l < 8) ? sh_ss[l] : 0.f;
        #pragma unroll
        for (int m = 4; m; m >>= 1) {
            a += __shfl_xor_sync(0xffffffffu, a, m);
            c += __shfl_xor_sync(0xffffffffu, c, m);
        }
        if (l == 0) {
            float mu  = a * (1.0f / Edim);
            float var = c * (1.0f / Edim) - mu * mu;
            s_mu = mu;
            s_rstd = rsqrtf(var + 1e-5f);
        }
    }
    __syncthreads();
    const float mu = s_mu, rstd = s_rstd;
    const float4 gv = reinterpret_cast<const float4*>(gamma)[tid];
    const float4 bv = reinterpret_cast<const float4*>(beta)[tid];
    float4 yv;
    yv.x = (xv.x - mu) * rstd * gv.x + bv.x;
    yv.y = (xv.y - mu) * rstd * gv.y + bv.y;
    yv.z = (xv.z - mu) * rstd * gv.z + bv.z;
    yv.w = (xv.w - mu) * rstd * gv.w + bv.w;
    reinterpret_cast<float4*>(y + (size_t)row * Edim)[tid] = yv;
}

// ---------------- TF32 tensor-core GEMM (ldmatrix A path) -------------------
// C = A(MxK) * W(KxN) + bias (+ residual). 128x128 block, BK=16, 256 threads.
// A smem: row-major, stride 20 (LDSM conflict-free). B smem: k-major, stride 136.
#define BM 128
#define BN 128
#define BK 16
#define ASTRIDE 20
#define BSTR 136

__global__ void __launch_bounds__(256, 2) gemm_tf32_kernel(const float* __restrict__ A,
                                                           const float* __restrict__ W,
                                                           const float* __restrict__ bias,
                                                           const float* __restrict__ res,
                                                           float* __restrict__ C,
                                                           int M, int N, int K) {
    __shared__ __align__(16) float As[2][BM * ASTRIDE];
    __shared__ __align__(16) float Bs[2][BK * BSTR];

    const int tid  = threadIdx.x;
    const int lane = tid & 31;
    const int wid  = tid >> 5;
    const int g  = lane >> 2;   // 0..7
    const int tg = lane & 3;    // 0..3
    const int wm = wid >> 2;    // 0..1
    const int wn = wid & 3;     // 0..3
    const int row0 = blockIdx.y * BM;
    const int col0 = blockIdx.x * BN;

    // global-load mapping
    const int ar = tid >> 2;            // 0..63 (+64)
    const int ac = (tid & 3) << 2;      // 0,4,8,12
    const int br = tid >> 5;            // 0..7 (+8)
    const int bc = (tid & 31) << 2;     // 0..124

    const float* Ap = A + (size_t)(row0 + ar) * K + ac;
    const float* Bp = W + (size_t)br * N + col0 + bc;

    // LDSM per-lane base (rows wm*64 + lane&15, col quad (lane>>4)*4)
    const uint32_t as_u32 = (uint32_t)__cvta_generic_to_shared(&As[0][0]);
    const uint32_t a_ldsm_base = as_u32 +
        (((wm * 64 + (lane & 15)) * ASTRIDE) + ((lane >> 4) << 2)) * 4u;

    float4 a0v = *reinterpret_cast<const float4*>(Ap);
    float4 a1v = *reinterpret_cast<const float4*>(Ap + (size_t)64 * K);
    float4 b0v = *reinterpret_cast<const float4*>(Bp);
    float4 b1v = *reinterpret_cast<const float4*>(Bp + (size_t)8 * N);

    {
        float4 t;
        t.x = f2tf(a0v.x); t.y = f2tf(a0v.y); t.z = f2tf(a0v.z); t.w = f2tf(a0v.w);
        *reinterpret_cast<float4*>(&As[0][ar * ASTRIDE + ac]) = t;
        t.x = f2tf(a1v.x); t.y = f2tf(a1v.y); t.z = f2tf(a1v.z); t.w = f2tf(a1v.w);
        *reinterpret_cast<float4*>(&As[0][(ar + 64) * ASTRIDE + ac]) = t;
        t.x = f2tf(b0v.x); t.y = f2tf(b0v.y); t.z = f2tf(b0v.z); t.w = f2tf(b0v.w);
        *reinterpret_cast<float4*>(&Bs[0][br * BSTR + bc]) = t;
        t.x = f2tf(b1v.x); t.y = f2tf(b1v.y); t.z = f2tf(b1v.z); t.w = f2tf(b1v.w);
        *reinterpret_cast<float4*>(&Bs[0][(br + 8) * BSTR + bc]) = t;
    }
    __syncthreads();

    float acc[4][4][4] = {};
    const int NIT = K / BK;

    for (int it = 0; it < NIT; it++) {
        const int cur = it & 1;
        if (it + 1 < NIT) {
            const float* Ap2 = Ap + (it + 1) * BK;
            const float* Bp2 = Bp + (size_t)(it + 1) * BK * N;
            a0v = *reinterpret_cast<const float4*>(Ap2);
            a1v = *reinterpret_cast<const float4*>(Ap2 + (size_t)64 * K);
            b0v = *reinterpret_cast<const float4*>(Bp2);
            b1v = *reinterpret_cast<const float4*>(Bp2 + (size_t)8 * N);
        }

        const float* Bsc = Bs[cur];
        const uint32_t a_base = a_ldsm_base + cur * (BM * ASTRIDE * 4);
        #pragma unroll
        for (int kb = 0; kb < 2; kb++) {
            const int k0 = kb * 8;
            uint32_t af[4][4];
            #pragma unroll
            for (int mi = 0; mi < 4; mi++)
                ldsm4(af[mi], a_base + (mi * 16 * ASTRIDE + k0) * 4u);
            uint32_t bf[4][2];
            #pragma unroll
            for (int ni = 0; ni < 4; ni++) {
                const int cb = wn * 32 + ni * 8 + g;
                bf[ni][0] = fu(Bsc[(k0 + tg)     * BSTR + cb]);
                bf[ni][1] = fu(Bsc[(k0 + tg + 4) * BSTR + cb]);
            }
            #pragma unroll
            for (int mi = 0; mi < 4; mi++)
                #pragma unroll
                for (int ni = 0; ni < 4; ni++)
                    mma_tf32(acc[mi][ni], af[mi][0], af[mi][1], af[mi][2], af[mi][3],
                             bf[ni][0], bf[ni][1]);
        }

        if (it + 1 < NIT) {
            const int nxt = cur ^ 1;
            float4 t;
            t.x = f2tf(a0v.x); t.y = f2tf(a0v.y); t.z = f2tf(a0v.z); t.w = f2tf(a0v.w);
            *reinterpret_cast<float4*>(&As[nxt][ar * ASTRIDE + ac]) = t;
            t.x = f2tf(a1v.x); t.y = f2tf(a1v.y); t.z = f2tf(a1v.z); t.w = f2tf(a1v.w);
            *reinterpret_cast<float4*>(&As[nxt][(ar + 64) * ASTRIDE + ac]) = t;
            t.x = f2tf(b0v.x); t.y = f2tf(b0v.y); t.z = f2tf(b0v.z); t.w = f2tf(b0v.w);
            *reinterpret_cast<float4*>(&Bs[nxt][br * BSTR + bc]) = t;
            t.x = f2tf(b1v.x); t.y = f2tf(b1v.y); t.z = f2tf(b1v.z); t.w = f2tf(b1v.w);
            *reinterpret_cast<float4*>(&Bs[nxt][(br + 8) * BSTR + bc]) = t;
        }
        __syncthreads();
    }

    // epilogue: bias (+ residual)
    #pragma unroll
    for (int mi = 0; mi < 4; mi++) {
        const int r1 = row0 + wm * 64 + mi * 16 + g;
        const int r2 = r1 + 8;
        #pragma unroll
        for (int ni = 0; ni < 4; ni++) {
            const int cb = col0 + wn * 32 + ni * 8 + 2 * tg;
            float2 v1, v2;
            v1.x = acc[mi][ni][0] + bias[cb];
            v1.y = acc[mi][ni][1] + bias[cb + 1];
            v2.x = acc[mi][ni][2] + bias[cb];
            v2.y = acc[mi][ni][3] + bias[cb + 1];
            if (res) {
                const float2 r1v = *reinterpret_cast<const float2*>(res + (size_t)r1 * N + cb);
                const float2 r2v = *reinterpret_cast<const float2*>(res + (size_t)r2 * N + cb);
                v1.x += r1v.x; v1.y += r1v.y;
                v2.x += r2v.x; v2.y += r2v.y;
            }
            *reinterpret_cast<float2*>(C + (size_t)r1 * N + cb) = v1;
            *reinterpret_cast<float2*>(C + (size_t)r2 * N + cb) = v2;
        }
    }
}

// ---------------- Flash attention (causal) with tf32 mma + LDSM -------------
// grid (S/64, H, B), 128 threads (4 warps). Warp w owns query rows [16w,16w+16).
// Qs/Ps stride 76 (LDSM conflict-free); Ks/Vs stride 72.
// Ks uses paired-k column permutation: col' = 2*(k&3) + ((k>>2)&1) + (k&~7)
// so the b-fragment (k=tg, k=tg+4) is one float2.
#define QP_STR 76
#define KV_STR 72
#define ATTN_SMEM_FLOATS (2 * 64 * QP_STR + 2 * 64 * KV_STR)
#define ATTN_SMEM_BYTES (ATTN_SMEM_FLOATS * 4)

__global__ void __launch_bounds__(128) attn_tf32_kernel(const float* __restrict__ Q,
                                                        const float* __restrict__ K,
                                                        const float* __restrict__ V,
                                                        float* __restrict__ O) {
    extern __shared__ __align__(16) float sm[];
    float* Qs = sm;
    float* Ps = Qs + 64 * QP_STR;
    float* Ks = Ps + 64 * QP_STR;
    float* Vs = Ks + 64 * KV_STR;

    const int tid  = threadIdx.x;
    const int lane = tid & 31;
    const int wid  = tid >> 5;      // 0..3
    const int g  = lane >> 2;
    const int tg = lane & 3;
    const int rbase = wid * 16;
    const int q0 = blockIdx.x * 64;
    const int h = blockIdx.y, b = blockIdx.z;
    const size_t base = (size_t)b * Sdim * HD + (size_t)h * Ddim;

    const uint32_t q_u32 = (uint32_t)__cvta_generic_to_shared(Qs);
    const uint32_t p_u32 = (uint32_t)__cvta_generic_to_shared(Ps);
    const uint32_t q_ldsm = q_u32 + (((rbase + (lane & 15)) * QP_STR) + ((lane >> 4) << 2)) * 4u;
    const uint32_t p_ldsm = p_u32 + (((rbase + (lane & 15)) * QP_STR) + ((lane >> 4) << 2)) * 4u;

    // load Q tile (64x64), tf32-rounded
    #pragma unroll
    for (int it = 0; it < 8; it++) {
        const int f4i = tid + it * 128;
        const int r = f4i >> 4, c4 = (f4i & 15) << 2;
        float4 qv = *reinterpret_cast<const float4*>(Q + base + (size_t)(q0 + r) * HD + c4);
        float4 t;
        t.x = f2tf(qv.x); t.y = f2tf(qv.y); t.z = f2tf(qv.z); t.w = f2tf(qv.w);
        *reinterpret_cast<float4*>(&Qs[r * QP_STR + c4]) = t;
    }

    float m1 = -1e30f, m2 = -1e30f, l1 = 0.f, l2 = 0.f;
    float o[8][4] = {};
    const int row1 = rbase + g, row2 = row1 + 8;   // block-local query rows
    const int ntiles = (q0 >> 6) + 1;

    for (int jt = 0; jt < ntiles; jt++) {
        const int j0 = jt * 64;
        __syncthreads();   // prev iter done with Ks/Vs; also covers initial Q visibility
        #pragma unroll
        for (int it = 0; it < 8; it++) {
            const int f4i = tid + it * 128;
            const int r = f4i >> 4, c4 = (f4i & 15) << 2;
            float4 kv = *reinterpret_cast<const float4*>(K + base + (size_t)(j0 + r) * HD + c4);
            // paired-k permuted scatter
            const int cperm = ((c4 >> 2) & 1) + (c4 & ~7);
            float* dk = &Ks[r * KV_STR + cperm];
            dk[0] = f2tf(kv.x); dk[2] = f2tf(kv.y); dk[4] = f2tf(kv.z); dk[6] = f2tf(kv.w);
            float4 vv = *reinterpret_cast<const float4*>(V + base + (size_t)(j0 + r) * HD + c4);
            float4 t;
            t.x = f2tf(vv.x); t.y = f2tf(vv.y); t.z = f2tf(vv.z); t.w = f2tf(vv.w);
            *reinterpret_cast<float4*>(&Vs[r * KV_STR + c4]) = t;
        }
        __syncthreads();

        // S = Q K^T  (warp: 16 rows x 64 cols)
        float s[8][4] = {};
        #pragma unroll
        for (int kb = 0; kb < 8; kb++) {
            uint32_t af[4];
            ldsm4(af, q_ldsm + kb * 32u);
            #pragma unroll
            for (int nt = 0; nt < 8; nt++) {
                const float2 bp = *reinterpret_cast<const float2*>(
                    &Ks[(nt * 8 + g) * KV_STR + kb * 8 + 2 * tg]);
                mma_tf32(s[nt], af[0], af[1], af[2], af[3], fu(bp.x), fu(bp.y));
            }
        }

        // online softmax
        const bool diag = (jt == ntiles - 1);
        float rm1 = -1e30f, rm2 = -1e30f;
        #pragma unroll
        for (int nt = 0; nt < 8; nt++) {
            s[nt][0] *= 0.125f; s[nt][1] *= 0.125f; s[nt][2] *= 0.125f; s[nt][3] *= 0.125f;
            if (diag) {
                const int c0 = nt * 8 + 2 * tg;
                if (c0     > row1) s[nt][0] = -1e30f;
                if (c0 + 1 > row1) s[nt][1] = -1e30f;
                if (c0     > row2) s[nt][2] = -1e30f;
                if (c0 + 1 > row2) s[nt][3] = -1e30f;
            }
            rm1 = fmaxf(rm1, fmaxf(s[nt][0], s[nt][1]));
            rm2 = fmaxf(rm2, fmaxf(s[nt][2], s[nt][3]));
        }
        rm1 = fmaxf(rm1, __shfl_xor_sync(0xffffffffu, rm1, 1));
        rm1 = fmaxf(rm1, __shfl_xor_sync(0xffffffffu, rm1, 2));
        rm2 = fmaxf(rm2, __shfl_xor_sync(0xffffffffu, rm2, 1));
        rm2 = fmaxf(rm2, __shfl_xor_sync(0xffffffffu, rm2, 2));

        const float mn1 = fmaxf(m1, rm1), mn2 = fmaxf(m2, rm2);
        const float sc1 = __expf(m1 - mn1), sc2 = __expf(m2 - mn2);
        m1 = mn1; m2 = mn2;

        float sum1 = 0.f, sum2 = 0.f;
        #pragma unroll
        for (int nt = 0; nt < 8; nt++) {
            const float p0 = __expf(s[nt][0] - mn1);
            const float p1 = __expf(s[nt][1] - mn1);
            const float p2 = __expf(s[nt][2] - mn2);
            const float p3 = __expf(s[nt][3] - mn2);
            sum1 += p0 + p1;
            sum2 += p2 + p3;
            const int cb = nt * 8 + 2 * tg;
            float2 w1; w1.x = f2tf(p0); w1.y = f2tf(p1);
            float2 w2; w2.x = f2tf(p2); w2.y = f2tf(p3);
            *reinterpret_cast<float2*>(&Ps[row1 * QP_STR + cb]) = w1;
            *reinterpret_cast<float2*>(&Ps[row2 * QP_STR + cb]) = w2;
        }
        sum1 += __shfl_xor_sync(0xffffffffu, sum1, 1);
        sum1 += __shfl_xor_sync(0xffffffffu, sum1, 2);
        sum2 += __shfl_xor_sync(0xffffffffu, sum2, 1);
        sum2 += __shfl_xor_sync(0xffffffffu, sum2, 2);
        l1 = l1 * sc1 + sum1;
        l2 = l2 * sc2 + sum2;

        #pragma unroll
        for (int nt = 0; nt < 8; nt++) {
            o[nt][0] *= sc1; o[nt][1] *= sc1;
            o[nt][2] *= sc2; o[nt][3] *= sc2;
        }
        __syncwarp();   // P writes visible within warp (each warp reads own 16 rows)

        // O += P V   (A=P 16x64, B=V 64x64)
        #pragma unroll
        for (int kb = 0; kb < 8; kb++) {
            const int k0 = kb * 8;
            uint32_t af[4];
            ldsm4(af, p_ldsm + kb * 32u);
            #pragma unroll
            for (int nt = 0; nt < 8; nt++) {
                const uint32_t b0 = fu(Vs[(k0 + tg)     * KV_STR + nt * 8 + g]);
                const uint32_t b1 = fu(Vs[(k0 + tg + 4) * KV_STR + nt * 8 + g]);
                mma_tf32(o[nt], af[0], af[1], af[2], af[3], b0, b1);
            }
        }
    }

    const float inv1 = 1.0f / l1;
    const float inv2 = 1.0f / l2;
    #pragma unroll
    for (int nt = 0; nt < 8; nt++) {
        const int cb = nt * 8 + 2 * tg;
        float2 v1; v1.x = o[nt][0] * inv1; v1.y = o[nt][1] * inv1;
        float2 v2; v2.x = o[nt][2] * inv2; v2.y = o[nt][3] * inv2;
        *reinterpret_cast<float2*>(O + base + (size_t)(q0 + row1) * HD + cb) = v1;
        *reinterpret_cast<float2*>(O + base + (size_t)(q0 + row2) * HD + cb) = v2;
    }
}

// ---------------- launch ----------------------------------------------------
extern "C" void kernel_launch(void* const* d_in, const int* in_sizes, int n_in,
                              void* d_out, int out_size) {
    const float* x     = (const float*)d_in[0];
    const float* gamma = (const float*)d_in[1];
    const float* beta  = (const float*)d_in[2];
    const float* Wq    = (const float*)d_in[3];
    const float* bq    = (const float*)d_in[4];
    const float* Wk    = (const float*)d_in[5];
    const float* bk    = (const float*)d_in[6];
    const float* Wv    = (const float*)d_in[7];
    const float* bv    = (const float*)d_in[8];
    const float* Wo    = (const float*)d_in[9];
    const float* bo    = (const float*)d_in[10];
    float* out = (float*)d_out;

    float *xn, *qp, *kp, *vp, *ao;
    cudaGetSymbolAddress((void**)&xn, g_xn);
    cudaGetSymbolAddress((void**)&qp, g_q);
    cudaGetSymbolAddress((void**)&kp, g_k);
    cudaGetSymbolAddress((void**)&vp, g_v);
    cudaGetSymbolAddress((void**)&ao, g_ao);

    ln_kernel<<<Mrows, 256>>>(x, gamma, beta, xn);

    dim3 gg(HD / BN, Mrows / BM);   // (8, 64)
    gemm_tf32_kernel<<<gg, 256>>>(xn, Wq, bq, nullptr, qp, Mrows, HD, Edim);
    gemm_tf32_kernel<<<gg, 256>>>(xn, Wk, bk, nullptr, kp, Mrows, HD, Edim);
    gemm_tf32_kernel<<<gg, 256>>>(xn, Wv, bv, nullptr, vp, Mrows, HD, Edim);

    cudaFuncSetAttribute(attn_tf32_kernel, cudaFuncAttributeMaxDynamicSharedMemorySize,
                         ATTN_SMEM_BYTES);
    attn_tf32_kernel<<<dim3(Sdim / 64, Hdim, Bdim), 128, ATTN_SMEM_BYTES>>>(qp, kp, vp, ao);

    gemm_tf32_kernel<<<dim3(Edim / BN, Mrows / BM), 256>>>(ao, Wo, bo, x, out, Mrows, Edim, HD);
}

// round 4
// speedup vs baseline: 3.7278x; 1.1041x over previous
#include <cuda_runtime.h>
#include <math.h>
#include <stdint.h>

#define Bdim 4
#define Sdim 2048
#define Edim 1024
#define Hdim 16
#define Ddim 64
#define Mrows (Bdim * Sdim)          // 8192
#define HD (Hdim * Ddim)             // 1024

// ---------------- scratch (static device globals; no allocs) ----------------
__device__ float g_xn[Mrows * Edim];
__device__ float g_q [Mrows * HD];
__device__ float g_k [Mrows * HD];
__device__ float g_v [Mrows * HD];
__device__ float g_ao[Mrows * HD];

// ---------------- helpers ----------------------------------------------------
__device__ __forceinline__ uint32_t fu(float x) { return __float_as_uint(x); }

// D(16x8) += A(16x8,row) * B(8x8,col)  tf32 (HW converts fp32 operands)
__device__ __forceinline__ void mma_tf32(float c[4],
                                         uint32_t a0, uint32_t a1, uint32_t a2, uint32_t a3,
                                         uint32_t b0, uint32_t b1) {
    asm volatile(
        "mma.sync.aligned.m16n8k8.row.col.f32.tf32.tf32.f32 "
        "{%0,%1,%2,%3}, {%4,%5,%6,%7}, {%8,%9}, {%0,%1,%2,%3};\n"
        : "+f"(c[0]), "+f"(c[1]), "+f"(c[2]), "+f"(c[3])
        : "r"(a0), "r"(a1), "r"(a2), "r"(a3), "r"(b0), "r"(b1));
}

// ldmatrix x4 (b16): on 32-bit data this yields exactly the tf32 mma A-fragment.
__device__ __forceinline__ void ldsm4(uint32_t r[4], uint32_t addr) {
    asm volatile("ldmatrix.sync.aligned.m8n8.x4.shared.b16 {%0,%1,%2,%3}, [%4];"
                 : "=r"(r[0]), "=r"(r[1]), "=r"(r[2]), "=r"(r[3])
                 : "r"(addr));
}

__device__ __forceinline__ void cp16(uint32_t dst, const void* src) {
    asm volatile("cp.async.cg.shared.global [%0], [%1], 16;" :: "r"(dst), "l"(src));
}
__device__ __forceinline__ void cp_commit() {
    asm volatile("cp.async.commit_group;");
}
template <int N>
__device__ __forceinline__ void cp_wait() {
    asm volatile("cp.async.wait_group %0;" :: "n"(N));
}

// ---------------- LayerNorm --------------------------------------------------
__global__ void __launch_bounds__(256) ln_kernel(const float* __restrict__ x,
                                                 const float* __restrict__ gamma,
                                                 const float* __restrict__ beta,
                                                 float* __restrict__ y) {
    const int row = blockIdx.x;
    const int tid = threadIdx.x;
    const float4 xv = reinterpret_cast<const float4*>(x + (size_t)row * Edim)[tid];
    float s  = xv.x + xv.y + xv.z + xv.w;
    float ss = xv.x * xv.x + xv.y * xv.y + xv.z * xv.z + xv.w * xv.w;
    #pragma unroll
    for (int m = 16; m; m >>= 1) {
        s  += __shfl_xor_sync(0xffffffffu, s,  m);
        ss += __shfl_xor_sync(0xffffffffu, ss, m);
    }
    __shared__ float sh_s[8], sh_ss[8];
    __shared__ float s_mu, s_rstd;
    const int w = tid >> 5, l = tid & 31;
    if (l == 0) { sh_s[w] = s; sh_ss[w] = ss; }
    __syncthreads();
    if (w == 0) {
        float a = (l < 8) ? sh_s[l]  : 0.f;
        float c = (l < 8) ? sh_ss[l] : 0.f;
        #pragma unroll
        for (int m = 4; m; m >>= 1) {
            a += __shfl_xor_sync(0xffffffffu, a, m);
            c += __shfl_xor_sync(0xffffffffu, c, m);
        }
        if (l == 0) {
            float mu  = a * (1.0f / Edim);
            float var = c * (1.0f / Edim) - mu * mu;
            s_mu = mu;
            s_rstd = rsqrtf(var + 1e-5f);
        }
    }
    __syncthreads();
    const float mu = s_mu, rstd = s_rstd;
    const float4 gv = reinterpret_cast<const float4*>(gamma)[tid];
    const float4 bv = reinterpret_cast<const float4*>(beta)[tid];
    float4 yv;
    yv.x = (xv.x - mu) * rstd * gv.x + bv.x;
    yv.y = (xv.y - mu) * rstd * gv.y + bv.y;
    yv.z = (xv.z - mu) * rstd * gv.z + bv.z;
    yv.w = (xv.w - mu) * rstd * gv.w + bv.w;
    reinterpret_cast<float4*>(y + (size_t)row * Edim)[tid] = yv;
}

// ---------------- TF32 GEMM: 4-stage cp.async pipeline ----------------------
// C = A(MxK) * W(KxN) + bias (+ residual). 128x128 block, BK=16, 256 threads.
#define BM 128
#define BN 128
#define BK 16
#define ASTRIDE 20
#define BSTR 136
#define STAGES 4
#define A_STAGE_F (BM * ASTRIDE)          // 2560 floats
#define B_STAGE_F (BK * BSTR)             // 2176 floats
#define GEMM_SMEM_BYTES ((STAGES * (A_STAGE_F + B_STAGE_F)) * 4)   // 75776 B

__global__ void __launch_bounds__(256, 2) gemm_tf32_kernel(const float* __restrict__ A,
                                                           const float* __restrict__ W,
                                                           const float* __restrict__ bias,
                                                           const float* __restrict__ res,
                                                           float* __restrict__ C,
                                                           int M, int N, int K) {
    extern __shared__ __align__(16) float smem[];
    float* Asm = smem;                          // STAGES * A_STAGE_F
    float* Bsm = smem + STAGES * A_STAGE_F;     // STAGES * B_STAGE_F

    const int tid  = threadIdx.x;
    const int lane = tid & 31;
    const int wid  = tid >> 5;
    const int g  = lane >> 2;   // 0..7
    const int tg = lane & 3;    // 0..3
    const int wm = wid >> 2;    // 0..1
    const int wn = wid & 3;     // 0..3
    const int row0 = blockIdx.y * BM;
    const int col0 = blockIdx.x * BN;

    // global-load mapping
    const int ar = tid >> 2;            // 0..63 (+64)
    const int ac = (tid & 3) << 2;      // 0,4,8,12
    const int br = tid >> 5;            // 0..7 (+8)
    const int bc = (tid & 31) << 2;     // 0..124

    const float* Ap = A + (size_t)(row0 + ar) * K + ac;
    const float* Bp = W + (size_t)br * N + col0 + bc;

    const uint32_t asm_u32 = (uint32_t)__cvta_generic_to_shared(Asm);
    const uint32_t bsm_u32 = (uint32_t)__cvta_generic_to_shared(Bsm);
    const uint32_t a_dst0 = asm_u32 + (ar * ASTRIDE + ac) * 4u;
    const uint32_t a_dst1 = asm_u32 + ((ar + 64) * ASTRIDE + ac) * 4u;
    const uint32_t b_dst0 = bsm_u32 + (br * BSTR + bc) * 4u;
    const uint32_t b_dst1 = bsm_u32 + ((br + 8) * BSTR + bc) * 4u;

    // LDSM per-lane base (rows wm*64 + lane&15, col quad (lane>>4)*4)
    const uint32_t a_ldsm_base = asm_u32 +
        (((wm * 64 + (lane & 15)) * ASTRIDE) + ((lane >> 4) << 2)) * 4u;

    const int NIT = K / BK;

    // prologue: issue STAGES-1 stages
    #pragma unroll
    for (int s = 0; s < STAGES - 1; s++) {
        const uint32_t ao = s * (A_STAGE_F * 4u);
        const uint32_t bo = s * (B_STAGE_F * 4u);
        const float* Aps = Ap + s * BK;
        const float* Bps = Bp + (size_t)s * BK * N;
        cp16(a_dst0 + ao, Aps);
        cp16(a_dst1 + ao, Aps + (size_t)64 * K);
        cp16(b_dst0 + bo, Bps);
        cp16(b_dst1 + bo, Bps + (size_t)8 * N);
        cp_commit();
    }

    float acc[4][4][4] = {};

    for (int it = 0; it < NIT; it++) {
        cp_wait<STAGES - 2>();
        __syncthreads();

        // issue stage it+STAGES-1 into buffer (it+STAGES-1)%STAGES == (it-1)%STAGES
        if (it + STAGES - 1 < NIT) {
            const int s = (it + STAGES - 1) % STAGES;
            const uint32_t ao = s * (A_STAGE_F * 4u);
            const uint32_t bo = s * (B_STAGE_F * 4u);
            const float* Aps = Ap + (it + STAGES - 1) * BK;
            const float* Bps = Bp + (size_t)(it + STAGES - 1) * BK * N;
            cp16(a_dst0 + ao, Aps);
            cp16(a_dst1 + ao, Aps + (size_t)64 * K);
            cp16(b_dst0 + bo, Bps);
            cp16(b_dst1 + bo, Bps + (size_t)8 * N);
        }
        cp_commit();

        const int cur = it % STAGES;
        const float* Bsc = Bsm + cur * B_STAGE_F;
        const uint32_t a_base = a_ldsm_base + cur * (A_STAGE_F * 4u);
        #pragma unroll
        for (int kb = 0; kb < 2; kb++) {
            const int k0 = kb * 8;
            uint32_t af[4][4];
            #pragma unroll
            for (int mi = 0; mi < 4; mi++)
                ldsm4(af[mi], a_base + (mi * 16 * ASTRIDE + k0) * 4u);
            uint32_t bf[4][2];
            #pragma unroll
            for (int ni = 0; ni < 4; ni++) {
                const int cb = wn * 32 + ni * 8 + g;
                bf[ni][0] = fu(Bsc[(k0 + tg)     * BSTR + cb]);
                bf[ni][1] = fu(Bsc[(k0 + tg + 4) * BSTR + cb]);
            }
            #pragma unroll
            for (int mi = 0; mi < 4; mi++)
                #pragma unroll
                for (int ni = 0; ni < 4; ni++)
                    mma_tf32(acc[mi][ni], af[mi][0], af[mi][1], af[mi][2], af[mi][3],
                             bf[ni][0], bf[ni][1]);
        }
    }

    // epilogue: bias (+ residual)
    #pragma unroll
    for (int mi = 0; mi < 4; mi++) {
        const int r1 = row0 + wm * 64 + mi * 16 + g;
        const int r2 = r1 + 8;
        #pragma unroll
        for (int ni = 0; ni < 4; ni++) {
            const int cb = col0 + wn * 32 + ni * 8 + 2 * tg;
            float2 v1, v2;
            v1.x = acc[mi][ni][0] + bias[cb];
            v1.y = acc[mi][ni][1] + bias[cb + 1];
            v2.x = acc[mi][ni][2] + bias[cb];
            v2.y = acc[mi][ni][3] + bias[cb + 1];
            if (res) {
                const float2 r1v = *reinterpret_cast<const float2*>(res + (size_t)r1 * N + cb);
                const float2 r2v = *reinterpret_cast<const float2*>(res + (size_t)r2 * N + cb);
                v1.x += r1v.x; v1.y += r1v.y;
                v2.x += r2v.x; v2.y += r2v.y;
            }
            *reinterpret_cast<float2*>(C + (size_t)r1 * N + cb) = v1;
            *reinterpret_cast<float2*>(C + (size_t)r2 * N + cb) = v2;
        }
    }
}

// ---------------- Flash attention (causal), tf32 mma + LDSM + cp.async ------
// grid (S/64, H, B), 128 threads (4 warps). Warp w owns query rows [16w,16w+16).
// Qs/Ps stride 76 (LDSM conflict-free); Ks/Vs stride 72, plain row-major.
#define QP_STR 76
#define KV_STR 72
#define ATTN_SMEM_FLOATS (2 * 64 * QP_STR + 2 * 64 * KV_STR)
#define ATTN_SMEM_BYTES (ATTN_SMEM_FLOATS * 4)

__global__ void __launch_bounds__(128) attn_tf32_kernel(const float* __restrict__ Q,
                                                        const float* __restrict__ K,
                                                        const float* __restrict__ V,
                                                        float* __restrict__ O) {
    extern __shared__ __align__(16) float sm[];
    float* Qs = sm;
    float* Ps = Qs + 64 * QP_STR;
    float* Ks = Ps + 64 * QP_STR;
    float* Vs = Ks + 64 * KV_STR;

    const int tid  = threadIdx.x;
    const int lane = tid & 31;
    const int wid  = tid >> 5;      // 0..3
    const int g  = lane >> 2;
    const int tg = lane & 3;
    const int rbase = wid * 16;
    const int q0 = blockIdx.x * 64;
    const int h = blockIdx.y, b = blockIdx.z;
    const size_t base = (size_t)b * Sdim * HD + (size_t)h * Ddim;

    const uint32_t q_u32 = (uint32_t)__cvta_generic_to_shared(Qs);
    const uint32_t p_u32 = (uint32_t)__cvta_generic_to_shared(Ps);
    const uint32_t k_u32 = (uint32_t)__cvta_generic_to_shared(Ks);
    const uint32_t v_u32 = (uint32_t)__cvta_generic_to_shared(Vs);
    const uint32_t q_ldsm = q_u32 + (((rbase + (lane & 15)) * QP_STR) + ((lane >> 4) << 2)) * 4u;
    const uint32_t p_ldsm = p_u32 + (((rbase + (lane & 15)) * QP_STR) + ((lane >> 4) << 2)) * 4u;

    // per-thread tile-copy mapping: 8 chunks of 16B, chunk i covers (r, c4)
    // f4i = tid + i*128 ; r = f4i>>4 ; c4 = (f4i&15)<<2
    // load Q tile (64x64) via cp.async
    #pragma unroll
    for (int i = 0; i < 8; i++) {
        const int f4i = tid + i * 128;
        const int r = f4i >> 4, c4 = (f4i & 15) << 2;
        cp16(q_u32 + (r * QP_STR + c4) * 4u, Q + base + (size_t)(q0 + r) * HD + c4);
    }
    cp_commit();

    float m1 = -1e30f, m2 = -1e30f, l1 = 0.f, l2 = 0.f;
    float o[8][4] = {};
    const int row1 = rbase + g, row2 = row1 + 8;   // block-local query rows
    const int ntiles = (q0 >> 6) + 1;

    for (int jt = 0; jt < ntiles; jt++) {
        const int j0 = jt * 64;
        __syncthreads();   // prev iter done with Ks/Vs
        #pragma unroll
        for (int i = 0; i < 8; i++) {
            const int f4i = tid + i * 128;
            const int r = f4i >> 4, c4 = (f4i & 15) << 2;
            cp16(k_u32 + (r * KV_STR + c4) * 4u, K + base + (size_t)(j0 + r) * HD + c4);
            cp16(v_u32 + (r * KV_STR + c4) * 4u, V + base + (size_t)(j0 + r) * HD + c4);
        }
        cp_commit();
        cp_wait<0>();
        __syncthreads();

        // S = Q K^T  (warp: 16 rows x 64 cols)
        float s[8][4] = {};
        #pragma unroll
        for (int kb = 0; kb < 8; kb++) {
            const int k0 = kb * 8;
            uint32_t af[4];
            ldsm4(af, q_ldsm + kb * 32u);
            #pragma unroll
            for (int nt = 0; nt < 8; nt++) {
                const uint32_t b0 = fu(Ks[(nt * 8 + g) * KV_STR + k0 + tg]);
                const uint32_t b1 = fu(Ks[(nt * 8 + g) * KV_STR + k0 + tg + 4]);
                mma_tf32(s[nt], af[0], af[1], af[2], af[3], b0, b1);
            }
        }

        // online softmax
        const bool diag = (jt == ntiles - 1);
        float rm1 = -1e30f, rm2 = -1e30f;
        #pragma unroll
        for (int nt = 0; nt < 8; nt++) {
            s[nt][0] *= 0.125f; s[nt][1] *= 0.125f; s[nt][2] *= 0.125f; s[nt][3] *= 0.125f;
            if (diag) {
                const int c0 = nt * 8 + 2 * tg;
                if (c0     > row1) s[nt][0] = -1e30f;
                if (c0 + 1 > row1) s[nt][1] = -1e30f;
                if (c0     > row2) s[nt][2] = -1e30f;
                if (c0 + 1 > row2) s[nt][3] = -1e30f;
            }
            rm1 = fmaxf(rm1, fmaxf(s[nt][0], s[nt][1]));
            rm2 = fmaxf(rm2, fmaxf(s[nt][2], s[nt][3]));
        }
        rm1 = fmaxf(rm1, __shfl_xor_sync(0xffffffffu, rm1, 1));
        rm1 = fmaxf(rm1, __shfl_xor_sync(0xffffffffu, rm1, 2));
        rm2 = fmaxf(rm2, __shfl_xor_sync(0xffffffffu, rm2, 1));
        rm2 = fmaxf(rm2, __shfl_xor_sync(0xffffffffu, rm2, 2));

        const float mn1 = fmaxf(m1, rm1), mn2 = fmaxf(m2, rm2);
        const float sc1 = __expf(m1 - mn1), sc2 = __expf(m2 - mn2);
        m1 = mn1; m2 = mn2;

        float sum1 = 0.f, sum2 = 0.f;
        #pragma unroll
        for (int nt = 0; nt < 8; nt++) {
            const float p0 = __expf(s[nt][0] - mn1);
            const float p1 = __expf(s[nt][1] - mn1);
            const float p2 = __expf(s[nt][2] - mn2);
            const float p3 = __expf(s[nt][3] - mn2);
            sum1 += p0 + p1;
            sum2 += p2 + p3;
            const int cb = nt * 8 + 2 * tg;
            float2 w1; w1.x = p0; w1.y = p1;
            float2 w2; w2.x = p2; w2.y = p3;
            *reinterpret_cast<float2*>(&Ps[row1 * QP_STR + cb]) = w1;
            *reinterpret_cast<float2*>(&Ps[row2 * QP_STR + cb]) = w2;
        }
        sum1 += __shfl_xor_sync(0xffffffffu, sum1, 1);
        sum1 += __shfl_xor_sync(0xffffffffu, sum1, 2);
        sum2 += __shfl_xor_sync(0xffffffffu, sum2, 1);
        sum2 += __shfl_xor_sync(0xffffffffu, sum2, 2);
        l1 = l1 * sc1 + sum1;
        l2 = l2 * sc2 + sum2;

        #pragma unroll
        for (int nt = 0; nt < 8; nt++) {
            o[nt][0] *= sc1; o[nt][1] *= sc1;
            o[nt][2] *= sc2; o[nt][3] *= sc2;
        }
        __syncwarp();   // P writes visible within warp (each warp reads own 16 rows)

        // O += P V   (A=P 16x64, B=V 64x64)
        #pragma unroll
        for (int kb = 0; kb < 8; kb++) {
            const int k0 = kb * 8;
            uint32_t af[4];
            ldsm4(af, p_ldsm + kb * 32u);
            #pragma unroll
            for (int nt = 0; nt < 8; nt++) {
                const uint32_t b0 = fu(Vs[(k0 + tg)     * KV_STR + nt * 8 + g]);
                const uint32_t b1 = fu(Vs[(k0 + tg + 4) * KV_STR + nt * 8 + g]);
                mma_tf32(o[nt], af[0], af[1], af[2], af[3], b0, b1);
            }
        }
    }

    const float inv1 = 1.0f / l1;
    const float inv2 = 1.0f / l2;
    #pragma unroll
    for (int nt = 0; nt < 8; nt++) {
        const int cb = nt * 8 + 2 * tg;
        float2 v1; v1.x = o[nt][0] * inv1; v1.y = o[nt][1] * inv1;
        float2 v2; v2.x = o[nt][2] * inv2; v2.y = o[nt][3] * inv2;
        *reinterpret_cast<float2*>(O + base + (size_t)(q0 + row1) * HD + cb) = v1;
        *reinterpret_cast<float2*>(O + base + (size_t)(q0 + row2) * HD + cb) = v2;
    }
}

// ---------------- launch ----------------------------------------------------
extern "C" void kernel_launch(void* const* d_in, const int* in_sizes, int n_in,
                              void* d_out, int out_size) {
    const float* x     = (const float*)d_in[0];
    const float* gamma = (const float*)d_in[1];
    const float* beta  = (const float*)d_in[2];
    const float* Wq    = (const float*)d_in[3];
    const float* bq    = (const float*)d_in[4];
    const float* Wk    = (const float*)d_in[5];
    const float* bk    = (const float*)d_in[6];
    const float* Wv    = (const float*)d_in[7];
    const float* bv    = (const float*)d_in[8];
    const float* Wo    = (const float*)d_in[9];
    const float* bo    = (const float*)d_in[10];
    float* out = (float*)d_out;

    float *xn, *qp, *kp, *vp, *ao;
    cudaGetSymbolAddress((void**)&xn, g_xn);
    cudaGetSymbolAddress((void**)&qp, g_q);
    cudaGetSymbolAddress((void**)&kp, g_k);
    cudaGetSymbolAddress((void**)&vp, g_v);
    cudaGetSymbolAddress((void**)&ao, g_ao);

    ln_kernel<<<Mrows, 256>>>(x, gamma, beta, xn);

    cudaFuncSetAttribute(gemm_tf32_kernel, cudaFuncAttributeMaxDynamicSharedMemorySize,
                         GEMM_SMEM_BYTES);
    dim3 gg(HD / BN, Mrows / BM);   // (8, 64)
    gemm_tf32_kernel<<<gg, 256, GEMM_SMEM_BYTES>>>(xn, Wq, bq, nullptr, qp, Mrows, HD, Edim);
    gemm_tf32_kernel<<<gg, 256, GEMM_SMEM_BYTES>>>(xn, Wk, bk, nullptr, kp, Mrows, HD, Edim);
    gemm_tf32_kernel<<<gg, 256, GEMM_SMEM_BYTES>>>(xn, Wv, bv, nullptr, vp, Mrows, HD, Edim);

    cudaFuncSetAttribute(attn_tf32_kernel, cudaFuncAttributeMaxDynamicSharedMemorySize,
                         ATTN_SMEM_BYTES);
    attn_tf32_kernel<<<dim3(Sdim / 64, Hdim, Bdim), 128, ATTN_SMEM_BYTES>>>(qp, kp, vp, ao);

    gemm_tf32_kernel<<<dim3(Edim / BN, Mrows / BM), 256, GEMM_SMEM_BYTES>>>(ao, Wo, bo, x, out,
                                                                            Mrows, Edim, HD);
}

// round 5
// speedup vs baseline: 3.9030x; 1.0470x over previous
#include <cuda_runtime.h>
#include <math.h>
#include <stdint.h>

#define Bdim 4
#define Sdim 2048
#define Edim 1024
#define Hdim 16
#define Ddim 64
#define Mrows (Bdim * Sdim)          // 8192
#define HD (Hdim * Ddim)             // 1024

// ---------------- scratch (static device globals; no allocs) ----------------
__device__ float g_xn[Mrows * Edim];
__device__ float g_q [Mrows * HD];
__device__ float g_k [Mrows * HD];
__device__ float g_v [Mrows * HD];
__device__ float g_ao[Mrows * HD];

// ---------------- helpers ----------------------------------------------------
__device__ __forceinline__ uint32_t fu(float x) { return __float_as_uint(x); }

__device__ __forceinline__ void mma_tf32(float c[4],
                                         uint32_t a0, uint32_t a1, uint32_t a2, uint32_t a3,
                                         uint32_t b0, uint32_t b1) {
    asm volatile(
        "mma.sync.aligned.m16n8k8.row.col.f32.tf32.tf32.f32 "
        "{%0,%1,%2,%3}, {%4,%5,%6,%7}, {%8,%9}, {%0,%1,%2,%3};\n"
        : "+f"(c[0]), "+f"(c[1]), "+f"(c[2]), "+f"(c[3])
        : "r"(a0), "r"(a1), "r"(a2), "r"(a3), "r"(b0), "r"(b1));
}

__device__ __forceinline__ void ldsm4(uint32_t r[4], uint32_t addr) {
    asm volatile("ldmatrix.sync.aligned.m8n8.x4.shared.b16 {%0,%1,%2,%3}, [%4];"
                 : "=r"(r[0]), "=r"(r[1]), "=r"(r[2]), "=r"(r[3])
                 : "r"(addr));
}

__device__ __forceinline__ void cp16(uint32_t dst, const void* src) {
    asm volatile("cp.async.cg.shared.global [%0], [%1], 16;" :: "r"(dst), "l"(src));
}
__device__ __forceinline__ void cp_commit() {
    asm volatile("cp.async.commit_group;");
}
template <int N>
__device__ __forceinline__ void cp_wait() {
    asm volatile("cp.async.wait_group %0;" :: "n"(N));
}

// ---------------- LayerNorm --------------------------------------------------
__global__ void __launch_bounds__(256) ln_kernel(const float* __restrict__ x,
                                                 const float* __restrict__ gamma,
                                                 const float* __restrict__ beta,
                                                 float* __restrict__ y) {
    const int row = blockIdx.x;
    const int tid = threadIdx.x;
    const float4 xv = reinterpret_cast<const float4*>(x + (size_t)row * Edim)[tid];
    float s  = xv.x + xv.y + xv.z + xv.w;
    float ss = xv.x * xv.x + xv.y * xv.y + xv.z * xv.z + xv.w * xv.w;
    #pragma unroll
    for (int m = 16; m; m >>= 1) {
        s  += __shfl_xor_sync(0xffffffffu, s,  m);
        ss += __shfl_xor_sync(0xffffffffu, ss, m);
    }
    __shared__ float sh_s[8], sh_ss[8];
    __shared__ float s_mu, s_rstd;
    const int w = tid >> 5, l = tid & 31;
    if (l == 0) { sh_s[w] = s; sh_ss[w] = ss; }
    __syncthreads();
    if (w == 0) {
        float a = (l < 8) ? sh_s[l]  : 0.f;
        float c = (l < 8) ? sh_ss[l] : 0.f;
        #pragma unroll
        for (int m = 4; m; m >>= 1) {
            a += __shfl_xor_sync(0xffffffffu, a, m);
            c += __shfl_xor_sync(0xffffffffu, c, m);
        }
        if (l == 0) {
            float mu  = a * (1.0f / Edim);
            float var = c * (1.0f / Edim) - mu * mu;
            s_mu = mu;
            s_rstd = rsqrtf(var + 1e-5f);
        }
    }
    __syncthreads();
    const float mu = s_mu, rstd = s_rstd;
    const float4 gv = reinterpret_cast<const float4*>(gamma)[tid];
    const float4 bv = reinterpret_cast<const float4*>(beta)[tid];
    float4 yv;
    yv.x = (xv.x - mu) * rstd * gv.x + bv.x;
    yv.y = (xv.y - mu) * rstd * gv.y + bv.y;
    yv.z = (xv.z - mu) * rstd * gv.z + bv.z;
    yv.w = (xv.w - mu) * rstd * gv.w + bv.w;
    reinterpret_cast<float4*>(y + (size_t)row * Edim)[tid] = yv;
}

// ---------------- TF32 GEMM body: 4-stage cp.async pipeline -----------------
#define BM 128
#define BN 128
#define BK 16
#define ASTRIDE 20
#define BSTR 136
#define STAGES 4
#define A_STAGE_F (BM * ASTRIDE)          // 2560 floats
#define B_STAGE_F (BK * BSTR)             // 2176 floats
#define GEMM_SMEM_BYTES ((STAGES * (A_STAGE_F + B_STAGE_F)) * 4)   // 75776 B

__device__ __forceinline__ void gemm_body(const float* __restrict__ A,
                                          const float* __restrict__ W,
                                          const float* __restrict__ bias,
                                          const float* __restrict__ res,
                                          float* __restrict__ C,
                                          int M, int N, int K,
                                          int bx, int by, float* smem) {
    float* Asm = smem;
    float* Bsm = smem + STAGES * A_STAGE_F;

    const int tid  = threadIdx.x;
    const int lane = tid & 31;
    const int wid  = tid >> 5;
    const int g  = lane >> 2;
    const int tg = lane & 3;
    const int wm = wid >> 2;
    const int wn = wid & 3;
    const int row0 = by * BM;
    const int col0 = bx * BN;

    const int ar = tid >> 2;
    const int ac = (tid & 3) << 2;
    const int br = tid >> 5;
    const int bc = (tid & 31) << 2;

    const float* Ap = A + (size_t)(row0 + ar) * K + ac;
    const float* Bp = W + (size_t)br * N + col0 + bc;

    const uint32_t asm_u32 = (uint32_t)__cvta_generic_to_shared(Asm);
    const uint32_t bsm_u32 = (uint32_t)__cvta_generic_to_shared(Bsm);
    const uint32_t a_dst0 = asm_u32 + (ar * ASTRIDE + ac) * 4u;
    const uint32_t a_dst1 = asm_u32 + ((ar + 64) * ASTRIDE + ac) * 4u;
    const uint32_t b_dst0 = bsm_u32 + (br * BSTR + bc) * 4u;
    const uint32_t b_dst1 = bsm_u32 + ((br + 8) * BSTR + bc) * 4u;

    const uint32_t a_ldsm_base = asm_u32 +
        (((wm * 64 + (lane & 15)) * ASTRIDE) + ((lane >> 4) << 2)) * 4u;

    const int NIT = K / BK;

    #pragma unroll
    for (int s = 0; s < STAGES - 1; s++) {
        const uint32_t ao = s * (A_STAGE_F * 4u);
        const uint32_t bo = s * (B_STAGE_F * 4u);
        const float* Aps = Ap + s * BK;
        const float* Bps = Bp + (size_t)s * BK * N;
        cp16(a_dst0 + ao, Aps);
        cp16(a_dst1 + ao, Aps + (size_t)64 * K);
        cp16(b_dst0 + bo, Bps);
        cp16(b_dst1 + bo, Bps + (size_t)8 * N);
        cp_commit();
    }

    float acc[4][4][4] = {};

    for (int it = 0; it < NIT; it++) {
        cp_wait<STAGES - 2>();
        __syncthreads();

        if (it + STAGES - 1 < NIT) {
            const int s = (it + STAGES - 1) % STAGES;
            const uint32_t ao = s * (A_STAGE_F * 4u);
            const uint32_t bo = s * (B_STAGE_F * 4u);
            const float* Aps = Ap + (it + STAGES - 1) * BK;
            const float* Bps = Bp + (size_t)(it + STAGES - 1) * BK * N;
            cp16(a_dst0 + ao, Aps);
            cp16(a_dst1 + ao, Aps + (size_t)64 * K);
            cp16(b_dst0 + bo, Bps);
            cp16(b_dst1 + bo, Bps + (size_t)8 * N);
        }
        cp_commit();

        const int cur = it % STAGES;
        const float* Bsc = Bsm + cur * B_STAGE_F;
        const uint32_t a_base = a_ldsm_base + cur * (A_STAGE_F * 4u);
        #pragma unroll
        for (int kb = 0; kb < 2; kb++) {
            const int k0 = kb * 8;
            uint32_t af[4][4];
            #pragma unroll
            for (int mi = 0; mi < 4; mi++)
                ldsm4(af[mi], a_base + (mi * 16 * ASTRIDE + k0) * 4u);
            uint32_t bf[4][2];
            #pragma unroll
            for (int ni = 0; ni < 4; ni++) {
                const int cb = wn * 32 + ni * 8 + g;
                bf[ni][0] = fu(Bsc[(k0 + tg)     * BSTR + cb]);
                bf[ni][1] = fu(Bsc[(k0 + tg + 4) * BSTR + cb]);
            }
            #pragma unroll
            for (int mi = 0; mi < 4; mi++)
                #pragma unroll
                for (int ni = 0; ni < 4; ni++)
                    mma_tf32(acc[mi][ni], af[mi][0], af[mi][1], af[mi][2], af[mi][3],
                             bf[ni][0], bf[ni][1]);
        }
    }

    #pragma unroll
    for (int mi = 0; mi < 4; mi++) {
        const int r1 = row0 + wm * 64 + mi * 16 + g;
        const int r2 = r1 + 8;
        #pragma unroll
        for (int ni = 0; ni < 4; ni++) {
            const int cb = col0 + wn * 32 + ni * 8 + 2 * tg;
            float2 v1, v2;
            v1.x = acc[mi][ni][0] + bias[cb];
            v1.y = acc[mi][ni][1] + bias[cb + 1];
            v2.x = acc[mi][ni][2] + bias[cb];
            v2.y = acc[mi][ni][3] + bias[cb + 1];
            if (res) {
                const float2 r1v = *reinterpret_cast<const float2*>(res + (size_t)r1 * N + cb);
                const float2 r2v = *reinterpret_cast<const float2*>(res + (size_t)r2 * N + cb);
                v1.x += r1v.x; v1.y += r1v.y;
                v2.x += r2v.x; v2.y += r2v.y;
            }
            *reinterpret_cast<float2*>(C + (size_t)r1 * N + cb) = v1;
            *reinterpret_cast<float2*>(C + (size_t)r2 * N + cb) = v2;
        }
    }
}

// fused QKV: grid (24, 64); blockIdx.x selects matrix (x>>3) and col tile (x&7)
__global__ void __launch_bounds__(256, 2) qkv_gemm_kernel(const float* __restrict__ A,
                                                          const float* __restrict__ Wq,
                                                          const float* __restrict__ bq,
                                                          const float* __restrict__ Wk,
                                                          const float* __restrict__ bk,
                                                          const float* __restrict__ Wv,
                                                          const float* __restrict__ bv,
                                                          float* __restrict__ Cq,
                                                          float* __restrict__ Ck,
                                                          float* __restrict__ Cv) {
    extern __shared__ __align__(16) float smem[];
    const int mat = blockIdx.x >> 3;
    const int bx  = blockIdx.x & 7;
    const float* W   = (mat == 0) ? Wq : (mat == 1) ? Wk : Wv;
    const float* bia = (mat == 0) ? bq : (mat == 1) ? bk : bv;
    float* C         = (mat == 0) ? Cq : (mat == 1) ? Ck : Cv;
    gemm_body(A, W, bia, nullptr, C, Mrows, HD, Edim, bx, blockIdx.y, smem);
}

__global__ void __launch_bounds__(256, 2) gemm_tf32_kernel(const float* __restrict__ A,
                                                           const float* __restrict__ W,
                                                           const float* __restrict__ bias,
                                                           const float* __restrict__ res,
                                                           float* __restrict__ C,
                                                           int M, int N, int K) {
    extern __shared__ __align__(16) float smem[];
    gemm_body(A, W, bias, res, C, M, N, K, blockIdx.x, blockIdx.y, smem);
}

// ---------------- Flash attention: tf32 mma + LDSM + double-buffered KV -----
// grid (S/64, H, B), 128 threads (4 warps). Warp w owns query rows [16w,16w+16).
#define QP_STR 76
#define KV_STR 72
#define KV_BUF_F (2 * 64 * KV_STR)                       // K+V one buffer: 9216 floats
#define ATTN_SMEM_FLOATS (2 * 64 * QP_STR + 2 * KV_BUF_F)  // 28160 floats
#define ATTN_SMEM_BYTES (ATTN_SMEM_FLOATS * 4)           // 112640 B

__global__ void __launch_bounds__(128) attn_tf32_kernel(const float* __restrict__ Q,
                                                        const float* __restrict__ K,
                                                        const float* __restrict__ V,
                                                        float* __restrict__ O) {
    extern __shared__ __align__(16) float sm[];
    float* Qs  = sm;
    float* Ps  = Qs + 64 * QP_STR;
    float* KV0 = Ps + 64 * QP_STR;     // [K(64x72) | V(64x72)] x2 buffers

    const int tid  = threadIdx.x;
    const int lane = tid & 31;
    const int wid  = tid >> 5;
    const int g  = lane >> 2;
    const int tg = lane & 3;
    const int rbase = wid * 16;
    const int q0 = blockIdx.x * 64;
    const int h = blockIdx.y, b = blockIdx.z;
    const size_t base = (size_t)b * Sdim * HD + (size_t)h * Ddim;

    const uint32_t q_u32  = (uint32_t)__cvta_generic_to_shared(Qs);
    const uint32_t p_u32  = (uint32_t)__cvta_generic_to_shared(Ps);
    const uint32_t kv_u32 = (uint32_t)__cvta_generic_to_shared(KV0);
    const uint32_t q_ldsm = q_u32 + (((rbase + (lane & 15)) * QP_STR) + ((lane >> 4) << 2)) * 4u;
    const uint32_t p_ldsm = p_u32 + (((rbase + (lane & 15)) * QP_STR) + ((lane >> 4) << 2)) * 4u;

    const int ntiles = (q0 >> 6) + 1;

    // prologue: G0 = Q + KV tile 0
    #pragma unroll
    for (int i = 0; i < 8; i++) {
        const int f4i = tid + i * 128;
        const int r = f4i >> 4, c4 = (f4i & 15) << 2;
        cp16(q_u32 + (r * QP_STR + c4) * 4u, Q + base + (size_t)(q0 + r) * HD + c4);
        cp16(kv_u32 + (r * KV_STR + c4) * 4u,               K + base + (size_t)r * HD + c4);
        cp16(kv_u32 + ((64 + r) * KV_STR + c4) * 4u,        V + base + (size_t)r * HD + c4);
    }
    cp_commit();
    // G1 = KV tile 1 (or empty)
    if (ntiles > 1) {
        const uint32_t kvb = kv_u32 + KV_BUF_F * 4u;
        #pragma unroll
        for (int i = 0; i < 8; i++) {
            const int f4i = tid + i * 128;
            const int r = f4i >> 4, c4 = (f4i & 15) << 2;
            cp16(kvb + (r * KV_STR + c4) * 4u,        K + base + (size_t)(64 + r) * HD + c4);
            cp16(kvb + ((64 + r) * KV_STR + c4) * 4u, V + base + (size_t)(64 + r) * HD + c4);
        }
    }
    cp_commit();

    float m1 = -1e30f, m2 = -1e30f, l1 = 0.f, l2 = 0.f;
    float o[8][4] = {};
    const int row1 = rbase + g, row2 = row1 + 8;

    for (int jt = 0; jt < ntiles; jt++) {
        cp_wait<1>();          // all but most-recent group complete => KV_jt (and Q) ready
        __syncthreads();

        const float* Ks = KV0 + (jt & 1) * KV_BUF_F;
        const float* Vs = Ks + 64 * KV_STR;

        // S = Q K^T
        float s[8][4] = {};
        #pragma unroll
        for (int kb = 0; kb < 8; kb++) {
            const int k0 = kb * 8;
            uint32_t af[4];
            ldsm4(af, q_ldsm + kb * 32u);
            #pragma unroll
            for (int nt = 0; nt < 8; nt++) {
                const uint32_t b0 = fu(Ks[(nt * 8 + g) * KV_STR + k0 + tg]);
                const uint32_t b1 = fu(Ks[(nt * 8 + g) * KV_STR + k0 + tg + 4]);
                mma_tf32(s[nt], af[0], af[1], af[2], af[3], b0, b1);
            }
        }

        // online softmax
        const bool diag = (jt == ntiles - 1);
        float rm1 = -1e30f, rm2 = -1e30f;
        #pragma unroll
        for (int nt = 0; nt < 8; nt++) {
            s[nt][0] *= 0.125f; s[nt][1] *= 0.125f; s[nt][2] *= 0.125f; s[nt][3] *= 0.125f;
            if (diag) {
                const int c0 = nt * 8 + 2 * tg;
                if (c0     > row1) s[nt][0] = -1e30f;
                if (c0 + 1 > row1) s[nt][1] = -1e30f;
                if (c0     > row2) s[nt][2] = -1e30f;
                if (c0 + 1 > row2) s[nt][3] = -1e30f;
            }
            rm1 = fmaxf(rm1, fmaxf(s[nt][0], s[nt][1]));
            rm2 = fmaxf(rm2, fmaxf(s[nt][2], s[nt][3]));
        }
        rm1 = fmaxf(rm1, __shfl_xor_sync(0xffffffffu, rm1, 1));
        rm1 = fmaxf(rm1, __shfl_xor_sync(0xffffffffu, rm1, 2));
        rm2 = fmaxf(rm2, __shfl_xor_sync(0xffffffffu, rm2, 1));
        rm2 = fmaxf(rm2, __shfl_xor_sync(0xffffffffu, rm2, 2));

        const float mn1 = fmaxf(m1, rm1), mn2 = fmaxf(m2, rm2);
        const float sc1 = __expf(m1 - mn1), sc2 = __expf(m2 - mn2);
        m1 = mn1; m2 = mn2;

        float sum1 = 0.f, sum2 = 0.f;
        #pragma unroll
        for (int nt = 0; nt < 8; nt++) {
            const float p0 = __expf(s[nt][0] - mn1);
            const float p1 = __expf(s[nt][1] - mn1);
            const float p2 = __expf(s[nt][2] - mn2);
            const float p3 = __expf(s[nt][3] - mn2);
            sum1 += p0 + p1;
            sum2 += p2 + p3;
            const int cb = nt * 8 + 2 * tg;
            float2 w1; w1.x = p0; w1.y = p1;
            float2 w2; w2.x = p2; w2.y = p3;
            *reinterpret_cast<float2*>(&Ps[row1 * QP_STR + cb]) = w1;
            *reinterpret_cast<float2*>(&Ps[row2 * QP_STR + cb]) = w2;
        }
        sum1 += __shfl_xor_sync(0xffffffffu, sum1, 1);
        sum1 += __shfl_xor_sync(0xffffffffu, sum1, 2);
        sum2 += __shfl_xor_sync(0xffffffffu, sum2, 1);
        sum2 += __shfl_xor_sync(0xffffffffu, sum2, 2);
        l1 = l1 * sc1 + sum1;
        l2 = l2 * sc2 + sum2;

        #pragma unroll
        for (int nt = 0; nt < 8; nt++) {
            o[nt][0] *= sc1; o[nt][1] *= sc1;
            o[nt][2] *= sc2; o[nt][3] *= sc2;
        }
        __syncwarp();

        // O += P V
        #pragma unroll
        for (int kb = 0; kb < 8; kb++) {
            const int k0 = kb * 8;
            uint32_t af[4];
            ldsm4(af, p_ldsm + kb * 32u);
            #pragma unroll
            for (int nt = 0; nt < 8; nt++) {
                const uint32_t b0 = fu(Vs[(k0 + tg)     * KV_STR + nt * 8 + g]);
                const uint32_t b1 = fu(Vs[(k0 + tg + 4) * KV_STR + nt * 8 + g]);
                mma_tf32(o[nt], af[0], af[1], af[2], af[3], b0, b1);
            }
        }

        // refill buffer (jt&1) with KV tile jt+2 (buffer now fully consumed)
        __syncthreads();
        if (jt + 2 < ntiles) {
            const int j2 = (jt + 2) * 64;
            const uint32_t kvb = kv_u32 + (jt & 1) * (KV_BUF_F * 4u);
            #pragma unroll
            for (int i = 0; i < 8; i++) {
                const int f4i = tid + i * 128;
                const int r = f4i >> 4, c4 = (f4i & 15) << 2;
                cp16(kvb + (r * KV_STR + c4) * 4u,        K + base + (size_t)(j2 + r) * HD + c4);
                cp16(kvb + ((64 + r) * KV_STR + c4) * 4u, V + base + (size_t)(j2 + r) * HD + c4);
            }
        }
        cp_commit();
    }

    const float inv1 = 1.0f / l1;
    const float inv2 = 1.0f / l2;
    #pragma unroll
    for (int nt = 0; nt < 8; nt++) {
        const int cb = nt * 8 + 2 * tg;
        float2 v1; v1.x = o[nt][0] * inv1; v1.y = o[nt][1] * inv1;
        float2 v2; v2.x = o[nt][2] * inv2; v2.y = o[nt][3] * inv2;
        *reinterpret_cast<float2*>(O + base + (size_t)(q0 + row1) * HD + cb) = v1;
        *reinterpret_cast<float2*>(O + base + (size_t)(q0 + row2) * HD + cb) = v2;
    }
}

// ---------------- launch ----------------------------------------------------
extern "C" void kernel_launch(void* const* d_in, const int* in_sizes, int n_in,
                              void* d_out, int out_size) {
    const float* x     = (const float*)d_in[0];
    const float* gamma = (const float*)d_in[1];
    const float* beta  = (const float*)d_in[2];
    const float* Wq    = (const float*)d_in[3];
    const float* bq    = (const float*)d_in[4];
    const float* Wk    = (const float*)d_in[5];
    const float* bk    = (const float*)d_in[6];
    const float* Wv    = (const float*)d_in[7];
    const float* bv    = (const float*)d_in[8];
    const float* Wo    = (const float*)d_in[9];
    const float* bo    = (const float*)d_in[10];
    float* out = (float*)d_out;

    float *xn, *qp, *kp, *vp, *ao;
    cudaGetSymbolAddress((void**)&xn, g_xn);
    cudaGetSymbolAddress((void**)&qp, g_q);
    cudaGetSymbolAddress((void**)&kp, g_k);
    cudaGetSymbolAddress((void**)&vp, g_v);
    cudaGetSymbolAddress((void**)&ao, g_ao);

    ln_kernel<<<Mrows, 256>>>(x, gamma, beta, xn);

    cudaFuncSetAttribute(qkv_gemm_kernel, cudaFuncAttributeMaxDynamicSharedMemorySize,
                         GEMM_SMEM_BYTES);
    cudaFuncSetAttribute(gemm_tf32_kernel, cudaFuncAttributeMaxDynamicSharedMemorySize,
                         GEMM_SMEM_BYTES);

    qkv_gemm_kernel<<<dim3(24, Mrows / BM), 256, GEMM_SMEM_BYTES>>>(
        xn, Wq, bq, Wk, bk, Wv, bv, qp, kp, vp);

    cudaFuncSetAttribute(attn_tf32_kernel, cudaFuncAttributeMaxDynamicSharedMemorySize,
                         ATTN_SMEM_BYTES);
    attn_tf32_kernel<<<dim3(Sdim / 64, Hdim, Bdim), 128, ATTN_SMEM_BYTES>>>(qp, kp, vp, ao);

    gemm_tf32_kernel<<<dim3(Edim / BN, Mrows / BM), 256, GEMM_SMEM_BYTES>>>(ao, Wo, bo, x, out,
                                                                            Mrows, Edim, HD);
}

// round 7
// speedup vs baseline: 7.4188x; 1.9008x over previous
#include <cuda_runtime.h>
#include <cuda_bf16.h>
#include <math.h>
#include <stdint.h>

#define Bdim 4
#define Sdim 2048
#define Edim 1024
#define Hdim 16
#define Ddim 64
#define Mrows (Bdim * Sdim)          // 8192
#define HD (Hdim * Ddim)             // 1024
#define GK 1024

// ---------------- scratch (static device globals; no allocs) ----------------
__device__ __nv_bfloat16 g_xn[Mrows * Edim];
__device__ __nv_bfloat16 g_q [Mrows * HD];
__device__ __nv_bfloat16 g_k [Mrows * HD];
__device__ __nv_bfloat16 g_v [Mrows * HD];
__device__ __nv_bfloat16 g_ao[Mrows * HD];
__device__ __nv_bfloat16 g_wt[4 * GK * GK];   // transposed weights [N][K] bf16

// ---------------- helpers ----------------------------------------------------
__device__ __forceinline__ uint32_t packbf(float lo, float hi) {
    uint32_t d;
    asm("cvt.rn.bf16x2.f32 %0, %1, %2;" : "=r"(d) : "f"(hi), "f"(lo));
    return d;
}

// D(16x8) += A(16x16,row) * B(16x8,col)  bf16 -> fp32
__device__ __forceinline__ void mma_bf16(float c[4],
                                         uint32_t a0, uint32_t a1, uint32_t a2, uint32_t a3,
                                         uint32_t b0, uint32_t b1) {
    asm volatile(
        "mma.sync.aligned.m16n8k16.row.col.f32.bf16.bf16.f32 "
        "{%0,%1,%2,%3}, {%4,%5,%6,%7}, {%8,%9}, {%0,%1,%2,%3};\n"
        : "+f"(c[0]), "+f"(c[1]), "+f"(c[2]), "+f"(c[3])
        : "r"(a0), "r"(a1), "r"(a2), "r"(a3), "r"(b0), "r"(b1));
}

__device__ __forceinline__ void ldsm4(uint32_t r[4], uint32_t addr) {
    asm volatile("ldmatrix.sync.aligned.m8n8.x4.shared.b16 {%0,%1,%2,%3}, [%4];"
                 : "=r"(r[0]), "=r"(r[1]), "=r"(r[2]), "=r"(r[3])
                 : "r"(addr));
}
__device__ __forceinline__ void ldsm4t(uint32_t r[4], uint32_t addr) {
    asm volatile("ldmatrix.sync.aligned.m8n8.x4.trans.shared.b16 {%0,%1,%2,%3}, [%4];"
                 : "=r"(r[0]), "=r"(r[1]), "=r"(r[2]), "=r"(r[3])
                 : "r"(addr));
}

__device__ __forceinline__ void cp16(uint32_t dst, const void* src) {
    asm volatile("cp.async.cg.shared.global [%0], [%1], 16;" :: "r"(dst), "l"(src));
}
__device__ __forceinline__ void cp_commit() {
    asm volatile("cp.async.commit_group;");
}
template <int N>
__device__ __forceinline__ void cp_wait() {
    asm volatile("cp.async.wait_group %0;" :: "n"(N));
}

// ---------------- LayerNorm (fp32 in -> bf16 out) ----------------------------
__global__ void __launch_bounds__(256) ln_kernel(const float* __restrict__ x,
                                                 const float* __restrict__ gamma,
                                                 const float* __restrict__ beta,
                                                 __nv_bfloat16* __restrict__ y) {
    const int row = blockIdx.x;
    const int tid = threadIdx.x;
    const float4 xv = reinterpret_cast<const float4*>(x + (size_t)row * Edim)[tid];
    float s  = xv.x + xv.y + xv.z + xv.w;
    float ss = xv.x * xv.x + xv.y * xv.y + xv.z * xv.z + xv.w * xv.w;
    #pragma unroll
    for (int m = 16; m; m >>= 1) {
        s  += __shfl_xor_sync(0xffffffffu, s,  m);
        ss += __shfl_xor_sync(0xffffffffu, ss, m);
    }
    __shared__ float sh_s[8], sh_ss[8];
    __shared__ float s_mu, s_rstd;
    const int w = tid >> 5, l = tid & 31;
    if (l == 0) { sh_s[w] = s; sh_ss[w] = ss; }
    __syncthreads();
    if (w == 0) {
        float a = (l < 8) ? sh_s[l]  : 0.f;
        float c = (l < 8) ? sh_ss[l] : 0.f;
        #pragma unroll
        for (int m = 4; m; m >>= 1) {
            a += __shfl_xor_sync(0xffffffffu, a, m);
            c += __shfl_xor_sync(0xffffffffu, c, m);
        }
        if (l == 0) {
            float mu  = a * (1.0f / Edim);
            float var = c * (1.0f / Edim) - mu * mu;
            s_mu = mu;
            s_rstd = rsqrtf(var + 1e-5f);
        }
    }
    __syncthreads();
    const float mu = s_mu, rstd = s_rstd;
    const float4 gv = reinterpret_cast<const float4*>(gamma)[tid];
    const float4 bv = reinterpret_cast<const float4*>(beta)[tid];
    uint2 o2;
    o2.x = packbf((xv.x - mu) * rstd * gv.x + bv.x, (xv.y - mu) * rstd * gv.y + bv.y);
    o2.y = packbf((xv.z - mu) * rstd * gv.z + bv.z, (xv.w - mu) * rstd * gv.w + bv.w);
    *reinterpret_cast<uint2*>(y + (size_t)row * Edim + tid * 4) = o2;
}

// ---------------- weight transpose: W[K,N] fp32 -> WT[N,K] bf16 --------------
__global__ void __launch_bounds__(256) transpose_kernel(const float* __restrict__ Wq,
                                                        const float* __restrict__ Wk,
                                                        const float* __restrict__ Wv,
                                                        const float* __restrict__ Wo,
                                                        __nv_bfloat16* __restrict__ wt) {
    __shared__ float t[32][33];
    const int z = blockIdx.z;
    const float* W = (z == 0) ? Wq : (z == 1) ? Wk : (z == 2) ? Wv : Wo;
    __nv_bfloat16* T = wt + (size_t)z * GK * GK;
    const int x0 = blockIdx.x * 32, y0 = blockIdx.y * 32;
    const int tx = threadIdx.x & 31, ty = threadIdx.x >> 5;   // 32x8
    #pragma unroll
    for (int i = 0; i < 32; i += 8)
        t[ty + i][tx] = W[(size_t)(y0 + ty + i) * GK + x0 + tx];
    __syncthreads();
    #pragma unroll
    for (int i = 0; i < 32; i += 8)
        T[(size_t)(x0 + ty + i) * GK + y0 + tx] = __float2bfloat16(t[tx][ty + i]);
}

// ---------------- bf16 GEMM: 128x128 tile, BK=32, 3-stage cp.async ----------
// A [M,K] bf16 row-major; WT [N,K] bf16 row-major (= B col-major). 256 thr.
// smem rows: 64B data + 16B pad = 80B stride (LDSM conflict-free).
#define BK 32
#define ROWB 80u
#define STG_A 0u
#define STG_B 10240u                     // 128 rows * 80B
#define STAGE_BYTES 20480u
#define GSTAGES 3
#define GEMM_SMEM_BYTES (GSTAGES * STAGE_BYTES)

template <bool BF16OUT>
__device__ __forceinline__ void gemm_body(const __nv_bfloat16* __restrict__ A,
                                          const __nv_bfloat16* __restrict__ WT,
                                          const float* __restrict__ bias,
                                          const float* __restrict__ res,
                                          void* __restrict__ C,
                                          int bx, int by) {
    extern __shared__ __align__(16) char smem[];
    const uint32_t s0 = (uint32_t)__cvta_generic_to_shared(smem);

    const int tid  = threadIdx.x;
    const int lane = tid & 31;
    const int wid  = tid >> 5;
    const int g  = lane >> 2;
    const int tg = lane & 3;
    const int wm = wid >> 2;      // 0..1
    const int wn = wid & 3;       // 0..3
    const int row0 = by * 128;
    const int col0 = bx * 128;
    const int N = 1024;

    // LDSM lane bases (byte offsets within a stage)
    const uint32_t a_off = STG_A + (uint32_t)(wm * 64 + (lane & 15)) * ROWB
                                 + (uint32_t)((lane >> 4) << 4);
    const uint32_t b_off = STG_B + (uint32_t)(wn * 32 + (lane & 7) + ((lane >> 4) << 3)) * ROWB
                                 + (uint32_t)(((lane >> 3) & 1) << 4);

    auto issue_tile = [&](int t) {
        const uint32_t sb = s0 + (uint32_t)(t % GSTAGES) * STAGE_BYTES;
        const int gk = t * BK;
        #pragma unroll
        for (int i = 0; i < 4; i++) {
            const int idx = tid + i * 256;
            const int r = (idx & 511) >> 2;
            const int j = idx & 3;
            if (idx < 512)
                cp16(sb + STG_A + r * ROWB + j * 16u,
                     A + (size_t)(row0 + r) * GK + gk + j * 8);
            else
                cp16(sb + STG_B + r * ROWB + j * 16u,
                     WT + (size_t)(col0 + r) * GK + gk + j * 8);
        }
        cp_commit();
    };

    issue_tile(0);
    issue_tile(1);

    float acc[4][4][4] = {};
    const int NIT = GK / BK;     // 32

    for (int it = 0; it < NIT; it++) {
        cp_wait<GSTAGES - 2>();
        __syncthreads();

        if (it + GSTAGES - 1 < NIT) issue_tile(it + GSTAGES - 1);
        else cp_commit();

        const uint32_t sb = s0 + (uint32_t)(it % GSTAGES) * STAGE_BYTES;
        #pragma unroll
        for (int kb = 0; kb < 2; kb++) {
            uint32_t af[4][4], bf[2][4];
            #pragma unroll
            for (int mi = 0; mi < 4; mi++)
                ldsm4(af[mi], sb + a_off + (uint32_t)(mi * 16) * ROWB + kb * 32u);
            #pragma unroll
            for (int nb = 0; nb < 2; nb++)
                ldsm4(bf[nb], sb + b_off + (uint32_t)(nb * 16) * ROWB + kb * 32u);
            #pragma unroll
            for (int mi = 0; mi < 4; mi++)
                #pragma unroll
                for (int nb = 0; nb < 2; nb++) {
                    mma_bf16(acc[mi][nb * 2],     af[mi][0], af[mi][1], af[mi][2], af[mi][3],
                             bf[nb][0], bf[nb][1]);
                    mma_bf16(acc[mi][nb * 2 + 1], af[mi][0], af[mi][1], af[mi][2], af[mi][3],
                             bf[nb][2], bf[nb][3]);
                }
        }
        __syncthreads();
    }

    #pragma unroll
    for (int mi = 0; mi < 4; mi++) {
        const int r1 = row0 + wm * 64 + mi * 16 + g;
        const int r2 = r1 + 8;
        #pragma unroll
        for (int ni = 0; ni < 4; ni++) {
            const int cb = col0 + wn * 32 + ni * 8 + 2 * tg;
            float v0 = acc[mi][ni][0] + bias[cb];
            float v1 = acc[mi][ni][1] + bias[cb + 1];
            float v2 = acc[mi][ni][2] + bias[cb];
            float v3 = acc[mi][ni][3] + bias[cb + 1];
            if (BF16OUT) {
                ((uint32_t*)C)[(size_t)r1 * (N / 2) + (cb >> 1)] = packbf(v0, v1);
                ((uint32_t*)C)[(size_t)r2 * (N / 2) + (cb >> 1)] = packbf(v2, v3);
            } else {
                const float2 r1v = *reinterpret_cast<const float2*>(res + (size_t)r1 * N + cb);
                const float2 r2v = *reinterpret_cast<const float2*>(res + (size_t)r2 * N + cb);
                float2 w1; w1.x = v0 + r1v.x; w1.y = v1 + r1v.y;
                float2 w2; w2.x = v2 + r2v.x; w2.y = v3 + r2v.y;
                *reinterpret_cast<float2*>((float*)C + (size_t)r1 * N + cb) = w1;
                *reinterpret_cast<float2*>((float*)C + (size_t)r2 * N + cb) = w2;
            }
        }
    }
}

// fused QKV: grid (24, 64); blockIdx.x: matrix (x>>3), col tile (x&7)
__global__ void __launch_bounds__(256, 2) qkv_gemm_kernel(const __nv_bfloat16* __restrict__ A,
                                                          const __nv_bfloat16* __restrict__ wt,
                                                          const float* __restrict__ bq,
                                                          const float* __restrict__ bk,
                                                          const float* __restrict__ bv,
                                                          __nv_bfloat16* __restrict__ Cq,
                                                          __nv_bfloat16* __restrict__ Ck,
                                                          __nv_bfloat16* __restrict__ Cv) {
    const int mat = blockIdx.x >> 3;
    const int bx  = blockIdx.x & 7;
    const __nv_bfloat16* WT = wt + (size_t)mat * GK * GK;
    const float* bias = (mat == 0) ? bq : (mat == 1) ? bk : bv;
    __nv_bfloat16* C  = (mat == 0) ? Cq : (mat == 1) ? Ck : Cv;
    gemm_body<true>(A, WT, bias, nullptr, C, bx, blockIdx.y);
}

__global__ void __launch_bounds__(256, 2) o_gemm_kernel(const __nv_bfloat16* __restrict__ A,
                                                        const __nv_bfloat16* __restrict__ wt,
                                                        const float* __restrict__ bo,
                                                        const float* __restrict__ res,
                                                        float* __restrict__ out) {
    gemm_body<false>(A, wt + (size_t)3 * GK * GK, bo, res, out, blockIdx.x, blockIdx.y);
}

// ---------------- Flash attention (causal), bf16 mma ------------------------
// grid (S/64, H, B), 128 threads (4 warps). Warp w owns query rows [16w,16w+16).
// All tiles 64 rows x 128B data, stride 144B.
#define TROW 144u
#define TILE_B (64u * TROW)              // 9216 B
#define KVBUF (2u * TILE_B)              // K+V per buffer
#define ATTN_SMEM_BYTES (2 * TILE_B + 2 * KVBUF)   // Q,P + 2 KV buffers = 55296

__global__ void __launch_bounds__(128) attn_bf16_kernel(const __nv_bfloat16* __restrict__ Q,
                                                        const __nv_bfloat16* __restrict__ K,
                                                        const __nv_bfloat16* __restrict__ V,
                                                        __nv_bfloat16* __restrict__ O) {
    extern __shared__ __align__(16) char sm[];
    const uint32_t q_u32  = (uint32_t)__cvta_generic_to_shared(sm);
    const uint32_t p_u32  = q_u32 + TILE_B;
    const uint32_t kv_u32 = p_u32 + TILE_B;
    char* Ps = sm + TILE_B;

    const int tid  = threadIdx.x;
    const int lane = tid & 31;
    const int wid  = tid >> 5;
    const int g  = lane >> 2;
    const int tg = lane & 3;
    const int rbase = wid * 16;
    const int q0 = blockIdx.x * 64;
    const int h = blockIdx.y, b = blockIdx.z;
    const size_t base = (size_t)b * Sdim * HD + (size_t)h * Ddim;

    // LDSM lane bases
    const uint32_t qp_loff = (uint32_t)(rbase + (lane & 15)) * TROW + (uint32_t)((lane >> 4) << 4);
    const uint32_t b_loff  = (uint32_t)((lane & 7) + ((lane >> 4) << 3)) * TROW
                           + (uint32_t)(((lane >> 3) & 1) << 4);
    const uint32_t v_loff  = (uint32_t)((lane & 7) + (((lane >> 3) & 1) << 3)) * TROW
                           + (uint32_t)((lane >> 4) << 4);

    const int ntiles = (q0 >> 6) + 1;

    // prologue: G0 = Q + KV tile 0, G1 = KV tile 1
    #pragma unroll
    for (int i = 0; i < 4; i++) {
        const int idx = tid + i * 128;
        const int r = idx >> 3, j = idx & 7;
        cp16(q_u32 + r * TROW + j * 16u, Q + base + (size_t)(q0 + r) * HD + j * 8);
        cp16(kv_u32 + r * TROW + j * 16u,          K + base + (size_t)r * HD + j * 8);
        cp16(kv_u32 + TILE_B + r * TROW + j * 16u, V + base + (size_t)r * HD + j * 8);
    }
    cp_commit();
    if (ntiles > 1) {
        const uint32_t kvb = kv_u32 + KVBUF;
        #pragma unroll
        for (int i = 0; i < 4; i++) {
            const int idx = tid + i * 128;
            const int r = idx >> 3, j = idx & 7;
            cp16(kvb + r * TROW + j * 16u,          K + base + (size_t)(64 + r) * HD + j * 8);
            cp16(kvb + TILE_B + r * TROW + j * 16u, V + base + (size_t)(64 + r) * HD + j * 8);
        }
    }
    cp_commit();

    float m1 = -1e30f, m2 = -1e30f, l1 = 0.f, l2 = 0.f;
    float o[8][4] = {};
    const int row1 = rbase + g, row2 = row1 + 8;

    for (int jt = 0; jt < ntiles; jt++) {
        cp_wait<1>();
        __syncthreads();

        const uint32_t kb32 = kv_u32 + (uint32_t)(jt & 1) * KVBUF;   // K tile
        const uint32_t vb32 = kb32 + TILE_B;                         // V tile

        // S = Q K^T : per kb (k16): 1 Q-ldsm4 + 4 K-ldsm4, 8 mma
        float s[8][4] = {};
        #pragma unroll
        for (int kb = 0; kb < 4; kb++) {
            uint32_t af[4];
            ldsm4(af, q_u32 + qp_loff + kb * 32u);
            #pragma unroll
            for (int nb = 0; nb < 4; nb++) {
                uint32_t bf[4];
                ldsm4(bf, kb32 + b_loff + (uint32_t)(nb * 16) * TROW + kb * 32u);
                mma_bf16(s[nb * 2],     af[0], af[1], af[2], af[3], bf[0], bf[1]);
                mma_bf16(s[nb * 2 + 1], af[0], af[1], af[2], af[3], bf[2], bf[3]);
            }
        }

        // online softmax (fp32)
        const bool diag = (jt == ntiles - 1);
        float rm1 = -1e30f, rm2 = -1e30f;
        #pragma unroll
        for (int nt = 0; nt < 8; nt++) {
            s[nt][0] *= 0.125f; s[nt][1] *= 0.125f; s[nt][2] *= 0.125f; s[nt][3] *= 0.125f;
            if (diag) {
                const int c0 = nt * 8 + 2 * tg;
                if (c0     > row1) s[nt][0] = -1e30f;
                if (c0 + 1 > row1) s[nt][1] = -1e30f;
                if (c0     > row2) s[nt][2] = -1e30f;
                if (c0 + 1 > row2) s[nt][3] = -1e30f;
            }
            rm1 = fmaxf(rm1, fmaxf(s[nt][0], s[nt][1]));
            rm2 = fmaxf(rm2, fmaxf(s[nt][2], s[nt][3]));
        }
        rm1 = fmaxf(rm1, __shfl_xor_sync(0xffffffffu, rm1, 1));
        rm1 = fmaxf(rm1, __shfl_xor_sync(0xffffffffu, rm1, 2));
        rm2 = fmaxf(rm2, __shfl_xor_sync(0xffffffffu, rm2, 1));
        rm2 = fmaxf(rm2, __shfl_xor_sync(0xffffffffu, rm2, 2));

        const float mn1 = fmaxf(m1, rm1), mn2 = fmaxf(m2, rm2);
        const float sc1 = __expf(m1 - mn1), sc2 = __expf(m2 - mn2);
        m1 = mn1; m2 = mn2;

        float sum1 = 0.f, sum2 = 0.f;
        #pragma unroll
        for (int nt = 0; nt < 8; nt++) {
            const float p0 = __expf(s[nt][0] - mn1);
            const float p1 = __expf(s[nt][1] - mn1);
            const float p2 = __expf(s[nt][2] - mn2);
            const float p3 = __expf(s[nt][3] - mn2);
            sum1 += p0 + p1;
            sum2 += p2 + p3;
            const int cb = nt * 8 + 2 * tg;
            *reinterpret_cast<uint32_t*>(Ps + row1 * TROW + cb * 2) = packbf(p0, p1);
            *reinterpret_cast<uint32_t*>(Ps + row2 * TROW + cb * 2) = packbf(p2, p3);
        }
        sum1 += __shfl_xor_sync(0xffffffffu, sum1, 1);
        sum1 += __shfl_xor_sync(0xffffffffu, sum1, 2);
        sum2 += __shfl_xor_sync(0xffffffffu, sum2, 1);
        sum2 += __shfl_xor_sync(0xffffffffu, sum2, 2);
        l1 = l1 * sc1 + sum1;
        l2 = l2 * sc2 + sum2;

        #pragma unroll
        for (int nt = 0; nt < 8; nt++) {
            o[nt][0] *= sc1; o[nt][1] *= sc1;
            o[nt][2] *= sc2; o[nt][3] *= sc2;
        }
        __syncwarp();   // P writes visible within warp (warp reads its own 16 rows)

        // O += P V : per kb (j16): 1 P-ldsm4 + 4 V-ldsm4(trans), 8 mma
        #pragma unroll
        for (int kb = 0; kb < 4; kb++) {
            uint32_t af[4];
            ldsm4(af, p_u32 + qp_loff + kb * 32u);
            #pragma unroll
            for (int nb = 0; nb < 4; nb++) {
                uint32_t bf[4];
                ldsm4t(bf, vb32 + v_loff + (uint32_t)(kb * 16) * TROW + nb * 32u);
                mma_bf16(o[nb * 2],     af[0], af[1], af[2], af[3], bf[0], bf[1]);
                mma_bf16(o[nb * 2 + 1], af[0], af[1], af[2], af[3], bf[2], bf[3]);
            }
        }

        __syncthreads();
        if (jt + 2 < ntiles) {
            const int j2 = (jt + 2) * 64;
            const uint32_t kvb = kv_u32 + (uint32_t)(jt & 1) * KVBUF;
            #pragma unroll
            for (int i = 0; i < 4; i++) {
                const int idx = tid + i * 128;
                const int r = idx >> 3, j = idx & 7;
                cp16(kvb + r * TROW + j * 16u,          K + base + (size_t)(j2 + r) * HD + j * 8);
                cp16(kvb + TILE_B + r * TROW + j * 16u, V + base + (size_t)(j2 + r) * HD + j * 8);
            }
        }
        cp_commit();
    }

    const float inv1 = 1.0f / l1;
    const float inv2 = 1.0f / l2;
    #pragma unroll
    for (int nt = 0; nt < 8; nt++) {
        const int cb = nt * 8 + 2 * tg;
        *reinterpret_cast<uint32_t*>(O + base + (size_t)(q0 + row1) * HD + cb) =
            packbf(o[nt][0] * inv1, o[nt][1] * inv1);
        *reinterpret_cast<uint32_t*>(O + base + (size_t)(q0 + row2) * HD + cb) =
            packbf(o[nt][2] * inv2, o[nt][3] * inv2);
    }
}

// ---------------- launch ----------------------------------------------------
extern "C" void kernel_launch(void* const* d_in, const int* in_sizes, int n_in,
                              void* d_out, int out_size) {
    const float* x     = (const float*)d_in[0];
    const float* gamma = (const float*)d_in[1];
    const float* beta  = (const float*)d_in[2];
    const float* Wq    = (const float*)d_in[3];
    const float* bq    = (const float*)d_in[4];
    const float* Wk    = (const float*)d_in[5];
    const float* bk    = (const float*)d_in[6];
    const float* Wv    = (const float*)d_in[7];
    const float* bv    = (const float*)d_in[8];
    const float* Wo    = (const float*)d_in[9];
    const float* bo    = (const float*)d_in[10];
    float* out = (float*)d_out;

    __nv_bfloat16 *xn, *qp, *kp, *vp, *ao, *wt;
    cudaGetSymbolAddress((void**)&xn, g_xn);
    cudaGetSymbolAddress((void**)&qp, g_q);
    cudaGetSymbolAddress((void**)&kp, g_k);
    cudaGetSymbolAddress((void**)&vp, g_v);
    cudaGetSymbolAddress((void**)&ao, g_ao);
    cudaGetSymbolAddress((void**)&wt, g_wt);

    ln_kernel<<<Mrows, 256>>>(x, gamma, beta, xn);
    transpose_kernel<<<dim3(32, 32, 4), 256>>>(Wq, Wk, Wv, Wo, wt);

    cudaFuncSetAttribute(qkv_gemm_kernel, cudaFuncAttributeMaxDynamicSharedMemorySize,
                         GEMM_SMEM_BYTES);
    cudaFuncSetAttribute(o_gemm_kernel, cudaFuncAttributeMaxDynamicSharedMemorySize,
                         GEMM_SMEM_BYTES);

    qkv_gemm_kernel<<<dim3(24, Mrows / 128), 256, GEMM_SMEM_BYTES>>>(
        xn, wt, bq, bk, bv, qp, kp, vp);

    cudaFuncSetAttribute(attn_bf16_kernel, cudaFuncAttributeMaxDynamicSharedMemorySize,
                         ATTN_SMEM_BYTES);
    attn_bf16_kernel<<<dim3(Sdim / 64, Hdim, Bdim), 128, ATTN_SMEM_BYTES>>>(qp, kp, vp, ao);

    o_gemm_kernel<<<dim3(8, Mrows / 128), 256, GEMM_SMEM_BYTES>>>(ao, wt, bo, x, out);
}

// round 8
// speedup vs baseline: 7.6582x; 1.0323x over previous
#include <cuda_runtime.h>
#include <cuda_bf16.h>
#include <math.h>
#include <stdint.h>

#define Bdim 4
#define Sdim 2048
#define Edim 1024
#define Hdim 16
#define Ddim 64
#define Mrows (Bdim * Sdim)          // 8192
#define HD (Hdim * Ddim)             // 1024
#define GK 1024

// ---------------- scratch (static device globals; no allocs) ----------------
__device__ __nv_bfloat16 g_xn[Mrows * Edim];
__device__ __nv_bfloat16 g_q [Mrows * HD];
__device__ __nv_bfloat16 g_k [Mrows * HD];
__device__ __nv_bfloat16 g_v [Mrows * HD];
__device__ __nv_bfloat16 g_ao[Mrows * HD];
__device__ __nv_bfloat16 g_wt[4 * GK * GK];   // transposed weights [N][K] bf16

// ---------------- helpers ----------------------------------------------------
__device__ __forceinline__ uint32_t packbf(float lo, float hi) {
    uint32_t d;
    asm("cvt.rn.bf16x2.f32 %0, %1, %2;" : "=r"(d) : "f"(hi), "f"(lo));
    return d;
}

// D(16x8) += A(16x16,row) * B(16x8,col)  bf16 -> fp32
__device__ __forceinline__ void mma_bf16(float c[4],
                                         uint32_t a0, uint32_t a1, uint32_t a2, uint32_t a3,
                                         uint32_t b0, uint32_t b1) {
    asm volatile(
        "mma.sync.aligned.m16n8k16.row.col.f32.bf16.bf16.f32 "
        "{%0,%1,%2,%3}, {%4,%5,%6,%7}, {%8,%9}, {%0,%1,%2,%3};\n"
        : "+f"(c[0]), "+f"(c[1]), "+f"(c[2]), "+f"(c[3])
        : "r"(a0), "r"(a1), "r"(a2), "r"(a3), "r"(b0), "r"(b1));
}

__device__ __forceinline__ void ldsm4(uint32_t r[4], uint32_t addr) {
    asm volatile("ldmatrix.sync.aligned.m8n8.x4.shared.b16 {%0,%1,%2,%3}, [%4];"
                 : "=r"(r[0]), "=r"(r[1]), "=r"(r[2]), "=r"(r[3])
                 : "r"(addr));
}
__device__ __forceinline__ void ldsm4t(uint32_t r[4], uint32_t addr) {
    asm volatile("ldmatrix.sync.aligned.m8n8.x4.trans.shared.b16 {%0,%1,%2,%3}, [%4];"
                 : "=r"(r[0]), "=r"(r[1]), "=r"(r[2]), "=r"(r[3])
                 : "r"(addr));
}

__device__ __forceinline__ void cp16(uint32_t dst, const void* src) {
    asm volatile("cp.async.cg.shared.global [%0], [%1], 16;" :: "r"(dst), "l"(src));
}
__device__ __forceinline__ void cp_commit() {
    asm volatile("cp.async.commit_group;");
}
template <int N>
__device__ __forceinline__ void cp_wait() {
    asm volatile("cp.async.wait_group %0;" :: "n"(N));
}

// ---------------- LayerNorm (fp32 in -> bf16 out) ----------------------------
__global__ void __launch_bounds__(256) ln_kernel(const float* __restrict__ x,
                                                 const float* __restrict__ gamma,
                                                 const float* __restrict__ beta,
                                                 __nv_bfloat16* __restrict__ y) {
    const int row = blockIdx.x;
    const int tid = threadIdx.x;
    const float4 xv = reinterpret_cast<const float4*>(x + (size_t)row * Edim)[tid];
    float s  = xv.x + xv.y + xv.z + xv.w;
    float ss = xv.x * xv.x + xv.y * xv.y + xv.z * xv.z + xv.w * xv.w;
    #pragma unroll
    for (int m = 16; m; m >>= 1) {
        s  += __shfl_xor_sync(0xffffffffu, s,  m);
        ss += __shfl_xor_sync(0xffffffffu, ss, m);
    }
    __shared__ float sh_s[8], sh_ss[8];
    __shared__ float s_mu, s_rstd;
    const int w = tid >> 5, l = tid & 31;
    if (l == 0) { sh_s[w] = s; sh_ss[w] = ss; }
    __syncthreads();
    if (w == 0) {
        float a = (l < 8) ? sh_s[l]  : 0.f;
        float c = (l < 8) ? sh_ss[l] : 0.f;
        #pragma unroll
        for (int m = 4; m; m >>= 1) {
            a += __shfl_xor_sync(0xffffffffu, a, m);
            c += __shfl_xor_sync(0xffffffffu, c, m);
        }
        if (l == 0) {
            float mu  = a * (1.0f / Edim);
            float var = c * (1.0f / Edim) - mu * mu;
            s_mu = mu;
            s_rstd = rsqrtf(var + 1e-5f);
        }
    }
    __syncthreads();
    const float mu = s_mu, rstd = s_rstd;
    const float4 gv = reinterpret_cast<const float4*>(gamma)[tid];
    const float4 bv = reinterpret_cast<const float4*>(beta)[tid];
    uint2 o2;
    o2.x = packbf((xv.x - mu) * rstd * gv.x + bv.x, (xv.y - mu) * rstd * gv.y + bv.y);
    o2.y = packbf((xv.z - mu) * rstd * gv.z + bv.z, (xv.w - mu) * rstd * gv.w + bv.w);
    *reinterpret_cast<uint2*>(y + (size_t)row * Edim + tid * 4) = o2;
}

// ---------------- weight transpose: W[K,N] fp32 -> WT[N,K] bf16 --------------
__global__ void __launch_bounds__(256) transpose_kernel(const float* __restrict__ Wq,
                                                        const float* __restrict__ Wk,
                                                        const float* __restrict__ Wv,
                                                        const float* __restrict__ Wo,
                                                        __nv_bfloat16* __restrict__ wt) {
    __shared__ float t[32][33];
    const int z = blockIdx.z;
    const float* W = (z == 0) ? Wq : (z == 1) ? Wk : (z == 2) ? Wv : Wo;
    __nv_bfloat16* T = wt + (size_t)z * GK * GK;
    const int x0 = blockIdx.x * 32, y0 = blockIdx.y * 32;
    const int tx = threadIdx.x & 31, ty = threadIdx.x >> 5;   // 32x8
    #pragma unroll
    for (int i = 0; i < 32; i += 8)
        t[ty + i][tx] = W[(size_t)(y0 + ty + i) * GK + x0 + tx];
    __syncthreads();
    #pragma unroll
    for (int i = 0; i < 32; i += 8)
        T[(size_t)(x0 + ty + i) * GK + y0 + tx] = __float2bfloat16(t[tx][ty + i]);
}

// ---------------- bf16 GEMM: 128x128 tile, BK=32, 3-stage cp.async ----------
#define BK 32
#define ROWB 80u
#define STG_A 0u
#define STG_B 10240u
#define STAGE_BYTES 20480u
#define GSTAGES 3
#define GEMM_SMEM_BYTES (GSTAGES * STAGE_BYTES)

template <bool BF16OUT>
__device__ __forceinline__ void gemm_body(const __nv_bfloat16* __restrict__ A,
                                          const __nv_bfloat16* __restrict__ WT,
                                          const float* __restrict__ bias,
                                          const float* __restrict__ res,
                                          void* __restrict__ C,
                                          int bx, int by, float oscale) {
    extern __shared__ __align__(16) char smem[];
    const uint32_t s0 = (uint32_t)__cvta_generic_to_shared(smem);

    const int tid  = threadIdx.x;
    const int lane = tid & 31;
    const int wid  = tid >> 5;
    const int g  = lane >> 2;
    const int tg = lane & 3;
    const int wm = wid >> 2;
    const int wn = wid & 3;
    const int row0 = by * 128;
    const int col0 = bx * 128;
    const int N = 1024;

    const uint32_t a_off = STG_A + (uint32_t)(wm * 64 + (lane & 15)) * ROWB
                                 + (uint32_t)((lane >> 4) << 4);
    const uint32_t b_off = STG_B + (uint32_t)(wn * 32 + (lane & 7) + ((lane >> 4) << 3)) * ROWB
                                 + (uint32_t)(((lane >> 3) & 1) << 4);

    auto issue_tile = [&](int t) {
        const uint32_t sb = s0 + (uint32_t)(t % GSTAGES) * STAGE_BYTES;
        const int gk = t * BK;
        #pragma unroll
        for (int i = 0; i < 4; i++) {
            const int idx = tid + i * 256;
            const int r = (idx & 511) >> 2;
            const int j = idx & 3;
            if (idx < 512)
                cp16(sb + STG_A + r * ROWB + j * 16u,
                     A + (size_t)(row0 + r) * GK + gk + j * 8);
            else
                cp16(sb + STG_B + r * ROWB + j * 16u,
                     WT + (size_t)(col0 + r) * GK + gk + j * 8);
        }
        cp_commit();
    };

    issue_tile(0);
    issue_tile(1);

    float acc[4][4][4] = {};
    const int NIT = GK / BK;     // 32

    for (int it = 0; it < NIT; it++) {
        cp_wait<GSTAGES - 2>();
        __syncthreads();

        if (it + GSTAGES - 1 < NIT) issue_tile(it + GSTAGES - 1);
        else cp_commit();

        const uint32_t sb = s0 + (uint32_t)(it % GSTAGES) * STAGE_BYTES;
        #pragma unroll
        for (int kb = 0; kb < 2; kb++) {
            uint32_t af[4][4], bf[2][4];
            #pragma unroll
            for (int mi = 0; mi < 4; mi++)
                ldsm4(af[mi], sb + a_off + (uint32_t)(mi * 16) * ROWB + kb * 32u);
            #pragma unroll
            for (int nb = 0; nb < 2; nb++)
                ldsm4(bf[nb], sb + b_off + (uint32_t)(nb * 16) * ROWB + kb * 32u);
            #pragma unroll
            for (int mi = 0; mi < 4; mi++)
                #pragma unroll
                for (int nb = 0; nb < 2; nb++) {
                    mma_bf16(acc[mi][nb * 2],     af[mi][0], af[mi][1], af[mi][2], af[mi][3],
                             bf[nb][0], bf[nb][1]);
                    mma_bf16(acc[mi][nb * 2 + 1], af[mi][0], af[mi][1], af[mi][2], af[mi][3],
                             bf[nb][2], bf[nb][3]);
                }
        }
        __syncthreads();
    }

    #pragma unroll
    for (int mi = 0; mi < 4; mi++) {
        const int r1 = row0 + wm * 64 + mi * 16 + g;
        const int r2 = r1 + 8;
        #pragma unroll
        for (int ni = 0; ni < 4; ni++) {
            const int cb = col0 + wn * 32 + ni * 8 + 2 * tg;
            float v0 = (acc[mi][ni][0] + bias[cb])     * oscale;
            float v1 = (acc[mi][ni][1] + bias[cb + 1]) * oscale;
            float v2 = (acc[mi][ni][2] + bias[cb])     * oscale;
            float v3 = (acc[mi][ni][3] + bias[cb + 1]) * oscale;
            if (BF16OUT) {
                ((uint32_t*)C)[(size_t)r1 * (N / 2) + (cb >> 1)] = packbf(v0, v1);
                ((uint32_t*)C)[(size_t)r2 * (N / 2) + (cb >> 1)] = packbf(v2, v3);
            } else {
                const float2 r1v = *reinterpret_cast<const float2*>(res + (size_t)r1 * N + cb);
                const float2 r2v = *reinterpret_cast<const float2*>(res + (size_t)r2 * N + cb);
                float2 w1; w1.x = v0 + r1v.x; w1.y = v1 + r1v.y;
                float2 w2; w2.x = v2 + r2v.x; w2.y = v3 + r2v.y;
                *reinterpret_cast<float2*>((float*)C + (size_t)r1 * N + cb) = w1;
                *reinterpret_cast<float2*>((float*)C + (size_t)r2 * N + cb) = w2;
            }
        }
    }
}

// fused QKV: grid (24, 64); Q output pre-scaled by 1/sqrt(D)
__global__ void __launch_bounds__(256, 2) qkv_gemm_kernel(const __nv_bfloat16* __restrict__ A,
                                                          const __nv_bfloat16* __restrict__ wt,
                                                          const float* __restrict__ bq,
                                                          const float* __restrict__ bk,
                                                          const float* __restrict__ bv,
                                                          __nv_bfloat16* __restrict__ Cq,
                                                          __nv_bfloat16* __restrict__ Ck,
                                                          __nv_bfloat16* __restrict__ Cv) {
    const int mat = blockIdx.x >> 3;
    const int bx  = blockIdx.x & 7;
    const __nv_bfloat16* WT = wt + (size_t)mat * GK * GK;
    const float* bias = (mat == 0) ? bq : (mat == 1) ? bk : bv;
    __nv_bfloat16* C  = (mat == 0) ? Cq : (mat == 1) ? Ck : Cv;
    const float sc = (mat == 0) ? 0.125f : 1.0f;
    gemm_body<true>(A, WT, bias, nullptr, C, bx, blockIdx.y, sc);
}

__global__ void __launch_bounds__(256, 2) o_gemm_kernel(const __nv_bfloat16* __restrict__ A,
                                                        const __nv_bfloat16* __restrict__ wt,
                                                        const float* __restrict__ bo,
                                                        const float* __restrict__ res,
                                                        float* __restrict__ out) {
    gemm_body<false>(A, wt + (size_t)3 * GK * GK, bo, res, out, blockIdx.x, blockIdx.y, 1.0f);
}

// ---------------- Flash attention (causal), bf16, in-register P -------------
// grid (S/128, H, B), 128 threads (4 warps). Warp w owns 32 query rows.
// smem: Q tile 128x128B (stride 144) + 2 KV double buffers. No P tile.
#define TROW 144u
#define QTILE_B (128u * TROW)            // 18432
#define KVTILE_B (64u * TROW)            // 9216
#define KVBUF (2u * KVTILE_B)            // K+V per buffer
#define ATTN_SMEM_BYTES (QTILE_B + 2 * KVBUF)   // 55296

__global__ void __launch_bounds__(128, 2) attn_bf16_kernel(const __nv_bfloat16* __restrict__ Q,
                                                           const __nv_bfloat16* __restrict__ K,
                                                           const __nv_bfloat16* __restrict__ V,
                                                           __nv_bfloat16* __restrict__ O) {
    extern __shared__ __align__(16) char sm[];
    const uint32_t q_u32  = (uint32_t)__cvta_generic_to_shared(sm);
    const uint32_t kv_u32 = q_u32 + QTILE_B;

    const int tid  = threadIdx.x;
    const int lane = tid & 31;
    const int wid  = tid >> 5;           // 0..3
    const int g  = lane >> 2;
    const int tg = lane & 3;
    const int rbase = wid * 32;          // warp owns rows rbase..rbase+31
    const int q0 = blockIdx.x * 128;
    const int h = blockIdx.y, b = blockIdx.z;
    const size_t base = (size_t)b * Sdim * HD + (size_t)h * Ddim;

    // LDSM lane bases
    const uint32_t q_loff0 = (uint32_t)(rbase +      (lane & 15)) * TROW + (uint32_t)((lane >> 4) << 4);
    const uint32_t q_loff1 = (uint32_t)(rbase + 16 + (lane & 15)) * TROW + (uint32_t)((lane >> 4) << 4);
    const uint32_t b_loff  = (uint32_t)((lane & 7) + ((lane >> 4) << 3)) * TROW
                           + (uint32_t)(((lane >> 3) & 1) << 4);
    const uint32_t v_loff  = (uint32_t)((lane & 7) + (((lane >> 3) & 1) << 3)) * TROW
                           + (uint32_t)((lane >> 4) << 4);

    const int ntiles = (q0 >> 6) + 2;

    // prologue: G0 = Q(128 rows) + KV tile 0 ; G1 = KV tile 1
    #pragma unroll
    for (int i = 0; i < 8; i++) {
        const int idx = tid + i * 128;
        const int r = idx >> 3, j = idx & 7;
        cp16(q_u32 + r * TROW + j * 16u, Q + base + (size_t)(q0 + r) * HD + j * 8);
    }
    #pragma unroll
    for (int i = 0; i < 8; i++) {
        const int idx = tid + i * 128;
        const int j = idx & 7;
        if (idx < 512) {
            const int r = idx >> 3;
            cp16(kv_u32 + r * TROW + j * 16u, K + base + (size_t)r * HD + j * 8);
        } else {
            const int r = (idx - 512) >> 3;
            cp16(kv_u32 + KVTILE_B + r * TROW + j * 16u, V + base + (size_t)r * HD + j * 8);
        }
    }
    cp_commit();
    {
        const uint32_t kvb = kv_u32 + KVBUF;
        #pragma unroll
        for (int i = 0; i < 8; i++) {
            const int idx = tid + i * 128;
            const int j = idx & 7;
            if (idx < 512) {
                const int r = idx >> 3;
                cp16(kvb + r * TROW + j * 16u, K + base + (size_t)(64 + r) * HD + j * 8);
            } else {
                const int r = (idx - 512) >> 3;
                cp16(kvb + KVTILE_B + r * TROW + j * 16u, V + base + (size_t)(64 + r) * HD + j * 8);
            }
        }
    }
    cp_commit();

    float m[2][2], l[2][2];
    m[0][0] = m[0][1] = m[1][0] = m[1][1] = -1e30f;
    l[0][0] = l[0][1] = l[1][0] = l[1][1] = 0.f;
    float o[2][8][4] = {};
    const int grow_base = q0 + rbase;    // warp's first global query row

    for (int jt = 0; jt < ntiles; jt++) {
        cp_wait<1>();
        __syncthreads();

        const int j0 = jt * 64;
        const uint32_t kb32 = kv_u32 + (uint32_t)(jt & 1) * KVBUF;
        const uint32_t vb32 = kb32 + KVTILE_B;
        const bool active = (j0 <= grow_base + 31);   // warp-uniform

        if (active) {
            // S = Q K^T for both 16-row groups
            float s[2][8][4] = {};
            #pragma unroll
            for (int kb = 0; kb < 4; kb++) {
                uint32_t af0[4], af1[4];
                ldsm4(af0, q_u32 + q_loff0 + kb * 32u);
                ldsm4(af1, q_u32 + q_loff1 + kb * 32u);
                #pragma unroll
                for (int nb = 0; nb < 4; nb++) {
                    uint32_t bf[4];
                    ldsm4(bf, kb32 + b_loff + (uint32_t)(nb * 16) * TROW + kb * 32u);
                    mma_bf16(s[0][nb * 2],     af0[0], af0[1], af0[2], af0[3], bf[0], bf[1]);
                    mma_bf16(s[0][nb * 2 + 1], af0[0], af0[1], af0[2], af0[3], bf[2], bf[3]);
                    mma_bf16(s[1][nb * 2],     af1[0], af1[1], af1[2], af1[3], bf[0], bf[1]);
                    mma_bf16(s[1][nb * 2 + 1], af1[0], af1[1], af1[2], af1[3], bf[2], bf[3]);
                }
            }

            // online softmax per group; p stored back into s[][][]
            float sc[2][2];
            #pragma unroll
            for (int gi = 0; gi < 2; gi++) {
                const int grow1 = grow_base + gi * 16 + g;
                const int grow2 = grow1 + 8;
                const bool diag = (j0 + 63 > grow_base + gi * 16);
                float rm1 = -1e30f, rm2 = -1e30f;
                #pragma unroll
                for (int nt = 0; nt < 8; nt++) {
                    if (diag) {
                        const int c0 = j0 + nt * 8 + 2 * tg;
                        if (c0     > grow1) s[gi][nt][0] = -1e30f;
                        if (c0 + 1 > grow1) s[gi][nt][1] = -1e30f;
                        if (c0     > grow2) s[gi][nt][2] = -1e30f;
                        if (c0 + 1 > grow2) s[gi][nt][3] = -1e30f;
                    }
                    rm1 = fmaxf(rm1, fmaxf(s[gi][nt][0], s[gi][nt][1]));
                    rm2 = fmaxf(rm2, fmaxf(s[gi][nt][2], s[gi][nt][3]));
                }
                rm1 = fmaxf(rm1, __shfl_xor_sync(0xffffffffu, rm1, 1));
                rm1 = fmaxf(rm1, __shfl_xor_sync(0xffffffffu, rm1, 2));
                rm2 = fmaxf(rm2, __shfl_xor_sync(0xffffffffu, rm2, 1));
                rm2 = fmaxf(rm2, __shfl_xor_sync(0xffffffffu, rm2, 2));

                const float mn1 = fmaxf(m[gi][0], rm1), mn2 = fmaxf(m[gi][1], rm2);
                sc[gi][0] = __expf(m[gi][0] - mn1);
                sc[gi][1] = __expf(m[gi][1] - mn2);
                m[gi][0] = mn1; m[gi][1] = mn2;

                float sum1 = 0.f, sum2 = 0.f;
                #pragma unroll
                for (int nt = 0; nt < 8; nt++) {
                    s[gi][nt][0] = __expf(s[gi][nt][0] - mn1);
                    s[gi][nt][1] = __expf(s[gi][nt][1] - mn1);
                    s[gi][nt][2] = __expf(s[gi][nt][2] - mn2);
                    s[gi][nt][3] = __expf(s[gi][nt][3] - mn2);
                    sum1 += s[gi][nt][0] + s[gi][nt][1];
                    sum2 += s[gi][nt][2] + s[gi][nt][3];
                }
                sum1 += __shfl_xor_sync(0xffffffffu, sum1, 1);
                sum1 += __shfl_xor_sync(0xffffffffu, sum1, 2);
                sum2 += __shfl_xor_sync(0xffffffffu, sum2, 1);
                sum2 += __shfl_xor_sync(0xffffffffu, sum2, 2);
                l[gi][0] = l[gi][0] * sc[gi][0] + sum1;
                l[gi][1] = l[gi][1] * sc[gi][1] + sum2;

                #pragma unroll
                for (int nt = 0; nt < 8; nt++) {
                    o[gi][nt][0] *= sc[gi][0]; o[gi][nt][1] *= sc[gi][0];
                    o[gi][nt][2] *= sc[gi][1]; o[gi][nt][3] *= sc[gi][1];
                }
            }

            // O += P V : P A-fragments built directly from S C-fragments
            #pragma unroll
            for (int kb = 0; kb < 4; kb++) {
                uint32_t pa[2][4];
                #pragma unroll
                for (int gi = 0; gi < 2; gi++) {
                    pa[gi][0] = packbf(s[gi][2 * kb][0],     s[gi][2 * kb][1]);
                    pa[gi][1] = packbf(s[gi][2 * kb][2],     s[gi][2 * kb][3]);
                    pa[gi][2] = packbf(s[gi][2 * kb + 1][0], s[gi][2 * kb + 1][1]);
                    pa[gi][3] = packbf(s[gi][2 * kb + 1][2], s[gi][2 * kb + 1][3]);
                }
                #pragma unroll
                for (int nb = 0; nb < 4; nb++) {
                    uint32_t bf[4];
                    ldsm4t(bf, vb32 + v_loff + (uint32_t)(kb * 16) * TROW + nb * 32u);
                    mma_bf16(o[0][nb * 2],     pa[0][0], pa[0][1], pa[0][2], pa[0][3], bf[0], bf[1]);
                    mma_bf16(o[0][nb * 2 + 1], pa[0][0], pa[0][1], pa[0][2], pa[0][3], bf[2], bf[3]);
                    mma_bf16(o[1][nb * 2],     pa[1][0], pa[1][1], pa[1][2], pa[1][3], bf[0], bf[1]);
                    mma_bf16(o[1][nb * 2 + 1], pa[1][0], pa[1][1], pa[1][2], pa[1][3], bf[2], bf[3]);
                }
            }
        }

        __syncthreads();
        if (jt + 2 < ntiles) {
            const int j2 = (jt + 2) * 64;
            const uint32_t kvb = kv_u32 + (uint32_t)(jt & 1) * KVBUF;
            #pragma unroll
            for (int i = 0; i < 8; i++) {
                const int idx = tid + i * 128;
                const int j = idx & 7;
                if (idx < 512) {
                    const int r = idx >> 3;
                    cp16(kvb + r * TROW + j * 16u, K + base + (size_t)(j2 + r) * HD + j * 8);
                } else {
                    const int r = (idx - 512) >> 3;
                    cp16(kvb + KVTILE_B + r * TROW + j * 16u,
                         V + base + (size_t)(j2 + r) * HD + j * 8);
                }
            }
        }
        cp_commit();
    }

    #pragma unroll
    for (int gi = 0; gi < 2; gi++) {
        const int grow1 = grow_base + gi * 16 + g;
        const int grow2 = grow1 + 8;
        const float inv1 = 1.0f / l[gi][0];
        const float inv2 = 1.0f / l[gi][1];
        #pragma unroll
        for (int nt = 0; nt < 8; nt++) {
            const int cb = nt * 8 + 2 * tg;
            *reinterpret_cast<uint32_t*>(O + base + (size_t)grow1 * HD + cb) =
                packbf(o[gi][nt][0] * inv1, o[gi][nt][1] * inv1);
            *reinterpret_cast<uint32_t*>(O + base + (size_t)grow2 * HD + cb) =
                packbf(o[gi][nt][2] * inv2, o[gi][nt][3] * inv2);
        }
    }
}

// ---------------- launch ----------------------------------------------------
extern "C" void kernel_launch(void* const* d_in, const int* in_sizes, int n_in,
                              void* d_out, int out_size) {
    const float* x     = (const float*)d_in[0];
    const float* gamma = (const float*)d_in[1];
    const float* beta  = (const float*)d_in[2];
    const float* Wq    = (const float*)d_in[3];
    const float* bq    = (const float*)d_in[4];
    const float* Wk    = (const float*)d_in[5];
    const float* bk    = (const float*)d_in[6];
    const float* Wv    = (const float*)d_in[7];
    const float* bv    = (const float*)d_in[8];
    const float* Wo    = (const float*)d_in[9];
    const float* bo    = (const float*)d_in[10];
    float* out = (float*)d_out;

    __nv_bfloat16 *xn, *qp, *kp, *vp, *ao, *wt;
    cudaGetSymbolAddress((void**)&xn, g_xn);
    cudaGetSymbolAddress((void**)&qp, g_q);
    cudaGetSymbolAddress((void**)&kp, g_k);
    cudaGetSymbolAddress((void**)&vp, g_v);
    cudaGetSymbolAddress((void**)&ao, g_ao);
    cudaGetSymbolAddress((void**)&wt, g_wt);

    ln_kernel<<<Mrows, 256>>>(x, gamma, beta, xn);
    transpose_kernel<<<dim3(32, 32, 4), 256>>>(Wq, Wk, Wv, Wo, wt);

    cudaFuncSetAttribute(qkv_gemm_kernel, cudaFuncAttributeMaxDynamicSharedMemorySize,
                         GEMM_SMEM_BYTES);
    cudaFuncSetAttribute(o_gemm_kernel, cudaFuncAttributeMaxDynamicSharedMemorySize,
                         GEMM_SMEM_BYTES);

    qkv_gemm_kernel<<<dim3(24, Mrows / 128), 256, GEMM_SMEM_BYTES>>>(
        xn, wt, bq, bk, bv, qp, kp, vp);

    cudaFuncSetAttribute(attn_bf16_kernel, cudaFuncAttributeMaxDynamicSharedMemorySize,
                         ATTN_SMEM_BYTES);
    attn_bf16_kernel<<<dim3(Sdim / 128, Hdim, Bdim), 128, ATTN_SMEM_BYTES>>>(qp, kp, vp, ao);

    o_gemm_kernel<<<dim3(8, Mrows / 128), 256, GEMM_SMEM_BYTES>>>(ao, wt, bo, x, out);
}

// round 9
// speedup vs baseline: 7.6610x; 1.0004x over previous
#include <cuda_runtime.h>
#include <cuda_bf16.h>
#include <math.h>
#include <stdint.h>

#define Bdim 4
#define Sdim 2048
#define Edim 1024
#define Hdim 16
#define Ddim 64
#define Mrows (Bdim * Sdim)          // 8192
#define HD (Hdim * Ddim)             // 1024
#define GK 1024

// ---------------- scratch (static device globals; no allocs) ----------------
__device__ __nv_bfloat16 g_xn[Mrows * Edim];
__device__ __nv_bfloat16 g_q [Mrows * HD];
__device__ __nv_bfloat16 g_k [Mrows * HD];
__device__ __nv_bfloat16 g_v [Mrows * HD];
__device__ __nv_bfloat16 g_ao[Mrows * HD];
__device__ __nv_bfloat16 g_wt[4 * GK * GK];   // transposed weights [N][K] bf16

// ---------------- helpers ----------------------------------------------------
__device__ __forceinline__ uint32_t packbf(float lo, float hi) {
    uint32_t d;
    asm("cvt.rn.bf16x2.f32 %0, %1, %2;" : "=r"(d) : "f"(hi), "f"(lo));
    return d;
}

// D(16x8) += A(16x16,row) * B(16x8,col)  bf16 -> fp32
__device__ __forceinline__ void mma_bf16(float c[4],
                                         uint32_t a0, uint32_t a1, uint32_t a2, uint32_t a3,
                                         uint32_t b0, uint32_t b1) {
    asm volatile(
        "mma.sync.aligned.m16n8k16.row.col.f32.bf16.bf16.f32 "
        "{%0,%1,%2,%3}, {%4,%5,%6,%7}, {%8,%9}, {%0,%1,%2,%3};\n"
        : "+f"(c[0]), "+f"(c[1]), "+f"(c[2]), "+f"(c[3])
        : "r"(a0), "r"(a1), "r"(a2), "r"(a3), "r"(b0), "r"(b1));
}

__device__ __forceinline__ void ldsm4(uint32_t r[4], uint32_t addr) {
    asm volatile("ldmatrix.sync.aligned.m8n8.x4.shared.b16 {%0,%1,%2,%3}, [%4];"
                 : "=r"(r[0]), "=r"(r[1]), "=r"(r[2]), "=r"(r[3])
                 : "r"(addr));
}
__device__ __forceinline__ void ldsm4t(uint32_t r[4], uint32_t addr) {
    asm volatile("ldmatrix.sync.aligned.m8n8.x4.trans.shared.b16 {%0,%1,%2,%3}, [%4];"
                 : "=r"(r[0]), "=r"(r[1]), "=r"(r[2]), "=r"(r[3])
                 : "r"(addr));
}

__device__ __forceinline__ void cp16(uint32_t dst, const void* src) {
    asm volatile("cp.async.cg.shared.global [%0], [%1], 16;" :: "r"(dst), "l"(src));
}
__device__ __forceinline__ void cp_commit() {
    asm volatile("cp.async.commit_group;");
}
template <int N>
__device__ __forceinline__ void cp_wait() {
    asm volatile("cp.async.wait_group %0;" :: "n"(N));
}

// ---------------- LayerNorm (fp32 in -> bf16 out) ----------------------------
__global__ void __launch_bounds__(256) ln_kernel(const float* __restrict__ x,
                                                 const float* __restrict__ gamma,
                                                 const float* __restrict__ beta,
                                                 __nv_bfloat16* __restrict__ y) {
    const int row = blockIdx.x;
    const int tid = threadIdx.x;
    const float4 xv = reinterpret_cast<const float4*>(x + (size_t)row * Edim)[tid];
    float s  = xv.x + xv.y + xv.z + xv.w;
    float ss = xv.x * xv.x + xv.y * xv.y + xv.z * xv.z + xv.w * xv.w;
    #pragma unroll
    for (int m = 16; m; m >>= 1) {
        s  += __shfl_xor_sync(0xffffffffu, s,  m);
        ss += __shfl_xor_sync(0xffffffffu, ss, m);
    }
    __shared__ float sh_s[8], sh_ss[8];
    __shared__ float s_mu, s_rstd;
    const int w = tid >> 5, l = tid & 31;
    if (l == 0) { sh_s[w] = s; sh_ss[w] = ss; }
    __syncthreads();
    if (w == 0) {
        float a = (l < 8) ? sh_s[l]  : 0.f;
        float c = (l < 8) ? sh_ss[l] : 0.f;
        #pragma unroll
        for (int m = 4; m; m >>= 1) {
            a += __shfl_xor_sync(0xffffffffu, a, m);
            c += __shfl_xor_sync(0xffffffffu, c, m);
        }
        if (l == 0) {
            float mu  = a * (1.0f / Edim);
            float var = c * (1.0f / Edim) - mu * mu;
            s_mu = mu;
            s_rstd = rsqrtf(var + 1e-5f);
        }
    }
    __syncthreads();
    const float mu = s_mu, rstd = s_rstd;
    const float4 gv = reinterpret_cast<const float4*>(gamma)[tid];
    const float4 bv = reinterpret_cast<const float4*>(beta)[tid];
    uint2 o2;
    o2.x = packbf((xv.x - mu) * rstd * gv.x + bv.x, (xv.y - mu) * rstd * gv.y + bv.y);
    o2.y = packbf((xv.z - mu) * rstd * gv.z + bv.z, (xv.w - mu) * rstd * gv.w + bv.w);
    *reinterpret_cast<uint2*>(y + (size_t)row * Edim + tid * 4) = o2;
}

// ---------------- weight transpose: W[K,N] fp32 -> WT[N,K] bf16 --------------
__global__ void __launch_bounds__(256) transpose_kernel(const float* __restrict__ Wq,
                                                        const float* __restrict__ Wk,
                                                        const float* __restrict__ Wv,
                                                        const float* __restrict__ Wo,
                                                        __nv_bfloat16* __restrict__ wt) {
    __shared__ float t[32][33];
    const int z = blockIdx.z;
    const float* W = (z == 0) ? Wq : (z == 1) ? Wk : (z == 2) ? Wv : Wo;
    __nv_bfloat16* T = wt + (size_t)z * GK * GK;
    const int x0 = blockIdx.x * 32, y0 = blockIdx.y * 32;
    const int tx = threadIdx.x & 31, ty = threadIdx.x >> 5;   // 32x8
    #pragma unroll
    for (int i = 0; i < 32; i += 8)
        t[ty + i][tx] = W[(size_t)(y0 + ty + i) * GK + x0 + tx];
    __syncthreads();
    #pragma unroll
    for (int i = 0; i < 32; i += 8)
        T[(size_t)(x0 + ty + i) * GK + y0 + tx] = __float2bfloat16(t[tx][ty + i]);
}

// ---------------- bf16 GEMM: 128x128 tile, BK=32, 3-stage cp.async ----------
#define BK 32
#define ROWB 80u
#define STG_A 0u
#define STG_B 10240u
#define STAGE_BYTES 20480u
#define GSTAGES 3
#define GEMM_SMEM_BYTES (GSTAGES * STAGE_BYTES)

template <bool BF16OUT>
__device__ __forceinline__ void gemm_body(const __nv_bfloat16* __restrict__ A,
                                          const __nv_bfloat16* __restrict__ WT,
                                          const float* __restrict__ bias,
                                          const float* __restrict__ res,
                                          void* __restrict__ C,
                                          int bx, int by, float oscale) {
    extern __shared__ __align__(16) char smem[];
    const uint32_t s0 = (uint32_t)__cvta_generic_to_shared(smem);

    const int tid  = threadIdx.x;
    const int lane = tid & 31;
    const int wid  = tid >> 5;
    const int g  = lane >> 2;
    const int tg = lane & 3;
    const int wm = wid >> 2;
    const int wn = wid & 3;
    const int row0 = by * 128;
    const int col0 = bx * 128;
    const int N = 1024;

    const uint32_t a_off = STG_A + (uint32_t)(wm * 64 + (lane & 15)) * ROWB
                                 + (uint32_t)((lane >> 4) << 4);
    const uint32_t b_off = STG_B + (uint32_t)(wn * 32 + (lane & 7) + ((lane >> 4) << 3)) * ROWB
                                 + (uint32_t)(((lane >> 3) & 1) << 4);

    auto issue_tile = [&](int t) {
        const uint32_t sb = s0 + (uint32_t)(t % GSTAGES) * STAGE_BYTES;
        const int gk = t * BK;
        #pragma unroll
        for (int i = 0; i < 4; i++) {
            const int idx = tid + i * 256;
            const int r = (idx & 511) >> 2;
            const int j = idx & 3;
            if (idx < 512)
                cp16(sb + STG_A + r * ROWB + j * 16u,
                     A + (size_t)(row0 + r) * GK + gk + j * 8);
            else
                cp16(sb + STG_B + r * ROWB + j * 16u,
                     WT + (size_t)(col0 + r) * GK + gk + j * 8);
        }
        cp_commit();
    };

    issue_tile(0);
    issue_tile(1);

    float acc[4][4][4] = {};
    const int NIT = GK / BK;     // 32

    for (int it = 0; it < NIT; it++) {
        cp_wait<GSTAGES - 2>();
        __syncthreads();

        if (it + GSTAGES - 1 < NIT) issue_tile(it + GSTAGES - 1);
        else cp_commit();

        const uint32_t sb = s0 + (uint32_t)(it % GSTAGES) * STAGE_BYTES;
        #pragma unroll
        for (int kb = 0; kb < 2; kb++) {
            uint32_t af[4][4], bf[2][4];
            #pragma unroll
            for (int mi = 0; mi < 4; mi++)
                ldsm4(af[mi], sb + a_off + (uint32_t)(mi * 16) * ROWB + kb * 32u);
            #pragma unroll
            for (int nb = 0; nb < 2; nb++)
                ldsm4(bf[nb], sb + b_off + (uint32_t)(nb * 16) * ROWB + kb * 32u);
            #pragma unroll
            for (int mi = 0; mi < 4; mi++)
                #pragma unroll
                for (int nb = 0; nb < 2; nb++) {
                    mma_bf16(acc[mi][nb * 2],     af[mi][0], af[mi][1], af[mi][2], af[mi][3],
                             bf[nb][0], bf[nb][1]);
                    mma_bf16(acc[mi][nb * 2 + 1], af[mi][0], af[mi][1], af[mi][2], af[mi][3],
                             bf[nb][2], bf[nb][3]);
                }
        }
        __syncthreads();
    }

    #pragma unroll
    for (int mi = 0; mi < 4; mi++) {
        const int r1 = row0 + wm * 64 + mi * 16 + g;
        const int r2 = r1 + 8;
        #pragma unroll
        for (int ni = 0; ni < 4; ni++) {
            const int cb = col0 + wn * 32 + ni * 8 + 2 * tg;
            float v0 = (acc[mi][ni][0] + bias[cb])     * oscale;
            float v1 = (acc[mi][ni][1] + bias[cb + 1]) * oscale;
            float v2 = (acc[mi][ni][2] + bias[cb])     * oscale;
            float v3 = (acc[mi][ni][3] + bias[cb + 1]) * oscale;
            if (BF16OUT) {
                ((uint32_t*)C)[(size_t)r1 * (N / 2) + (cb >> 1)] = packbf(v0, v1);
                ((uint32_t*)C)[(size_t)r2 * (N / 2) + (cb >> 1)] = packbf(v2, v3);
            } else {
                const float2 r1v = *reinterpret_cast<const float2*>(res + (size_t)r1 * N + cb);
                const float2 r2v = *reinterpret_cast<const float2*>(res + (size_t)r2 * N + cb);
                float2 w1; w1.x = v0 + r1v.x; w1.y = v1 + r1v.y;
                float2 w2; w2.x = v2 + r2v.x; w2.y = v3 + r2v.y;
                *reinterpret_cast<float2*>((float*)C + (size_t)r1 * N + cb) = w1;
                *reinterpret_cast<float2*>((float*)C + (size_t)r2 * N + cb) = w2;
            }
        }
    }
}

// fused QKV: grid (24, 64); Q output pre-scaled by 1/sqrt(D)
__global__ void __launch_bounds__(256, 2) qkv_gemm_kernel(const __nv_bfloat16* __restrict__ A,
                                                          const __nv_bfloat16* __restrict__ wt,
                                                          const float* __restrict__ bq,
                                                          const float* __restrict__ bk,
                                                          const float* __restrict__ bv,
                                                          __nv_bfloat16* __restrict__ Cq,
                                                          __nv_bfloat16* __restrict__ Ck,
                                                          __nv_bfloat16* __restrict__ Cv) {
    const int mat = blockIdx.x >> 3;
    const int bx  = blockIdx.x & 7;
    const __nv_bfloat16* WT = wt + (size_t)mat * GK * GK;
    const float* bias = (mat == 0) ? bq : (mat == 1) ? bk : bv;
    __nv_bfloat16* C  = (mat == 0) ? Cq : (mat == 1) ? Ck : Cv;
    const float sc = (mat == 0) ? 0.125f : 1.0f;
    gemm_body<true>(A, WT, bias, nullptr, C, bx, blockIdx.y, sc);
}

__global__ void __launch_bounds__(256, 2) o_gemm_kernel(const __nv_bfloat16* __restrict__ A,
                                                        const __nv_bfloat16* __restrict__ wt,
                                                        const float* __restrict__ bo,
                                                        const float* __restrict__ res,
                                                        float* __restrict__ out) {
    gemm_body<false>(A, wt + (size_t)3 * GK * GK, bo, res, out, blockIdx.x, blockIdx.y, 1.0f);
}

// ---------------- Flash attention (causal), bf16, in-register P -------------
// grid (S/128, H, B), 256 threads (8 warps). Warp w owns 16 query rows.
// smem: Q tile 128x128B (stride 144) + 2 KV double buffers. No P tile.
#define TROW 144u
#define QTILE_B (128u * TROW)            // 18432
#define KVTILE_B (64u * TROW)            // 9216
#define KVBUF (2u * KVTILE_B)            // K+V per buffer
#define ATTN_SMEM_BYTES (QTILE_B + 2 * KVBUF)   // 55296

__global__ void __launch_bounds__(256, 2) attn_bf16_kernel(const __nv_bfloat16* __restrict__ Q,
                                                           const __nv_bfloat16* __restrict__ K,
                                                           const __nv_bfloat16* __restrict__ V,
                                                           __nv_bfloat16* __restrict__ O) {
    extern __shared__ __align__(16) char sm[];
    const uint32_t q_u32  = (uint32_t)__cvta_generic_to_shared(sm);
    const uint32_t kv_u32 = q_u32 + QTILE_B;

    const int tid  = threadIdx.x;
    const int lane = tid & 31;
    const int wid  = tid >> 5;           // 0..7
    const int g  = lane >> 2;
    const int tg = lane & 3;
    const int rbase = wid * 16;          // warp owns rows rbase..rbase+15
    const int q0 = blockIdx.x * 128;
    const int h = blockIdx.y, b = blockIdx.z;
    const size_t base = (size_t)b * Sdim * HD + (size_t)h * Ddim;

    // LDSM lane bases
    const uint32_t q_loff = (uint32_t)(rbase + (lane & 15)) * TROW + (uint32_t)((lane >> 4) << 4);
    const uint32_t b_loff = (uint32_t)((lane & 7) + ((lane >> 4) << 3)) * TROW
                          + (uint32_t)(((lane >> 3) & 1) << 4);
    const uint32_t v_loff = (uint32_t)((lane & 7) + (((lane >> 3) & 1) << 3)) * TROW
                          + (uint32_t)((lane >> 4) << 4);

    const int ntiles = (q0 >> 6) + 2;

    // prologue: G0 = Q(128 rows) + KV tile 0 ; G1 = KV tile 1
    #pragma unroll
    for (int i = 0; i < 4; i++) {
        const int idx = tid + i * 256;
        const int r = idx >> 3, j = idx & 7;
        cp16(q_u32 + r * TROW + j * 16u, Q + base + (size_t)(q0 + r) * HD + j * 8);
    }
    #pragma unroll
    for (int i = 0; i < 4; i++) {
        const int idx = tid + i * 256;
        const int j = idx & 7;
        if (idx < 512) {
            const int r = idx >> 3;
            cp16(kv_u32 + r * TROW + j * 16u, K + base + (size_t)r * HD + j * 8);
        } else {
            const int r = (idx - 512) >> 3;
            cp16(kv_u32 + KVTILE_B + r * TROW + j * 16u, V + base + (size_t)r * HD + j * 8);
        }
    }
    cp_commit();
    {
        const uint32_t kvb = kv_u32 + KVBUF;
        #pragma unroll
        for (int i = 0; i < 4; i++) {
            const int idx = tid + i * 256;
            const int j = idx & 7;
            if (idx < 512) {
                const int r = idx >> 3;
                cp16(kvb + r * TROW + j * 16u, K + base + (size_t)(64 + r) * HD + j * 8);
            } else {
                const int r = (idx - 512) >> 3;
                cp16(kvb + KVTILE_B + r * TROW + j * 16u, V + base + (size_t)(64 + r) * HD + j * 8);
            }
        }
    }
    cp_commit();

    float m1 = -1e30f, m2 = -1e30f, l1 = 0.f, l2 = 0.f;
    float o[8][4] = {};
    const int grow_base = q0 + rbase;    // warp's first global query row
    const int grow1 = grow_base + g, grow2 = grow1 + 8;

    for (int jt = 0; jt < ntiles; jt++) {
        cp_wait<1>();
        __syncthreads();

        const int j0 = jt * 64;
        const uint32_t kb32 = kv_u32 + (uint32_t)(jt & 1) * KVBUF;
        const uint32_t vb32 = kb32 + KVTILE_B;
        const bool active = (j0 <= grow_base + 15);   // warp-uniform

        if (active) {
            // S = Q K^T (16 rows x 64 cols)
            float s[8][4] = {};
            #pragma unroll
            for (int kb = 0; kb < 4; kb++) {
                uint32_t af[4];
                ldsm4(af, q_u32 + q_loff + kb * 32u);
                #pragma unroll
                for (int nb = 0; nb < 4; nb++) {
                    uint32_t bf[4];
                    ldsm4(bf, kb32 + b_loff + (uint32_t)(nb * 16) * TROW + kb * 32u);
                    mma_bf16(s[nb * 2],     af[0], af[1], af[2], af[3], bf[0], bf[1]);
                    mma_bf16(s[nb * 2 + 1], af[0], af[1], af[2], af[3], bf[2], bf[3]);
                }
            }

            // online softmax; p stored back into s
            const bool diag = (j0 + 63 > grow_base);
            float rm1 = -1e30f, rm2 = -1e30f;
            #pragma unroll
            for (int nt = 0; nt < 8; nt++) {
                if (diag) {
                    const int c0 = j0 + nt * 8 + 2 * tg;
                    if (c0     > grow1) s[nt][0] = -1e30f;
                    if (c0 + 1 > grow1) s[nt][1] = -1e30f;
                    if (c0     > grow2) s[nt][2] = -1e30f;
                    if (c0 + 1 > grow2) s[nt][3] = -1e30f;
                }
                rm1 = fmaxf(rm1, fmaxf(s[nt][0], s[nt][1]));
                rm2 = fmaxf(rm2, fmaxf(s[nt][2], s[nt][3]));
            }
            rm1 = fmaxf(rm1, __shfl_xor_sync(0xffffffffu, rm1, 1));
            rm1 = fmaxf(rm1, __shfl_xor_sync(0xffffffffu, rm1, 2));
            rm2 = fmaxf(rm2, __shfl_xor_sync(0xffffffffu, rm2, 1));
            rm2 = fmaxf(rm2, __shfl_xor_sync(0xffffffffu, rm2, 2));

            const float mn1 = fmaxf(m1, rm1), mn2 = fmaxf(m2, rm2);
            const float sc1 = __expf(m1 - mn1), sc2 = __expf(m2 - mn2);
            m1 = mn1; m2 = mn2;

            float sum1 = 0.f, sum2 = 0.f;
            #pragma unroll
            for (int nt = 0; nt < 8; nt++) {
                s[nt][0] = __expf(s[nt][0] - mn1);
                s[nt][1] = __expf(s[nt][1] - mn1);
                s[nt][2] = __expf(s[nt][2] - mn2);
                s[nt][3] = __expf(s[nt][3] - mn2);
                sum1 += s[nt][0] + s[nt][1];
                sum2 += s[nt][2] + s[nt][3];
            }
            sum1 += __shfl_xor_sync(0xffffffffu, sum1, 1);
            sum1 += __shfl_xor_sync(0xffffffffu, sum1, 2);
            sum2 += __shfl_xor_sync(0xffffffffu, sum2, 1);
            sum2 += __shfl_xor_sync(0xffffffffu, sum2, 2);
            l1 = l1 * sc1 + sum1;
            l2 = l2 * sc2 + sum2;

            #pragma unroll
            for (int nt = 0; nt < 8; nt++) {
                o[nt][0] *= sc1; o[nt][1] *= sc1;
                o[nt][2] *= sc2; o[nt][3] *= sc2;
            }

            // O += P V : P A-fragments built directly from S C-fragments
            #pragma unroll
            for (int kb = 0; kb < 4; kb++) {
                uint32_t pa[4];
                pa[0] = packbf(s[2 * kb][0],     s[2 * kb][1]);
                pa[1] = packbf(s[2 * kb][2],     s[2 * kb][3]);
                pa[2] = packbf(s[2 * kb + 1][0], s[2 * kb + 1][1]);
                pa[3] = packbf(s[2 * kb + 1][2], s[2 * kb + 1][3]);
                #pragma unroll
                for (int nb = 0; nb < 4; nb++) {
                    uint32_t bf[4];
                    ldsm4t(bf, vb32 + v_loff + (uint32_t)(kb * 16) * TROW + nb * 32u);
                    mma_bf16(o[nb * 2],     pa[0], pa[1], pa[2], pa[3], bf[0], bf[1]);
                    mma_bf16(o[nb * 2 + 1], pa[0], pa[1], pa[2], pa[3], bf[2], bf[3]);
                }
            }
        }

        __syncthreads();
        if (jt + 2 < ntiles) {
            const int j2 = (jt + 2) * 64;
            const uint32_t kvb = kv_u32 + (uint32_t)(jt & 1) * KVBUF;
            #pragma unroll
            for (int i = 0; i < 4; i++) {
                const int idx = tid + i * 256;
                const int j = idx & 7;
                if (idx < 512) {
                    const int r = idx >> 3;
                    cp16(kvb + r * TROW + j * 16u, K + base + (size_t)(j2 + r) * HD + j * 8);
                } else {
                    const int r = (idx - 512) >> 3;
                    cp16(kvb + KVTILE_B + r * TROW + j * 16u,
                         V + base + (size_t)(j2 + r) * HD + j * 8);
                }
            }
        }
        cp_commit();
    }

    const float inv1 = 1.0f / l1;
    const float inv2 = 1.0f / l2;
    #pragma unroll
    for (int nt = 0; nt < 8; nt++) {
        const int cb = nt * 8 + 2 * tg;
        *reinterpret_cast<uint32_t*>(O + base + (size_t)grow1 * HD + cb) =
            packbf(o[nt][0] * inv1, o[nt][1] * inv1);
        *reinterpret_cast<uint32_t*>(O + base + (size_t)grow2 * HD + cb) =
            packbf(o[nt][2] * inv2, o[nt][3] * inv2);
    }
}

// ---------------- launch ----------------------------------------------------
extern "C" void kernel_launch(void* const* d_in, const int* in_sizes, int n_in,
                              void* d_out, int out_size) {
    const float* x     = (const float*)d_in[0];
    const float* gamma = (const float*)d_in[1];
    const float* beta  = (const float*)d_in[2];
    const float* Wq    = (const float*)d_in[3];
    const float* bq    = (const float*)d_in[4];
    const float* Wk    = (const float*)d_in[5];
    const float* bk    = (const float*)d_in[6];
    const float* Wv    = (const float*)d_in[7];
    const float* bv    = (const float*)d_in[8];
    const float* Wo    = (const float*)d_in[9];
    const float* bo    = (const float*)d_in[10];
    float* out = (float*)d_out;

    __nv_bfloat16 *xn, *qp, *kp, *vp, *ao, *wt;
    cudaGetSymbolAddress((void**)&xn, g_xn);
    cudaGetSymbolAddress((void**)&qp, g_q);
    cudaGetSymbolAddress((void**)&kp, g_k);
    cudaGetSymbolAddress((void**)&vp, g_v);
    cudaGetSymbolAddress((void**)&ao, g_ao);
    cudaGetSymbolAddress((void**)&wt, g_wt);

    ln_kernel<<<Mrows, 256>>>(x, gamma, beta, xn);
    transpose_kernel<<<dim3(32, 32, 4), 256>>>(Wq, Wk, Wv, Wo, wt);

    cudaFuncSetAttribute(qkv_gemm_kernel, cudaFuncAttributeMaxDynamicSharedMemorySize,
                         GEMM_SMEM_BYTES);
    cudaFuncSetAttribute(o_gemm_kernel, cudaFuncAttributeMaxDynamicSharedMemorySize,
                         GEMM_SMEM_BYTES);

    qkv_gemm_kernel<<<dim3(24, Mrows / 128), 256, GEMM_SMEM_BYTES>>>(
        xn, wt, bq, bk, bv, qp, kp, vp);

    cudaFuncSetAttribute(attn_bf16_kernel, cudaFuncAttributeMaxDynamicSharedMemorySize,
                         ATTN_SMEM_BYTES);
    attn_bf16_kernel<<<dim3(Sdim / 128, Hdim, Bdim), 256, ATTN_SMEM_BYTES>>>(qp, kp, vp, ao);

    o_gemm_kernel<<<dim3(8, Mrows / 128), 256, GEMM_SMEM_BYTES>>>(ao, wt, bo, x, out);
}

// round 10
// speedup vs baseline: 7.8070x; 1.0190x over previous
#include <cuda_runtime.h>
#include <cuda_bf16.h>
#include <math.h>
#include <stdint.h>

#define Bdim 4
#define Sdim 2048
#define Edim 1024
#define Hdim 16
#define Ddim 64
#define Mrows (Bdim * Sdim)          // 8192
#define HD (Hdim * Ddim)             // 1024
#define GK 1024

// ---------------- scratch (static device globals; no allocs) ----------------
__device__ __nv_bfloat16 g_xn[Mrows * Edim];
__device__ __nv_bfloat16 g_q [Mrows * HD];
__device__ __nv_bfloat16 g_k [Mrows * HD];
__device__ __nv_bfloat16 g_v [Mrows * HD];
__device__ __nv_bfloat16 g_ao[Mrows * HD];
__device__ __nv_bfloat16 g_wt[4 * GK * GK];   // transposed weights [N][K] bf16

// ---------------- helpers ----------------------------------------------------
__device__ __forceinline__ uint32_t packbf(float lo, float hi) {
    uint32_t d;
    asm("cvt.rn.bf16x2.f32 %0, %1, %2;" : "=r"(d) : "f"(hi), "f"(lo));
    return d;
}
__device__ __forceinline__ float ex2f(float x) {
    float y;
    asm("ex2.approx.f32 %0, %1;" : "=f"(y) : "f"(x));
    return y;
}

// D(16x8) += A(16x16,row) * B(16x8,col)  bf16 -> fp32
__device__ __forceinline__ void mma_bf16(float c[4],
                                         uint32_t a0, uint32_t a1, uint32_t a2, uint32_t a3,
                                         uint32_t b0, uint32_t b1) {
    asm volatile(
        "mma.sync.aligned.m16n8k16.row.col.f32.bf16.bf16.f32 "
        "{%0,%1,%2,%3}, {%4,%5,%6,%7}, {%8,%9}, {%0,%1,%2,%3};\n"
        : "+f"(c[0]), "+f"(c[1]), "+f"(c[2]), "+f"(c[3])
        : "r"(a0), "r"(a1), "r"(a2), "r"(a3), "r"(b0), "r"(b1));
}

__device__ __forceinline__ void ldsm4(uint32_t r[4], uint32_t addr) {
    asm volatile("ldmatrix.sync.aligned.m8n8.x4.shared.b16 {%0,%1,%2,%3}, [%4];"
                 : "=r"(r[0]), "=r"(r[1]), "=r"(r[2]), "=r"(r[3])
                 : "r"(addr));
}
__device__ __forceinline__ void ldsm4t(uint32_t r[4], uint32_t addr) {
    asm volatile("ldmatrix.sync.aligned.m8n8.x4.trans.shared.b16 {%0,%1,%2,%3}, [%4];"
                 : "=r"(r[0]), "=r"(r[1]), "=r"(r[2]), "=r"(r[3])
                 : "r"(addr));
}

__device__ __forceinline__ void cp16(uint32_t dst, const void* src) {
    asm volatile("cp.async.cg.shared.global [%0], [%1], 16;" :: "r"(dst), "l"(src));
}
__device__ __forceinline__ void cp_commit() {
    asm volatile("cp.async.commit_group;");
}
template <int N>
__device__ __forceinline__ void cp_wait() {
    asm volatile("cp.async.wait_group %0;" :: "n"(N));
}

// ---------------- LayerNorm (fp32 in -> bf16 out) ----------------------------
__global__ void __launch_bounds__(256) ln_kernel(const float* __restrict__ x,
                                                 const float* __restrict__ gamma,
                                                 const float* __restrict__ beta,
                                                 __nv_bfloat16* __restrict__ y) {
    const int row = blockIdx.x;
    const int tid = threadIdx.x;
    const float4 xv = reinterpret_cast<const float4*>(x + (size_t)row * Edim)[tid];
    float s  = xv.x + xv.y + xv.z + xv.w;
    float ss = xv.x * xv.x + xv.y * xv.y + xv.z * xv.z + xv.w * xv.w;
    #pragma unroll
    for (int m = 16; m; m >>= 1) {
        s  += __shfl_xor_sync(0xffffffffu, s,  m);
        ss += __shfl_xor_sync(0xffffffffu, ss, m);
    }
    __shared__ float sh_s[8], sh_ss[8];
    __shared__ float s_mu, s_rstd;
    const int w = tid >> 5, l = tid & 31;
    if (l == 0) { sh_s[w] = s; sh_ss[w] = ss; }
    __syncthreads();
    if (w == 0) {
        float a = (l < 8) ? sh_s[l]  : 0.f;
        float c = (l < 8) ? sh_ss[l] : 0.f;
        #pragma unroll
        for (int m = 4; m; m >>= 1) {
            a += __shfl_xor_sync(0xffffffffu, a, m);
            c += __shfl_xor_sync(0xffffffffu, c, m);
        }
        if (l == 0) {
            float mu  = a * (1.0f / Edim);
            float var = c * (1.0f / Edim) - mu * mu;
            s_mu = mu;
            s_rstd = rsqrtf(var + 1e-5f);
        }
    }
    __syncthreads();
    const float mu = s_mu, rstd = s_rstd;
    const float4 gv = reinterpret_cast<const float4*>(gamma)[tid];
    const float4 bv = reinterpret_cast<const float4*>(beta)[tid];
    uint2 o2;
    o2.x = packbf((xv.x - mu) * rstd * gv.x + bv.x, (xv.y - mu) * rstd * gv.y + bv.y);
    o2.y = packbf((xv.z - mu) * rstd * gv.z + bv.z, (xv.w - mu) * rstd * gv.w + bv.w);
    *reinterpret_cast<uint2*>(y + (size_t)row * Edim + tid * 4) = o2;
}

// ---------------- weight transpose: W[K,N] fp32 -> WT[N,K] bf16 --------------
__global__ void __launch_bounds__(256) transpose_kernel(const float* __restrict__ Wq,
                                                        const float* __restrict__ Wk,
                                                        const float* __restrict__ Wv,
                                                        const float* __restrict__ Wo,
                                                        __nv_bfloat16* __restrict__ wt) {
    __shared__ float t[32][33];
    const int z = blockIdx.z;
    const float* W = (z == 0) ? Wq : (z == 1) ? Wk : (z == 2) ? Wv : Wo;
    __nv_bfloat16* T = wt + (size_t)z * GK * GK;
    const int x0 = blockIdx.x * 32, y0 = blockIdx.y * 32;
    const int tx = threadIdx.x & 31, ty = threadIdx.x >> 5;   // 32x8
    #pragma unroll
    for (int i = 0; i < 32; i += 8)
        t[ty + i][tx] = W[(size_t)(y0 + ty + i) * GK + x0 + tx];
    __syncthreads();
    #pragma unroll
    for (int i = 0; i < 32; i += 8)
        T[(size_t)(x0 + ty + i) * GK + y0 + tx] = __float2bfloat16(t[tx][ty + i]);
}

// ---------------- bf16 GEMM: 128x128 tile, BK=32, 4-stage cp.async ----------
#define BK 32
#define ROWB 80u
#define STG_A 0u
#define STG_B 10240u
#define STAGE_BYTES 20480u
#define GSTAGES 4
#define GEMM_SMEM_BYTES (GSTAGES * STAGE_BYTES)

template <bool BF16OUT>
__device__ __forceinline__ void gemm_body(const __nv_bfloat16* __restrict__ A,
                                          const __nv_bfloat16* __restrict__ WT,
                                          const float* __restrict__ bias,
                                          const float* __restrict__ res,
                                          void* __restrict__ C,
                                          int bx, int by, float oscale) {
    extern __shared__ __align__(16) char smem[];
    const uint32_t s0 = (uint32_t)__cvta_generic_to_shared(smem);

    const int tid  = threadIdx.x;
    const int lane = tid & 31;
    const int wid  = tid >> 5;
    const int g  = lane >> 2;
    const int tg = lane & 3;
    const int wm = wid >> 2;
    const int wn = wid & 3;
    const int row0 = by * 128;
    const int col0 = bx * 128;
    const int N = 1024;

    const uint32_t a_off = STG_A + (uint32_t)(wm * 64 + (lane & 15)) * ROWB
                                 + (uint32_t)((lane >> 4) << 4);
    const uint32_t b_off = STG_B + (uint32_t)(wn * 32 + (lane & 7) + ((lane >> 4) << 3)) * ROWB
                                 + (uint32_t)(((lane >> 3) & 1) << 4);

    auto issue_tile = [&](int t) {
        const uint32_t sb = s0 + (uint32_t)(t % GSTAGES) * STAGE_BYTES;
        const int gk = t * BK;
        #pragma unroll
        for (int i = 0; i < 4; i++) {
            const int idx = tid + i * 256;
            const int r = (idx & 511) >> 2;
            const int j = idx & 3;
            if (idx < 512)
                cp16(sb + STG_A + r * ROWB + j * 16u,
                     A + (size_t)(row0 + r) * GK + gk + j * 8);
            else
                cp16(sb + STG_B + r * ROWB + j * 16u,
                     WT + (size_t)(col0 + r) * GK + gk + j * 8);
        }
        cp_commit();
    };

    issue_tile(0);
    issue_tile(1);
    issue_tile(2);

    float acc[4][4][4] = {};
    const int NIT = GK / BK;     // 32

    for (int it = 0; it < NIT; it++) {
        cp_wait<GSTAGES - 2>();
        __syncthreads();

        if (it + GSTAGES - 1 < NIT) issue_tile(it + GSTAGES - 1);
        else cp_commit();

        const uint32_t sb = s0 + (uint32_t)(it % GSTAGES) * STAGE_BYTES;
        #pragma unroll
        for (int kb = 0; kb < 2; kb++) {
            uint32_t af[4][4], bf[2][4];
            #pragma unroll
            for (int mi = 0; mi < 4; mi++)
                ldsm4(af[mi], sb + a_off + (uint32_t)(mi * 16) * ROWB + kb * 32u);
            #pragma unroll
            for (int nb = 0; nb < 2; nb++)
                ldsm4(bf[nb], sb + b_off + (uint32_t)(nb * 16) * ROWB + kb * 32u);
            #pragma unroll
            for (int mi = 0; mi < 4; mi++)
                #pragma unroll
                for (int nb = 0; nb < 2; nb++) {
                    mma_bf16(acc[mi][nb * 2],     af[mi][0], af[mi][1], af[mi][2], af[mi][3],
                             bf[nb][0], bf[nb][1]);
                    mma_bf16(acc[mi][nb * 2 + 1], af[mi][0], af[mi][1], af[mi][2], af[mi][3],
                             bf[nb][2], bf[nb][3]);
                }
        }
        __syncthreads();
    }

    #pragma unroll
    for (int mi = 0; mi < 4; mi++) {
        const int r1 = row0 + wm * 64 + mi * 16 + g;
        const int r2 = r1 + 8;
        #pragma unroll
        for (int ni = 0; ni < 4; ni++) {
            const int cb = col0 + wn * 32 + ni * 8 + 2 * tg;
            float v0 = (acc[mi][ni][0] + bias[cb])     * oscale;
            float v1 = (acc[mi][ni][1] + bias[cb + 1]) * oscale;
            float v2 = (acc[mi][ni][2] + bias[cb])     * oscale;
            float v3 = (acc[mi][ni][3] + bias[cb + 1]) * oscale;
            if (BF16OUT) {
                ((uint32_t*)C)[(size_t)r1 * (N / 2) + (cb >> 1)] = packbf(v0, v1);
                ((uint32_t*)C)[(size_t)r2 * (N / 2) + (cb >> 1)] = packbf(v2, v3);
            } else {
                const float2 r1v = *reinterpret_cast<const float2*>(res + (size_t)r1 * N + cb);
                const float2 r2v = *reinterpret_cast<const float2*>(res + (size_t)r2 * N + cb);
                float2 w1; w1.x = v0 + r1v.x; w1.y = v1 + r1v.y;
                float2 w2; w2.x = v2 + r2v.x; w2.y = v3 + r2v.y;
                *reinterpret_cast<float2*>((float*)C + (size_t)r1 * N + cb) = w1;
                *reinterpret_cast<float2*>((float*)C + (size_t)r2 * N + cb) = w2;
            }
        }
    }
}

// fused QKV: grid (24, 64); Q output pre-scaled by log2(e)/sqrt(D)
__global__ void __launch_bounds__(256, 2) qkv_gemm_kernel(const __nv_bfloat16* __restrict__ A,
                                                          const __nv_bfloat16* __restrict__ wt,
                                                          const float* __restrict__ bq,
                                                          const float* __restrict__ bk,
                                                          const float* __restrict__ bv,
                                                          __nv_bfloat16* __restrict__ Cq,
                                                          __nv_bfloat16* __restrict__ Ck,
                                                          __nv_bfloat16* __restrict__ Cv) {
    const int mat = blockIdx.x >> 3;
    const int bx  = blockIdx.x & 7;
    const __nv_bfloat16* WT = wt + (size_t)mat * GK * GK;
    const float* bias = (mat == 0) ? bq : (mat == 1) ? bk : bv;
    __nv_bfloat16* C  = (mat == 0) ? Cq : (mat == 1) ? Ck : Cv;
    const float sc = (mat == 0) ? 0.1803368801111354f : 1.0f;   // 0.125 * log2(e)
    gemm_body<true>(A, WT, bias, nullptr, C, bx, blockIdx.y, sc);
}

__global__ void __launch_bounds__(256, 2) o_gemm_kernel(const __nv_bfloat16* __restrict__ A,
                                                        const __nv_bfloat16* __restrict__ wt,
                                                        const float* __restrict__ bo,
                                                        const float* __restrict__ res,
                                                        float* __restrict__ out) {
    gemm_body<false>(A, wt + (size_t)3 * GK * GK, bo, res, out, blockIdx.x, blockIdx.y, 1.0f);
}

// ---------------- Flash attention (causal), bf16, in-register P -------------
// grid (S/128, H, B), 256 threads (8 warps). Warp w owns 16 query rows.
// Scores are in log2 domain (Q pre-scaled); softmax uses ex2.
// smem: Q tile + 3-deep KV ring => ONE __syncthreads per tile.
#define TROW 144u
#define QTILE_B (128u * TROW)            // 18432
#define KVTILE_B (64u * TROW)            // 9216
#define KVBUF (2u * KVTILE_B)            // K+V per buffer: 18432
#define ATTN_SMEM_BYTES (QTILE_B + 3 * KVBUF)   // 73728

__global__ void __launch_bounds__(256, 2) attn_bf16_kernel(const __nv_bfloat16* __restrict__ Q,
                                                           const __nv_bfloat16* __restrict__ K,
                                                           const __nv_bfloat16* __restrict__ V,
                                                           __nv_bfloat16* __restrict__ O) {
    extern __shared__ __align__(16) char sm[];
    const uint32_t q_u32  = (uint32_t)__cvta_generic_to_shared(sm);
    const uint32_t kv_u32 = q_u32 + QTILE_B;

    const int tid  = threadIdx.x;
    const int lane = tid & 31;
    const int wid  = tid >> 5;           // 0..7
    const int g  = lane >> 2;
    const int tg = lane & 3;
    const int rbase = wid * 16;          // warp owns rows rbase..rbase+15
    const int qblk = (int)gridDim.x - 1 - (int)blockIdx.x;   // LPT: heavy CTAs first
    const int q0 = qblk * 128;
    const int h = blockIdx.y, b = blockIdx.z;
    const size_t base = (size_t)b * Sdim * HD + (size_t)h * Ddim;

    // LDSM lane bases
    const uint32_t q_loff = (uint32_t)(rbase + (lane & 15)) * TROW + (uint32_t)((lane >> 4) << 4);
    const uint32_t b_loff = (uint32_t)((lane & 7) + ((lane >> 4) << 3)) * TROW
                          + (uint32_t)(((lane >> 3) & 1) << 4);
    const uint32_t v_loff = (uint32_t)((lane & 7) + (((lane >> 3) & 1) << 3)) * TROW
                          + (uint32_t)((lane >> 4) << 4);

    const int ntiles = (q0 >> 6) + 2;

    auto issue_kv = [&](int t) {
        const uint32_t kvb = kv_u32 + (uint32_t)(t % 3) * KVBUF;
        const int jr = t * 64;
        #pragma unroll
        for (int i = 0; i < 4; i++) {
            const int idx = tid + i * 256;
            const int j = idx & 7;
            if (idx < 512) {
                const int r = idx >> 3;
                cp16(kvb + r * TROW + j * 16u, K + base + (size_t)(jr + r) * HD + j * 8);
            } else {
                const int r = (idx - 512) >> 3;
                cp16(kvb + KVTILE_B + r * TROW + j * 16u,
                     V + base + (size_t)(jr + r) * HD + j * 8);
            }
        }
    };

    // prologue: G0 = Q(128 rows) + KV tile 0 ; G1 = KV tile 1 (always exists)
    #pragma unroll
    for (int i = 0; i < 4; i++) {
        const int idx = tid + i * 256;
        const int r = idx >> 3, j = idx & 7;
        cp16(q_u32 + r * TROW + j * 16u, Q + base + (size_t)(q0 + r) * HD + j * 8);
    }
    issue_kv(0);
    cp_commit();
    issue_kv(1);
    cp_commit();

    float m1 = -1e30f, m2 = -1e30f, l1 = 0.f, l2 = 0.f;
    float o[8][4] = {};
    const int grow_base = q0 + rbase;    // warp's first global query row
    const int grow1 = grow_base + g, grow2 = grow1 + 8;

    for (int jt = 0; jt < ntiles; jt++) {
        cp_wait<1>();
        __syncthreads();     // tile jt ready; all warps done with tile jt-1's buffer

        if (jt + 2 < ntiles) issue_kv(jt + 2);
        cp_commit();

        const int j0 = jt * 64;
        const uint32_t kb32 = kv_u32 + (uint32_t)(jt % 3) * KVBUF;
        const uint32_t vb32 = kb32 + KVTILE_B;
        const bool active = (j0 <= grow_base + 15);   // warp-uniform

        if (active) {
            // S = Q K^T (16 rows x 64 cols), log2 domain
            float s[8][4] = {};
            #pragma unroll
            for (int kb = 0; kb < 4; kb++) {
                uint32_t af[4];
                ldsm4(af, q_u32 + q_loff + kb * 32u);
                #pragma unroll
                for (int nb = 0; nb < 4; nb++) {
                    uint32_t bf[4];
                    ldsm4(bf, kb32 + b_loff + (uint32_t)(nb * 16) * TROW + kb * 32u);
                    mma_bf16(s[nb * 2],     af[0], af[1], af[2], af[3], bf[0], bf[1]);
                    mma_bf16(s[nb * 2 + 1], af[0], af[1], af[2], af[3], bf[2], bf[3]);
                }
            }

            // online softmax (base-2); p stored back into s
            const bool diag = (j0 + 63 > grow_base);
            float rm1 = -1e30f, rm2 = -1e30f;
            #pragma unroll
            for (int nt = 0; nt < 8; nt++) {
                if (diag) {
                    const int c0 = j0 + nt * 8 + 2 * tg;
                    if (c0     > grow1) s[nt][0] = -1e30f;
                    if (c0 + 1 > grow1) s[nt][1] = -1e30f;
                    if (c0     > grow2) s[nt][2] = -1e30f;
                    if (c0 + 1 > grow2) s[nt][3] = -1e30f;
                }
                rm1 = fmaxf(rm1, fmaxf(s[nt][0], s[nt][1]));
                rm2 = fmaxf(rm2, fmaxf(s[nt][2], s[nt][3]));
            }
            rm1 = fmaxf(rm1, __shfl_xor_sync(0xffffffffu, rm1, 1));
            rm1 = fmaxf(rm1, __shfl_xor_sync(0xffffffffu, rm1, 2));
            rm2 = fmaxf(rm2, __shfl_xor_sync(0xffffffffu, rm2, 1));
            rm2 = fmaxf(rm2, __shfl_xor_sync(0xffffffffu, rm2, 2));

            const float mn1 = fmaxf(m1, rm1), mn2 = fmaxf(m2, rm2);
            const float sc1 = ex2f(m1 - mn1), sc2 = ex2f(m2 - mn2);
            m1 = mn1; m2 = mn2;

            float sum1 = 0.f, sum2 = 0.f;
            #pragma unroll
            for (int nt = 0; nt < 8; nt++) {
                s[nt][0] = ex2f(s[nt][0] - mn1);
                s[nt][1] = ex2f(s[nt][1] - mn1);
                s[nt][2] = ex2f(s[nt][2] - mn2);
                s[nt][3] = ex2f(s[nt][3] - mn2);
                sum1 += s[nt][0] + s[nt][1];
                sum2 += s[nt][2] + s[nt][3];
            }
            sum1 += __shfl_xor_sync(0xffffffffu, sum1, 1);
            sum1 += __shfl_xor_sync(0xffffffffu, sum1, 2);
            sum2 += __shfl_xor_sync(0xffffffffu, sum2, 1);
            sum2 += __shfl_xor_sync(0xffffffffu, sum2, 2);
            l1 = l1 * sc1 + sum1;
            l2 = l2 * sc2 + sum2;

            #pragma unroll
            for (int nt = 0; nt < 8; nt++) {
                o[nt][0] *= sc1; o[nt][1] *= sc1;
                o[nt][2] *= sc2; o[nt][3] *= sc2;
            }

            // O += P V : P A-fragments built directly from S C-fragments
            #pragma unroll
            for (int kb = 0; kb < 4; kb++) {
                uint32_t pa[4];
                pa[0] = packbf(s[2 * kb][0],     s[2 * kb][1]);
                pa[1] = packbf(s[2 * kb][2],     s[2 * kb][3]);
                pa[2] = packbf(s[2 * kb + 1][0], s[2 * kb + 1][1]);
                pa[3] = packbf(s[2 * kb + 1][2], s[2 * kb + 1][3]);
                #pragma unroll
                for (int nb = 0; nb < 4; nb++) {
                    uint32_t bf[4];
                    ldsm4t(bf, vb32 + v_loff + (uint32_t)(kb * 16) * TROW + nb * 32u);
                    mma_bf16(o[nb * 2],     pa[0], pa[1], pa[2], pa[3], bf[0], bf[1]);
                    mma_bf16(o[nb * 2 + 1], pa[0], pa[1], pa[2], pa[3], bf[2], bf[3]);
                }
            }
        }
    }

    const float inv1 = 1.0f / l1;
    const float inv2 = 1.0f / l2;
    #pragma unroll
    for (int nt = 0; nt < 8; nt++) {
        const int cb = nt * 8 + 2 * tg;
        *reinterpret_cast<uint32_t*>(O + base + (size_t)grow1 * HD + cb) =
            packbf(o[nt][0] * inv1, o[nt][1] * inv1);
        *reinterpret_cast<uint32_t*>(O + base + (size_t)grow2 * HD + cb) =
            packbf(o[nt][2] * inv2, o[nt][3] * inv2);
    }
}

// ---------------- launch ----------------------------------------------------
extern "C" void kernel_launch(void* const* d_in, const int* in_sizes, int n_in,
                              void* d_out, int out_size) {
    const float* x     = (const float*)d_in[0];
    const float* gamma = (const float*)d_in[1];
    const float* beta  = (const float*)d_in[2];
    const float* Wq    = (const float*)d_in[3];
    const float* bq    = (const float*)d_in[4];
    const float* Wk    = (const float*)d_in[5];
    const float* bk    = (const float*)d_in[6];
    const float* Wv    = (const float*)d_in[7];
    const float* bv    = (const float*)d_in[8];
    const float* Wo    = (const float*)d_in[9];
    const float* bo    = (const float*)d_in[10];
    float* out = (float*)d_out;

    __nv_bfloat16 *xn, *qp, *kp, *vp, *ao, *wt;
    cudaGetSymbolAddress((void**)&xn, g_xn);
    cudaGetSymbolAddress((void**)&qp, g_q);
    cudaGetSymbolAddress((void**)&kp, g_k);
    cudaGetSymbolAddress((void**)&vp, g_v);
    cudaGetSymbolAddress((void**)&ao, g_ao);
    cudaGetSymbolAddress((void**)&wt, g_wt);

    ln_kernel<<<Mrows, 256>>>(x, gamma, beta, xn);
    transpose_kernel<<<dim3(32, 32, 4), 256>>>(Wq, Wk, Wv, Wo, wt);

    cudaFuncSetAttribute(qkv_gemm_kernel, cudaFuncAttributeMaxDynamicSharedMemorySize,
                         GEMM_SMEM_BYTES);
    cudaFuncSetAttribute(o_gemm_kernel, cudaFuncAttributeMaxDynamicSharedMemorySize,
                         GEMM_SMEM_BYTES);

    qkv_gemm_kernel<<<dim3(24, Mrows / 128), 256, GEMM_SMEM_BYTES>>>(
        xn, wt, bq, bk, bv, qp, kp, vp);

    cudaFuncSetAttribute(attn_bf16_kernel, cudaFuncAttributeMaxDynamicSharedMemorySize,
                         ATTN_SMEM_BYTES);
    attn_bf16_kernel<<<dim3(Sdim / 128, Hdim, Bdim), 256, ATTN_SMEM_BYTES>>>(qp, kp, vp, ao);

    o_gemm_kernel<<<dim3(8, Mrows / 128), 256, GEMM_SMEM_BYTES>>>(ao, wt, bo, x, out);
}